// round 1
// baseline (speedup 1.0000x reference)
#include <cuda_runtime.h>
#include <cuda_bf16.h>
#include <math.h>

#define NB 128

// ---------------- scratch (device globals; no allocation allowed) ----------
__device__ float g_t1[(size_t)NB*8*128*128];    // conv1 out
__device__ float g_ds[(size_t)NB*32*64*64];     // conv2 out (skip "ds")
__device__ float g_t3[(size_t)NB*4*32*32];
__device__ float g_t4[(size_t)NB*20*16*16];
__device__ float g_t5[(size_t)NB*30*8*8];
__device__ float g_t6[(size_t)NB*8*4*4];
__device__ float g_blur[NB*16];
__device__ float g_r1[(size_t)NB*64*64*64];
__device__ float g_r2[(size_t)NB*20*64*64];
__device__ float g_u1[(size_t)NB*30*64*64];
__device__ float g_part[2*64*32];               // BN partial sums
__device__ float g_scale[64];
__device__ float g_shift[64];

// ---------------- generic direct conv -------------------------------------
// One thread per output pixel (n,oy,ox); all COUT accumulators in registers.
// Weights transposed to [ci][ky][kx][co] (co padded to mult of 4) in shared,
// so inner loop is one LDS.128 per 4 FFMA.
template<int CIN,int COUT,int K,int S,int P,int HIN,int WIN,bool RELU>
__global__ __launch_bounds__(128) void conv_k(
    const float* __restrict__ in, const float* __restrict__ w,
    const float* __restrict__ bias, float* __restrict__ out)
{
    constexpr int HOUT = (HIN + 2*P - K)/S + 1;
    constexpr int WOUT = (WIN + 2*P - K)/S + 1;
    constexpr int COUTP = (COUT + 3) & ~3;
    extern __shared__ float sw[];                 // CIN*K*K*COUTP + COUTP
    float* sb = sw + CIN*K*K*COUTP;
    for (int i = threadIdx.x; i < CIN*K*K*COUTP; i += blockDim.x) {
        int co = i % COUTP; int r = i / COUTP;
        sw[i] = (co < COUT) ? w[co*CIN*K*K + r] : 0.f;
    }
    for (int i = threadIdx.x; i < COUTP; i += blockDim.x)
        sb[i] = (i < COUT) ? bias[i] : 0.f;
    __syncthreads();

    int idx = blockIdx.x*blockDim.x + threadIdx.x;
    if (idx >= NB*HOUT*WOUT) return;
    int ox = idx % WOUT; int oy = (idx/WOUT) % HOUT; int n = idx/(WOUT*HOUT);

    float acc[COUTP];
    #pragma unroll
    for (int c = 0; c < COUTP; c++) acc[c] = sb[c];

    const float* inp = in + (size_t)n*CIN*HIN*WIN;
    #pragma unroll 1
    for (int ci = 0; ci < CIN; ci++) {
        #pragma unroll
        for (int ky = 0; ky < K; ky++) {
            int iy = oy*S - P + ky;
            if (iy < 0 || iy >= HIN) continue;
            #pragma unroll
            for (int kx = 0; kx < K; kx++) {
                int ix = ox*S - P + kx;
                if (ix < 0 || ix >= WIN) continue;
                float v = __ldg(&inp[(size_t)ci*HIN*WIN + (size_t)iy*WIN + ix]);
                const float* wp = &sw[((ci*K+ky)*K+kx)*COUTP];
                #pragma unroll
                for (int co = 0; co < COUTP; co += 4) {
                    float4 w4 = *reinterpret_cast<const float4*>(wp + co);
                    acc[co+0] = fmaf(v, w4.x, acc[co+0]);
                    acc[co+1] = fmaf(v, w4.y, acc[co+1]);
                    acc[co+2] = fmaf(v, w4.z, acc[co+2]);
                    acc[co+3] = fmaf(v, w4.w, acc[co+3]);
                }
            }
        }
    }
    float* op = out + ((size_t)n*COUT*HOUT + (size_t)oy)*WOUT + ox;
    #pragma unroll
    for (int co = 0; co < COUT; co++) {
        float v = acc[co];
        if (RELU) v = fmaxf(v, 0.f);
        op[(size_t)co*HOUT*WOUT] = v;
    }
}

// ---------------- conv7: 1x1, 8->1 over 4x4, -> blur[n][16] ----------------
__global__ void conv7_k(const float* __restrict__ t6, const float* __restrict__ w,
                        const float* __restrict__ b, float* __restrict__ blur)
{
    int i = blockIdx.x*blockDim.x + threadIdx.x;
    if (i >= NB*16) return;
    int n = i >> 4, p = i & 15;
    float acc = b[0];
    #pragma unroll
    for (int ci = 0; ci < 8; ci++)
        acc = fmaf(t6[(n*8 + ci)*16 + p], w[ci], acc);
    blur[i] = fmaxf(acc, 0.f);
}

// ---------------- r1 conv: virtual pre = [blur(16 scalar ch) | ds(32 ch)] --
__global__ __launch_bounds__(128) void conv_r1_k(
    const float* __restrict__ blur, const float* __restrict__ ds,
    const float* __restrict__ w, const float* __restrict__ bias,
    float* __restrict__ out)
{
    constexpr int COUT = 64;
    extern __shared__ float sw[];                 // 48*9*64 + 64
    float* sb = sw + 48*9*COUT;
    for (int i = threadIdx.x; i < 48*9*COUT; i += blockDim.x) {
        int co = i % COUT; int r = i / COUT;
        sw[i] = w[co*48*9 + r];
    }
    for (int i = threadIdx.x; i < COUT; i += blockDim.x) sb[i] = bias[i];
    __syncthreads();

    int idx = blockIdx.x*blockDim.x + threadIdx.x;
    if (idx >= NB*64*64) return;
    int ox = idx & 63; int oy = (idx >> 6) & 63; int n = idx >> 12;

    float acc[COUT];
    #pragma unroll
    for (int c = 0; c < COUT; c++) acc[c] = sb[c];

    // blur channels: value is a per-(n,ci) scalar
    #pragma unroll 1
    for (int ci = 0; ci < 16; ci++) {
        float v = blur[n*16 + ci];
        #pragma unroll
        for (int ky = 0; ky < 3; ky++) {
            int iy = oy - 1 + ky; if (iy < 0 || iy >= 64) continue;
            #pragma unroll
            for (int kx = 0; kx < 3; kx++) {
                int ix = ox - 1 + kx; if (ix < 0 || ix >= 64) continue;
                const float* wp = &sw[((ci*3+ky)*3+kx)*COUT];
                #pragma unroll
                for (int co = 0; co < COUT; co += 4) {
                    float4 w4 = *reinterpret_cast<const float4*>(wp + co);
                    acc[co+0] = fmaf(v, w4.x, acc[co+0]);
                    acc[co+1] = fmaf(v, w4.y, acc[co+1]);
                    acc[co+2] = fmaf(v, w4.z, acc[co+2]);
                    acc[co+3] = fmaf(v, w4.w, acc[co+3]);
                }
            }
        }
    }
    const float* dsp = ds + (size_t)n*32*4096;
    #pragma unroll 1
    for (int ci = 0; ci < 32; ci++) {
        #pragma unroll
        for (int ky = 0; ky < 3; ky++) {
            int iy = oy - 1 + ky; if (iy < 0 || iy >= 64) continue;
            #pragma unroll
            for (int kx = 0; kx < 3; kx++) {
                int ix = ox - 1 + kx; if (ix < 0 || ix >= 64) continue;
                float v = __ldg(&dsp[ci*4096 + iy*64 + ix]);
                const float* wp = &sw[(((16+ci)*3+ky)*3+kx)*COUT];
                #pragma unroll
                for (int co = 0; co < COUT; co += 4) {
                    float4 w4 = *reinterpret_cast<const float4*>(wp + co);
                    acc[co+0] = fmaf(v, w4.x, acc[co+0]);
                    acc[co+1] = fmaf(v, w4.y, acc[co+1]);
                    acc[co+2] = fmaf(v, w4.z, acc[co+2]);
                    acc[co+3] = fmaf(v, w4.w, acc[co+3]);
                }
            }
        }
    }
    float* op = out + (size_t)n*64*4096 + oy*64 + ox;
    #pragma unroll
    for (int c = 0; c < COUT; c++) op[(size_t)c*4096] = acc[c];
}

// ---------------- BatchNorm: deterministic 2-stage stats -------------------
template<int C, int HW>
__global__ void bn_part_k(const float* __restrict__ x, float* __restrict__ part)
{
    int c = blockIdx.x;
    float s = 0.f, s2 = 0.f;
    const int per = NB*HW;
    for (int i = blockIdx.y*blockDim.x + threadIdx.x; i < per; i += gridDim.y*blockDim.x) {
        int n = i / HW; int j = i - n*HW;
        float v = x[((size_t)n*C + c)*HW + j];
        s += v; s2 += v*v;
    }
    __shared__ float rs[256], rs2[256];
    rs[threadIdx.x] = s; rs2[threadIdx.x] = s2;
    __syncthreads();
    for (int o = blockDim.x/2; o > 0; o >>= 1) {
        if (threadIdx.x < o) {
            rs[threadIdx.x]  += rs[threadIdx.x + o];
            rs2[threadIdx.x] += rs2[threadIdx.x + o];
        }
        __syncthreads();
    }
    if (threadIdx.x == 0) {
        part[c*32 + blockIdx.y]        = rs[0];
        part[C*32 + c*32 + blockIdx.y] = rs2[0];
    }
}

template<int C, int HW>
__global__ void bn_fin_k(const float* __restrict__ part, const float* __restrict__ g,
                         const float* __restrict__ be, float* __restrict__ scale,
                         float* __restrict__ shift)
{
    int c = threadIdx.x;
    if (c >= C) return;
    float s = 0.f, s2 = 0.f;
    for (int b = 0; b < 32; b++) { s += part[c*32 + b]; s2 += part[C*32 + c*32 + b]; }
    const float cnt = (float)NB * (float)HW;
    float mu  = s / cnt;
    float var = s2 / cnt - mu*mu;
    float sc  = g[c] * rsqrtf(var + 1e-5f);
    scale[c] = sc;
    shift[c] = be[c] - mu*sc;
}

template<int C, int HW, bool RELU>
__global__ void bn_apply_k(float* __restrict__ x, const float* __restrict__ scale,
                           const float* __restrict__ shift)
{
    int i = blockIdx.x*blockDim.x + threadIdx.x;
    if (i >= NB*C*HW) return;
    int c = (i / HW) % C;
    float v = fmaf(x[i], scale[c], shift[c]);
    if (RELU) v = fmaxf(v, 0.f);
    x[i] = v;
}

// ---------------- bn2 apply + pointwise(pre) residual add (in place) -------
__global__ __launch_bounds__(128) void bn2pw_k(
    float* __restrict__ r2, const float* __restrict__ blur,
    const float* __restrict__ ds, const float* __restrict__ pw,
    const float* __restrict__ pb, const float* __restrict__ scale,
    const float* __restrict__ shift)
{
    __shared__ float sw[48*20];   // transposed [ci][co]
    __shared__ float sb[20], ssc[20], ssh[20];
    for (int i = threadIdx.x; i < 48*20; i += blockDim.x) {
        int co = i % 20, ci = i / 20;
        sw[i] = pw[co*48 + ci];
    }
    if (threadIdx.x < 20) {
        sb[threadIdx.x]  = pb[threadIdx.x];
        ssc[threadIdx.x] = scale[threadIdx.x];
        ssh[threadIdx.x] = shift[threadIdx.x];
    }
    __syncthreads();

    int idx = blockIdx.x*blockDim.x + threadIdx.x;
    if (idx >= NB*4096) return;
    int p = idx & 4095; int n = idx >> 12;

    float acc[20];
    #pragma unroll
    for (int c = 0; c < 20; c++) acc[c] = sb[c];

    #pragma unroll 1
    for (int ci = 0; ci < 16; ci++) {
        float v = blur[n*16 + ci];
        #pragma unroll
        for (int c = 0; c < 20; c += 4) {
            float4 w4 = *reinterpret_cast<const float4*>(&sw[ci*20 + c]);
            acc[c+0] = fmaf(v, w4.x, acc[c+0]);
            acc[c+1] = fmaf(v, w4.y, acc[c+1]);
            acc[c+2] = fmaf(v, w4.z, acc[c+2]);
            acc[c+3] = fmaf(v, w4.w, acc[c+3]);
        }
    }
    const float* dsp = ds + (size_t)n*32*4096 + p;
    #pragma unroll 1
    for (int ci = 0; ci < 32; ci++) {
        float v = __ldg(&dsp[(size_t)ci*4096]);
        #pragma unroll
        for (int c = 0; c < 20; c += 4) {
            float4 w4 = *reinterpret_cast<const float4*>(&sw[(16+ci)*20 + c]);
            acc[c+0] = fmaf(v, w4.x, acc[c+0]);
            acc[c+1] = fmaf(v, w4.y, acc[c+1]);
            acc[c+2] = fmaf(v, w4.z, acc[c+2]);
            acc[c+3] = fmaf(v, w4.w, acc[c+3]);
        }
    }
    float* rp = r2 + (size_t)n*20*4096 + p;
    #pragma unroll
    for (int c = 0; c < 20; c++) {
        float v = fmaf(rp[(size_t)c*4096], ssc[c], ssh[c]) + acc[c];
        rp[(size_t)c*4096] = v;
    }
}

// ---------------- final: u2 1x1 (30->16) + relu + pixel_shuffle(4) + sigmoid
__global__ __launch_bounds__(128) void final_k(
    const float* __restrict__ u1, const float* __restrict__ w,
    const float* __restrict__ b, float* __restrict__ out)
{
    __shared__ float sw[30*16];   // transposed [ci][co]
    __shared__ float sb[16];
    for (int i = threadIdx.x; i < 30*16; i += blockDim.x) {
        int co = i % 16, ci = i / 16;
        sw[i] = w[co*30 + ci];
    }
    if (threadIdx.x < 16) sb[threadIdx.x] = b[threadIdx.x];
    __syncthreads();

    int idx = blockIdx.x*blockDim.x + threadIdx.x;
    if (idx >= NB*4096) return;
    int wq = idx & 63; int h = (idx >> 6) & 63; int n = idx >> 12;

    float acc[16];
    #pragma unroll
    for (int c = 0; c < 16; c++) acc[c] = sb[c];

    const float* up = u1 + (size_t)n*30*4096 + h*64 + wq;
    #pragma unroll 1
    for (int ci = 0; ci < 30; ci++) {
        float v = __ldg(&up[(size_t)ci*4096]);
        #pragma unroll
        for (int c = 0; c < 16; c += 4) {
            float4 w4 = *reinterpret_cast<const float4*>(&sw[ci*16 + c]);
            acc[c+0] = fmaf(v, w4.x, acc[c+0]);
            acc[c+1] = fmaf(v, w4.y, acc[c+1]);
            acc[c+2] = fmaf(v, w4.z, acc[c+2]);
            acc[c+3] = fmaf(v, w4.w, acc[c+3]);
        }
    }
    float* op = out + (size_t)n*65536;
    #pragma unroll
    for (int c = 0; c < 16; c++) {
        float v = fmaxf(acc[c], 0.f);
        v = 1.f / (1.f + expf(-v));
        op[(h*4 + (c >> 2))*256 + wq*4 + (c & 3)] = v;
    }
}

// ---------------------------------------------------------------------------
extern "C" void kernel_launch(void* const* d_in, const int* in_sizes, int n_in,
                              void* d_out, int out_size)
{
    const float* x1  = (const float*)d_in[0];
    const float* c1w = (const float*)d_in[1];  const float* c1b = (const float*)d_in[2];
    const float* c2w = (const float*)d_in[3];  const float* c2b = (const float*)d_in[4];
    const float* c3w = (const float*)d_in[5];  const float* c3b = (const float*)d_in[6];
    const float* c4w = (const float*)d_in[7];  const float* c4b = (const float*)d_in[8];
    const float* c5w = (const float*)d_in[9];  const float* c5b = (const float*)d_in[10];
    const float* c6w = (const float*)d_in[11]; const float* c6b = (const float*)d_in[12];
    const float* c7w = (const float*)d_in[13]; const float* c7b = (const float*)d_in[14];
    const float* r1w = (const float*)d_in[15]; const float* r1b = (const float*)d_in[16];
    const float* g1  = (const float*)d_in[17]; const float* be1 = (const float*)d_in[18];
    const float* r2w = (const float*)d_in[19]; const float* r2b = (const float*)d_in[20];
    const float* g2  = (const float*)d_in[21]; const float* be2 = (const float*)d_in[22];
    const float* pw  = (const float*)d_in[23]; const float* pb  = (const float*)d_in[24];
    const float* u1w = (const float*)d_in[25]; const float* u1b = (const float*)d_in[26];
    const float* u2w = (const float*)d_in[27]; const float* u2b = (const float*)d_in[28];
    // d_in[29] = epoch (unused)

    float *t1,*ds,*t3,*t4,*t5,*t6,*blur,*r1,*r2,*u1,*part,*scale,*shift;
    cudaGetSymbolAddress((void**)&t1,   g_t1);
    cudaGetSymbolAddress((void**)&ds,   g_ds);
    cudaGetSymbolAddress((void**)&t3,   g_t3);
    cudaGetSymbolAddress((void**)&t4,   g_t4);
    cudaGetSymbolAddress((void**)&t5,   g_t5);
    cudaGetSymbolAddress((void**)&t6,   g_t6);
    cudaGetSymbolAddress((void**)&blur, g_blur);
    cudaGetSymbolAddress((void**)&r1,   g_r1);
    cudaGetSymbolAddress((void**)&r2,   g_r2);
    cudaGetSymbolAddress((void**)&u1,   g_u1);
    cudaGetSymbolAddress((void**)&part, g_part);
    cudaGetSymbolAddress((void**)&scale,g_scale);
    cudaGetSymbolAddress((void**)&shift,g_shift);

    // dynamic smem sizes (weights transposed + padded bias)
    auto smem = [](int cin, int coutp, int k) { return (size_t)(cin*k*k*coutp + coutp)*4; };

    // opt-in for >48KB dynamic smem instantiations (immediate host calls; idempotent)
    cudaFuncSetAttribute((const void*)conv_k<20,30,5,2,2,16,16,true>,
                         cudaFuncAttributeMaxDynamicSharedMemorySize, (int)smem(20,32,5));
    cudaFuncSetAttribute((const void*)conv_r1_k,
                         cudaFuncAttributeMaxDynamicSharedMemorySize, (int)((48*9*64 + 64)*4));

    // encoder
    conv_k<1, 8,3,2,1,256,256,true><<<(NB*128*128+127)/128,128, smem(1,8,3)>>> (x1, c1w, c1b, t1);
    conv_k<8,32,5,2,2,128,128,true><<<(NB*64*64 +127)/128,128, smem(8,32,5)>>> (t1, c2w, c2b, ds);
    conv_k<32,4,3,2,1, 64, 64,false><<<(NB*32*32+127)/128,128, smem(32,4,3)>>> (ds, c3w, c3b, t3);
    conv_k<4,20,3,2,1, 32, 32,true><<<(NB*16*16+127)/128,128, smem(4,20,3)>>>  (t3, c4w, c4b, t4);
    conv_k<20,30,5,2,2,16, 16,true><<<(NB*8*8  +127)/128,128, smem(20,32,5)>>> (t4, c5w, c5b, t5);
    conv_k<30, 8,3,2,1,  8,  8,true><<<(NB*4*4 +127)/128,128, smem(30,8,3)>>>  (t5, c6w, c6b, t6);
    conv7_k<<<(NB*16+127)/128,128>>>(t6, c7w, c7b, blur);

    // residual block with training-mode BN
    conv_r1_k<<<(NB*64*64+127)/128,128, (48*9*64 + 64)*4>>>(blur, ds, r1w, r1b, r1);
    { dim3 g(64,32); bn_part_k<64,4096><<<g,256>>>(r1, part); }
    bn_fin_k<64,4096><<<1,64>>>(part, g1, be1, scale, shift);
    bn_apply_k<64,4096,true><<<(NB*64*4096+255)/256,256>>>(r1, scale, shift);

    conv_k<64,20,3,1,1,64,64,false><<<(NB*64*64+127)/128,128, smem(64,20,3)>>>(r1, r2w, r2b, r2);
    { dim3 g(20,32); bn_part_k<20,4096><<<g,256>>>(r2, part); }
    bn_fin_k<20,4096><<<1,32>>>(part, g2, be2, scale, shift);
    bn2pw_k<<<(NB*4096+127)/128,128>>>(r2, blur, ds, pw, pb, scale, shift);

    // upsample head
    conv_k<20,30,3,1,1,64,64,true><<<(NB*64*64+127)/128,128, smem(20,32,3)>>>(r2, u1w, u1b, u1);
    final_k<<<(NB*4096+127)/128,128>>>(u1, u2w, u2b, (float*)d_out);
}

// round 2
// speedup vs baseline: 1.6810x; 1.6810x over previous
#include <cuda_runtime.h>
#include <cuda_bf16.h>
#include <math.h>

#define NB 128

// ---------------- scratch (device globals; no allocation allowed) ----------
__device__ float g_t1[(size_t)NB*8*128*128];    // conv1 out
__device__ float g_ds[(size_t)NB*32*64*64];     // conv2 out (skip "ds")
__device__ float g_t3[(size_t)NB*4*32*32];
__device__ float g_t4[(size_t)NB*20*16*16];
__device__ float g_t5[(size_t)NB*30*8*8];
__device__ float g_t6[(size_t)NB*8*4*4];
__device__ float g_blur[NB*16];
__device__ float g_r1[(size_t)NB*64*64*64];
__device__ float g_r2[(size_t)NB*20*64*64];
__device__ float g_u1[(size_t)NB*30*64*64];
__device__ float g_part[2*64*32];               // BN partial sums
__device__ float g_scale[64];
__device__ float g_shift[64];

// =====================================================================
// Blocked direct conv: PX output pixels along x per thread, CG output
// channels per block-group (blockIdx.y). Weights transposed [ci][ky][kx][co]
// in shared; each weight float4 LDS feeds PX*4 FFMAs. Input row values are
// register-cached (zero-filled OOB == zero padding, exact).
// =====================================================================
template<int CIN,int COUT,int CG,int PX,int K,int S,int P,int HIN,int WIN,bool RELU>
__global__ __launch_bounds__(128) void convb_k(
    const float* __restrict__ in, const float* __restrict__ w,
    const float* __restrict__ bias, float* __restrict__ out)
{
    constexpr int HOUT = (HIN + 2*P - K)/S + 1;
    constexpr int WOUT = (WIN + 2*P - K)/S + 1;
    constexpr int CGP  = (CG + 3) & ~3;
    constexpr int IW   = (PX-1)*S + K;
    static_assert(WOUT % PX == 0, "");
    extern __shared__ float sw[];                 // CIN*K*K*CGP + CGP
    float* sb = sw + CIN*K*K*CGP;
    const int co0 = blockIdx.y * CG;
    for (int i = threadIdx.x; i < CIN*K*K*CGP; i += blockDim.x) {
        int co = i % CGP; int r = i / CGP;
        sw[i] = (co < CG) ? w[(size_t)(co0+co)*CIN*K*K + r] : 0.f;
    }
    for (int i = threadIdx.x; i < CGP; i += blockDim.x)
        sb[i] = (i < CG) ? bias[co0 + i] : 0.f;
    __syncthreads();

    int idx = blockIdx.x*blockDim.x + threadIdx.x;
    constexpr int XB = WOUT / PX;
    if (idx >= NB*HOUT*XB) return;
    int xb = (idx % XB) * PX;
    int oy = (idx / XB) % HOUT;
    int n  = idx / (XB*HOUT);

    float acc[PX][CGP];
    #pragma unroll
    for (int p = 0; p < PX; p++)
        #pragma unroll
        for (int c = 0; c < CGP; c++) acc[p][c] = sb[c];

    const float* inp = in + (size_t)n*CIN*HIN*WIN;
    const int ix0 = xb*S - P;
    #pragma unroll 1
    for (int ci = 0; ci < CIN; ci++) {
        #pragma unroll
        for (int ky = 0; ky < K; ky++) {
            int iy = oy*S - P + ky;
            if (iy < 0 || iy >= HIN) continue;
            const float* row = inp + (size_t)ci*HIN*WIN + (size_t)iy*WIN;
            float v[IW];
            #pragma unroll
            for (int j = 0; j < IW; j++) {
                int ix = ix0 + j;
                v[j] = (ix >= 0 && ix < WIN) ? __ldg(row + ix) : 0.f;
            }
            #pragma unroll
            for (int kx = 0; kx < K; kx++) {
                const float* wp = &sw[((ci*K+ky)*K+kx)*CGP];
                #pragma unroll
                for (int c = 0; c < CGP; c += 4) {
                    float4 w4 = *reinterpret_cast<const float4*>(wp + c);
                    #pragma unroll
                    for (int p = 0; p < PX; p++) {
                        float vv = v[p*S + kx];
                        acc[p][c+0] = fmaf(vv, w4.x, acc[p][c+0]);
                        acc[p][c+1] = fmaf(vv, w4.y, acc[p][c+1]);
                        acc[p][c+2] = fmaf(vv, w4.z, acc[p][c+2]);
                        acc[p][c+3] = fmaf(vv, w4.w, acc[p][c+3]);
                    }
                }
            }
        }
    }
    float* op = out + ((size_t)n*COUT + co0)*HOUT*WOUT + (size_t)oy*WOUT + xb;
    #pragma unroll
    for (int c = 0; c < CG; c++)
        #pragma unroll
        for (int p = 0; p < PX; p++) {
            float vv = acc[p][c];
            if (RELU) vv = fmaxf(vv, 0.f);
            op[(size_t)c*HOUT*WOUT + p] = vv;
        }
}

// ---------------- legacy per-pixel conv (tail kernels, tiny grids) ---------
template<int CIN,int COUT,int K,int S,int P,int HIN,int WIN,bool RELU>
__global__ __launch_bounds__(128) void conv_k(
    const float* __restrict__ in, const float* __restrict__ w,
    const float* __restrict__ bias, float* __restrict__ out)
{
    constexpr int HOUT = (HIN + 2*P - K)/S + 1;
    constexpr int WOUT = (WIN + 2*P - K)/S + 1;
    constexpr int COUTP = (COUT + 3) & ~3;
    extern __shared__ float sw[];
    float* sb = sw + CIN*K*K*COUTP;
    for (int i = threadIdx.x; i < CIN*K*K*COUTP; i += blockDim.x) {
        int co = i % COUTP; int r = i / COUTP;
        sw[i] = (co < COUT) ? w[co*CIN*K*K + r] : 0.f;
    }
    for (int i = threadIdx.x; i < COUTP; i += blockDim.x)
        sb[i] = (i < COUT) ? bias[i] : 0.f;
    __syncthreads();

    int idx = blockIdx.x*blockDim.x + threadIdx.x;
    if (idx >= NB*HOUT*WOUT) return;
    int ox = idx % WOUT; int oy = (idx/WOUT) % HOUT; int n = idx/(WOUT*HOUT);

    float acc[COUTP];
    #pragma unroll
    for (int c = 0; c < COUTP; c++) acc[c] = sb[c];

    const float* inp = in + (size_t)n*CIN*HIN*WIN;
    #pragma unroll 1
    for (int ci = 0; ci < CIN; ci++) {
        #pragma unroll
        for (int ky = 0; ky < K; ky++) {
            int iy = oy*S - P + ky;
            if (iy < 0 || iy >= HIN) continue;
            #pragma unroll
            for (int kx = 0; kx < K; kx++) {
                int ix = ox*S - P + kx;
                if (ix < 0 || ix >= WIN) continue;
                float v = __ldg(&inp[(size_t)ci*HIN*WIN + (size_t)iy*WIN + ix]);
                const float* wp = &sw[((ci*K+ky)*K+kx)*COUTP];
                #pragma unroll
                for (int co = 0; co < COUTP; co += 4) {
                    float4 w4 = *reinterpret_cast<const float4*>(wp + co);
                    acc[co+0] = fmaf(v, w4.x, acc[co+0]);
                    acc[co+1] = fmaf(v, w4.y, acc[co+1]);
                    acc[co+2] = fmaf(v, w4.z, acc[co+2]);
                    acc[co+3] = fmaf(v, w4.w, acc[co+3]);
                }
            }
        }
    }
    float* op = out + ((size_t)n*COUT*HOUT + (size_t)oy)*WOUT + ox;
    #pragma unroll
    for (int co = 0; co < COUT; co++) {
        float v = acc[co];
        if (RELU) v = fmaxf(v, 0.f);
        op[(size_t)co*HOUT*WOUT] = v;
    }
}

// ---------------- conv7: 1x1, 8->1 over 4x4, -> blur[n][16] ----------------
__global__ void conv7_k(const float* __restrict__ t6, const float* __restrict__ w,
                        const float* __restrict__ b, float* __restrict__ blur)
{
    int i = blockIdx.x*blockDim.x + threadIdx.x;
    if (i >= NB*16) return;
    int n = i >> 4, p = i & 15;
    float acc = b[0];
    #pragma unroll
    for (int ci = 0; ci < 8; ci++)
        acc = fmaf(t6[(n*8 + ci)*16 + p], w[ci], acc);
    blur[i] = fmaxf(acc, 0.f);
}

// ---------------- r1 conv: virtual pre = [blur(16 scalar ch) | ds(32 ch)] --
// PX=2 pixels/thread, CG=32 channels/group (blockIdx.y in {0,1}).
__global__ __launch_bounds__(128) void conv_r1b_k(
    const float* __restrict__ blur, const float* __restrict__ ds,
    const float* __restrict__ w, const float* __restrict__ bias,
    float* __restrict__ out)
{
    constexpr int CG = 32, PX = 2, IW = 4;
    extern __shared__ float sw[];                 // 48*9*32 + 32
    float* sb = sw + 48*9*CG;
    const int co0 = blockIdx.y * CG;
    for (int i = threadIdx.x; i < 48*9*CG; i += blockDim.x) {
        int co = i % CG; int r = i / CG;
        sw[i] = w[(size_t)(co0+co)*48*9 + r];
    }
    for (int i = threadIdx.x; i < CG; i += blockDim.x) sb[i] = bias[co0 + i];
    __syncthreads();

    int idx = blockIdx.x*blockDim.x + threadIdx.x;
    if (idx >= NB*64*32) return;
    int xb = (idx & 31) * PX;
    int oy = (idx >> 5) & 63;
    int n  = idx >> 11;

    float acc[PX][CG];
    #pragma unroll
    for (int p = 0; p < PX; p++)
        #pragma unroll
        for (int c = 0; c < CG; c++) acc[p][c] = sb[c];

    const int ix0 = xb - 1;
    // --- blur channels: per-(n,ci) scalar with zero padding at borders ---
    #pragma unroll 1
    for (int ci = 0; ci < 16; ci++) {
        float bval = blur[n*16 + ci];
        #pragma unroll
        for (int ky = 0; ky < 3; ky++) {
            int iy = oy - 1 + ky;
            if (iy < 0 || iy >= 64) continue;
            float v[IW];
            #pragma unroll
            for (int j = 0; j < IW; j++) {
                int ix = ix0 + j;
                v[j] = (ix >= 0 && ix < 64) ? bval : 0.f;
            }
            #pragma unroll
            for (int kx = 0; kx < 3; kx++) {
                const float* wp = &sw[((ci*3+ky)*3+kx)*CG];
                #pragma unroll
                for (int c = 0; c < CG; c += 4) {
                    float4 w4 = *reinterpret_cast<const float4*>(wp + c);
                    #pragma unroll
                    for (int p = 0; p < PX; p++) {
                        float vv = v[p + kx];
                        acc[p][c+0] = fmaf(vv, w4.x, acc[p][c+0]);
                        acc[p][c+1] = fmaf(vv, w4.y, acc[p][c+1]);
                        acc[p][c+2] = fmaf(vv, w4.z, acc[p][c+2]);
                        acc[p][c+3] = fmaf(vv, w4.w, acc[p][c+3]);
                    }
                }
            }
        }
    }
    // --- ds channels ---
    const float* dsp = ds + (size_t)n*32*4096;
    #pragma unroll 1
    for (int ci = 0; ci < 32; ci++) {
        #pragma unroll
        for (int ky = 0; ky < 3; ky++) {
            int iy = oy - 1 + ky;
            if (iy < 0 || iy >= 64) continue;
            const float* row = dsp + (size_t)ci*4096 + iy*64;
            float v[IW];
            #pragma unroll
            for (int j = 0; j < IW; j++) {
                int ix = ix0 + j;
                v[j] = (ix >= 0 && ix < 64) ? __ldg(row + ix) : 0.f;
            }
            #pragma unroll
            for (int kx = 0; kx < 3; kx++) {
                const float* wp = &sw[(((16+ci)*3+ky)*3+kx)*CG];
                #pragma unroll
                for (int c = 0; c < CG; c += 4) {
                    float4 w4 = *reinterpret_cast<const float4*>(wp + c);
                    #pragma unroll
                    for (int p = 0; p < PX; p++) {
                        float vv = v[p + kx];
                        acc[p][c+0] = fmaf(vv, w4.x, acc[p][c+0]);
                        acc[p][c+1] = fmaf(vv, w4.y, acc[p][c+1]);
                        acc[p][c+2] = fmaf(vv, w4.z, acc[p][c+2]);
                        acc[p][c+3] = fmaf(vv, w4.w, acc[p][c+3]);
                    }
                }
            }
        }
    }
    float* op = out + ((size_t)n*64 + co0)*4096 + oy*64 + xb;
    #pragma unroll
    for (int c = 0; c < CG; c++)
        #pragma unroll
        for (int p = 0; p < PX; p++)
            op[(size_t)c*4096 + p] = acc[p][c];
}

// ---------------- BatchNorm: deterministic 2-stage stats (float4) ----------
template<int C, int HW>
__global__ void bn_part_k(const float* __restrict__ x, float* __restrict__ part)
{
    int c = blockIdx.x;
    float s = 0.f, s2 = 0.f;
    constexpr int HW4 = HW/4;
    const int per = NB*HW4;
    for (int i = blockIdx.y*blockDim.x + threadIdx.x; i < per; i += gridDim.y*blockDim.x) {
        int n = i / HW4; int j = i - n*HW4;
        float4 v = *reinterpret_cast<const float4*>(&x[((size_t)n*C + c)*HW + j*4]);
        s  += (v.x + v.y) + (v.z + v.w);
        s2 += (v.x*v.x + v.y*v.y) + (v.z*v.z + v.w*v.w);
    }
    __shared__ float rs[256], rs2[256];
    rs[threadIdx.x] = s; rs2[threadIdx.x] = s2;
    __syncthreads();
    for (int o = blockDim.x/2; o > 0; o >>= 1) {
        if (threadIdx.x < o) {
            rs[threadIdx.x]  += rs[threadIdx.x + o];
            rs2[threadIdx.x] += rs2[threadIdx.x + o];
        }
        __syncthreads();
    }
    if (threadIdx.x == 0) {
        part[c*32 + blockIdx.y]        = rs[0];
        part[C*32 + c*32 + blockIdx.y] = rs2[0];
    }
}

template<int C, int HW>
__global__ void bn_fin_k(const float* __restrict__ part, const float* __restrict__ g,
                         const float* __restrict__ be, float* __restrict__ scale,
                         float* __restrict__ shift)
{
    int c = threadIdx.x;
    if (c >= C) return;
    float s = 0.f, s2 = 0.f;
    for (int b = 0; b < 32; b++) { s += part[c*32 + b]; s2 += part[C*32 + c*32 + b]; }
    const float cnt = (float)NB * (float)HW;
    float mu  = s / cnt;
    float var = s2 / cnt - mu*mu;
    float sc  = g[c] * rsqrtf(var + 1e-5f);
    scale[c] = sc;
    shift[c] = be[c] - mu*sc;
}

template<int C, int HW, bool RELU>
__global__ void bn_apply_k(float* __restrict__ x, const float* __restrict__ scale,
                           const float* __restrict__ shift)
{
    constexpr int HW4 = HW/4;
    int i = blockIdx.x*blockDim.x + threadIdx.x;
    if (i >= NB*C*HW4) return;
    int c = (i / HW4) % C;
    float sc = scale[c], sh = shift[c];
    float4 v = *reinterpret_cast<const float4*>(&x[(size_t)i*4]);
    v.x = fmaf(v.x, sc, sh); v.y = fmaf(v.y, sc, sh);
    v.z = fmaf(v.z, sc, sh); v.w = fmaf(v.w, sc, sh);
    if (RELU) {
        v.x = fmaxf(v.x, 0.f); v.y = fmaxf(v.y, 0.f);
        v.z = fmaxf(v.z, 0.f); v.w = fmaxf(v.w, 0.f);
    }
    *reinterpret_cast<float4*>(&x[(size_t)i*4]) = v;
}

// ---------------- bn2 apply + pointwise(pre) residual add (in place) -------
__global__ __launch_bounds__(128) void bn2pw_k(
    float* __restrict__ r2, const float* __restrict__ blur,
    const float* __restrict__ ds, const float* __restrict__ pw,
    const float* __restrict__ pb, const float* __restrict__ scale,
    const float* __restrict__ shift)
{
    __shared__ float sw[48*20];   // transposed [ci][co]
    __shared__ float sb[20], ssc[20], ssh[20];
    for (int i = threadIdx.x; i < 48*20; i += blockDim.x) {
        int co = i % 20, ci = i / 20;
        sw[i] = pw[co*48 + ci];
    }
    if (threadIdx.x < 20) {
        sb[threadIdx.x]  = pb[threadIdx.x];
        ssc[threadIdx.x] = scale[threadIdx.x];
        ssh[threadIdx.x] = shift[threadIdx.x];
    }
    __syncthreads();

    int idx = blockIdx.x*blockDim.x + threadIdx.x;
    if (idx >= NB*4096) return;
    int p = idx & 4095; int n = idx >> 12;

    float acc[20];
    #pragma unroll
    for (int c = 0; c < 20; c++) acc[c] = sb[c];

    #pragma unroll 1
    for (int ci = 0; ci < 16; ci++) {
        float v = blur[n*16 + ci];
        #pragma unroll
        for (int c = 0; c < 20; c += 4) {
            float4 w4 = *reinterpret_cast<const float4*>(&sw[ci*20 + c]);
            acc[c+0] = fmaf(v, w4.x, acc[c+0]);
            acc[c+1] = fmaf(v, w4.y, acc[c+1]);
            acc[c+2] = fmaf(v, w4.z, acc[c+2]);
            acc[c+3] = fmaf(v, w4.w, acc[c+3]);
        }
    }
    const float* dsp = ds + (size_t)n*32*4096 + p;
    #pragma unroll 1
    for (int ci = 0; ci < 32; ci++) {
        float v = __ldg(&dsp[(size_t)ci*4096]);
        #pragma unroll
        for (int c = 0; c < 20; c += 4) {
            float4 w4 = *reinterpret_cast<const float4*>(&sw[(16+ci)*20 + c]);
            acc[c+0] = fmaf(v, w4.x, acc[c+0]);
            acc[c+1] = fmaf(v, w4.y, acc[c+1]);
            acc[c+2] = fmaf(v, w4.z, acc[c+2]);
            acc[c+3] = fmaf(v, w4.w, acc[c+3]);
        }
    }
    float* rp = r2 + (size_t)n*20*4096 + p;
    #pragma unroll
    for (int c = 0; c < 20; c++) {
        float v = fmaf(rp[(size_t)c*4096], ssc[c], ssh[c]) + acc[c];
        rp[(size_t)c*4096] = v;
    }
}

// ---------------- final: u2 1x1 (30->16) + relu + pixel_shuffle(4) + sigmoid
__global__ __launch_bounds__(128) void final_k(
    const float* __restrict__ u1, const float* __restrict__ w,
    const float* __restrict__ b, float* __restrict__ out)
{
    __shared__ float sw[30*16];   // transposed [ci][co]
    __shared__ float sb[16];
    for (int i = threadIdx.x; i < 30*16; i += blockDim.x) {
        int co = i % 16, ci = i / 16;
        sw[i] = w[co*30 + ci];
    }
    if (threadIdx.x < 16) sb[threadIdx.x] = b[threadIdx.x];
    __syncthreads();

    int idx = blockIdx.x*blockDim.x + threadIdx.x;
    if (idx >= NB*4096) return;
    int wq = idx & 63; int h = (idx >> 6) & 63; int n = idx >> 12;

    float acc[16];
    #pragma unroll
    for (int c = 0; c < 16; c++) acc[c] = sb[c];

    const float* up = u1 + (size_t)n*30*4096 + h*64 + wq;
    #pragma unroll 1
    for (int ci = 0; ci < 30; ci++) {
        float v = __ldg(&up[(size_t)ci*4096]);
        #pragma unroll
        for (int c = 0; c < 16; c += 4) {
            float4 w4 = *reinterpret_cast<const float4*>(&sw[ci*16 + c]);
            acc[c+0] = fmaf(v, w4.x, acc[c+0]);
            acc[c+1] = fmaf(v, w4.y, acc[c+1]);
            acc[c+2] = fmaf(v, w4.z, acc[c+2]);
            acc[c+3] = fmaf(v, w4.w, acc[c+3]);
        }
    }
    float* op = out + (size_t)n*65536;
    #pragma unroll
    for (int c = 0; c < 16; c++) {
        float v = fmaxf(acc[c], 0.f);
        v = 1.f / (1.f + expf(-v));
        op[(h*4 + (c >> 2))*256 + wq*4 + (c & 3)] = v;
    }
}

// ---------------------------------------------------------------------------
extern "C" void kernel_launch(void* const* d_in, const int* in_sizes, int n_in,
                              void* d_out, int out_size)
{
    const float* x1  = (const float*)d_in[0];
    const float* c1w = (const float*)d_in[1];  const float* c1b = (const float*)d_in[2];
    const float* c2w = (const float*)d_in[3];  const float* c2b = (const float*)d_in[4];
    const float* c3w = (const float*)d_in[5];  const float* c3b = (const float*)d_in[6];
    const float* c4w = (const float*)d_in[7];  const float* c4b = (const float*)d_in[8];
    const float* c5w = (const float*)d_in[9];  const float* c5b = (const float*)d_in[10];
    const float* c6w = (const float*)d_in[11]; const float* c6b = (const float*)d_in[12];
    const float* c7w = (const float*)d_in[13]; const float* c7b = (const float*)d_in[14];
    const float* r1w = (const float*)d_in[15]; const float* r1b = (const float*)d_in[16];
    const float* g1  = (const float*)d_in[17]; const float* be1 = (const float*)d_in[18];
    const float* r2w = (const float*)d_in[19]; const float* r2b = (const float*)d_in[20];
    const float* g2  = (const float*)d_in[21]; const float* be2 = (const float*)d_in[22];
    const float* pw  = (const float*)d_in[23]; const float* pb  = (const float*)d_in[24];
    const float* u1w = (const float*)d_in[25]; const float* u1b = (const float*)d_in[26];
    const float* u2w = (const float*)d_in[27]; const float* u2b = (const float*)d_in[28];
    // d_in[29] = epoch (unused)

    float *t1,*ds,*t3,*t4,*t5,*t6,*blur,*r1,*r2,*u1,*part,*scale,*shift;
    cudaGetSymbolAddress((void**)&t1,   g_t1);
    cudaGetSymbolAddress((void**)&ds,   g_ds);
    cudaGetSymbolAddress((void**)&t3,   g_t3);
    cudaGetSymbolAddress((void**)&t4,   g_t4);
    cudaGetSymbolAddress((void**)&t5,   g_t5);
    cudaGetSymbolAddress((void**)&t6,   g_t6);
    cudaGetSymbolAddress((void**)&blur, g_blur);
    cudaGetSymbolAddress((void**)&r1,   g_r1);
    cudaGetSymbolAddress((void**)&r2,   g_r2);
    cudaGetSymbolAddress((void**)&u1,   g_u1);
    cudaGetSymbolAddress((void**)&part, g_part);
    cudaGetSymbolAddress((void**)&scale,g_scale);
    cudaGetSymbolAddress((void**)&shift,g_shift);

    auto smem  = [](int cin, int coutp, int k) { return (size_t)(cin*k*k*coutp + coutp)*4; };

    // opt-in for >48KB dynamic smem instantiations
    cudaFuncSetAttribute((const void*)conv_k<20,30,5,2,2,16,16,true>,
                         cudaFuncAttributeMaxDynamicSharedMemorySize, (int)smem(20,32,5));
    cudaFuncSetAttribute((const void*)conv_r1b_k,
                         cudaFuncAttributeMaxDynamicSharedMemorySize, (int)((48*9*32 + 32)*4));

    // ---------------- encoder ----------------
    // conv1: 1->8, k3 s2, 256->128, PX=4
    convb_k<1,8,8,4,3,2,1,256,256,true>
        <<<(NB*128*32+127)/128,128, smem(1,8,3)>>>(x1, c1w, c1b, t1);
    // conv2: 8->32, k5 s2, 128->64, PX=2
    convb_k<8,32,32,2,5,2,2,128,128,true>
        <<<(NB*64*32+127)/128,128, smem(8,32,5)>>>(t1, c2w, c2b, ds);
    // tail encoder (tiny)
    conv_k<32,4,3,2,1, 64, 64,false><<<(NB*32*32+127)/128,128, smem(32,4,3)>>> (ds, c3w, c3b, t3);
    conv_k<4,20,3,2,1, 32, 32,true><<<(NB*16*16+127)/128,128, smem(4,20,3)>>>  (t3, c4w, c4b, t4);
    conv_k<20,30,5,2,2,16, 16,true><<<(NB*8*8  +127)/128,128, smem(20,32,5)>>> (t4, c5w, c5b, t5);
    conv_k<30, 8,3,2,1,  8,  8,true><<<(NB*4*4 +127)/128,128, smem(30,8,3)>>>  (t5, c6w, c6b, t6);
    conv7_k<<<(NB*16+127)/128,128>>>(t6, c7w, c7b, blur);

    // ---------------- residual block with training-mode BN ----------------
    {
        dim3 g((NB*64*32+127)/128, 2);
        conv_r1b_k<<<g,128, (48*9*32 + 32)*4>>>(blur, ds, r1w, r1b, r1);
    }
    { dim3 g(64,32); bn_part_k<64,4096><<<g,256>>>(r1, part); }
    bn_fin_k<64,4096><<<1,64>>>(part, g1, be1, scale, shift);
    bn_apply_k<64,4096,true><<<(NB*64*1024+255)/256,256>>>(r1, scale, shift);

    // r2: 64->20, k3 s1, 64x64, PX=2
    convb_k<64,20,20,2,3,1,1,64,64,false>
        <<<(NB*64*32+127)/128,128, smem(64,20,3)>>>(r1, r2w, r2b, r2);
    { dim3 g(20,32); bn_part_k<20,4096><<<g,256>>>(r2, part); }
    bn_fin_k<20,4096><<<1,32>>>(part, g2, be2, scale, shift);
    bn2pw_k<<<(NB*4096+127)/128,128>>>(r2, blur, ds, pw, pb, scale, shift);

    // ---------------- upsample head ----------------
    // u1: 20->30, k3 s1, 64x64, PX=2
    convb_k<20,30,30,2,3,1,1,64,64,true>
        <<<(NB*64*32+127)/128,128, smem(20,32,3)>>>(r2, u1w, u1b, u1);
    final_k<<<(NB*4096+127)/128,128>>>(u1, u2w, u2b, (float*)d_out);
}

// round 3
// speedup vs baseline: 1.9033x; 1.1322x over previous
#include <cuda_runtime.h>
#include <cuda_bf16.h>
#include <math.h>

#define NB 128

// ---------------- scratch (device globals; no allocation allowed) ----------
__device__ float g_t1[(size_t)NB*8*128*128];
__device__ float g_ds[(size_t)NB*32*64*64];
__device__ float g_t3[(size_t)NB*4*32*32];
__device__ float g_t4[(size_t)NB*20*16*16];
__device__ float g_t5[(size_t)NB*30*8*8];
__device__ float g_t6[(size_t)NB*8*4*4];
__device__ float g_blur[NB*16];
__device__ float g_r1[(size_t)NB*64*64*64];
__device__ float g_r2[(size_t)NB*20*64*64];
__device__ float g_u1[(size_t)NB*30*64*64];
__device__ float g_part[2*64*32];
__device__ float g_scale[64];
__device__ float g_shift[64];
__device__ float g_contrib[NB*9*64];   // blur-part of r1 per (n, border-combo, co)
__device__ float g_pwblur[NB*20];      // blur-part of pointwise conv per (n, co)

// ---------------- packed f32x2 helpers (sm_103a FFMA2) ---------------------
typedef unsigned long long u64;
static __device__ __forceinline__ u64 pack2(float x, float y) {
    u64 r; asm("mov.b64 %0, {%1, %2};" : "=l"(r) : "f"(x), "f"(y)); return r;
}
static __device__ __forceinline__ u64 bcast2(float x) { return pack2(x, x); }
static __device__ __forceinline__ void fma2(u64& d, u64 a, u64 b) {
    asm("fma.rn.f32x2 %0, %1, %2, %0;" : "+l"(d) : "l"(a), "l"(b));
}
static __device__ __forceinline__ float2 unpack2(u64 v) {
    float2 r; asm("mov.b64 {%0, %1}, %2;" : "=f"(r.x), "=f"(r.y) : "l"(v)); return r;
}

// =====================================================================
// Packed direct conv: PX pixels/thread, CG output channels (blockIdx.y
// group), channel PAIRS in 64-bit accumulators driven by fma.rn.f32x2.
// Optional fused input BatchNorm(scale,shift)+ReLU (BNIN).
// =====================================================================
template<int CIN,int COUT,int CG,int PX,int K,int S,int P,int HIN,int WIN,bool RELU,bool BNIN>
__global__ __launch_bounds__(128) void convp_k(
    const float* __restrict__ in, const float* __restrict__ w,
    const float* __restrict__ bias, const float* __restrict__ bnsc,
    const float* __restrict__ bnsh, float* __restrict__ out)
{
    constexpr int HOUT = (HIN + 2*P - K)/S + 1;
    constexpr int WOUT = (WIN + 2*P - K)/S + 1;
    constexpr int CGP  = (CG + 3) & ~3;
    constexpr int NP   = CGP/2;
    constexpr int IW   = (PX-1)*S + K;
    static_assert(WOUT % PX == 0 && CG % 2 == 0, "");
    extern __shared__ float sw[];            // CIN*K*K*CGP | CGP bias | [2*CIN bn]
    float* sb  = sw + CIN*K*K*CGP;
    float* ssc = sb + CGP;
    float* ssh = ssc + (BNIN ? CIN : 0);
    const int co0 = blockIdx.y * CG;
    for (int i = threadIdx.x; i < CIN*K*K*CGP; i += blockDim.x) {
        int co = i % CGP; int r = i / CGP;
        sw[i] = (co < CG) ? w[(size_t)(co0+co)*CIN*K*K + r] : 0.f;
    }
    for (int i = threadIdx.x; i < CGP; i += blockDim.x)
        sb[i] = (i < CG) ? bias[co0 + i] : 0.f;
    if (BNIN) {
        for (int i = threadIdx.x; i < CIN; i += blockDim.x) {
            ssc[i] = bnsc[i]; ssh[i] = bnsh[i];
        }
    }
    __syncthreads();

    constexpr int XB = WOUT / PX;
    int idx = blockIdx.x*blockDim.x + threadIdx.x;
    if (idx >= NB*HOUT*XB) return;
    int xb = (idx % XB) * PX;
    int oy = (idx / XB) % HOUT;
    int n  = idx / (XB*HOUT);

    u64 acc[PX][NP];
    #pragma unroll
    for (int p = 0; p < PX; p++)
        #pragma unroll
        for (int j = 0; j < NP; j++) acc[p][j] = pack2(sb[2*j], sb[2*j+1]);

    const float* inp = in + (size_t)n*CIN*HIN*WIN;
    const int ix0 = xb*S - P;
    #pragma unroll 1
    for (int ci = 0; ci < CIN; ci++) {
        float isc = 0.f, ish = 0.f;
        if (BNIN) { isc = ssc[ci]; ish = ssh[ci]; }
        #pragma unroll
        for (int ky = 0; ky < K; ky++) {
            int iy = oy*S - P + ky;
            if (iy < 0 || iy >= HIN) continue;
            const float* row = inp + (size_t)ci*HIN*WIN + (size_t)iy*WIN;
            u64 v2[IW];
            #pragma unroll
            for (int j = 0; j < IW; j++) {
                int ix = ix0 + j;
                float raw = (ix >= 0 && ix < WIN) ? __ldg(row + ix) : 0.f;
                if (BNIN) raw = (ix >= 0 && ix < WIN) ? fmaxf(fmaf(raw, isc, ish), 0.f) : 0.f;
                v2[j] = bcast2(raw);
            }
            #pragma unroll
            for (int kx = 0; kx < K; kx++) {
                const float* wp = &sw[((ci*K+ky)*K+kx)*CGP];
                #pragma unroll
                for (int j = 0; j < NP; j += 2) {
                    ulonglong2 wq = *reinterpret_cast<const ulonglong2*>(wp + 2*j);
                    #pragma unroll
                    for (int p = 0; p < PX; p++) {
                        fma2(acc[p][j],   v2[p*S+kx], wq.x);
                        fma2(acc[p][j+1], v2[p*S+kx], wq.y);
                    }
                }
            }
        }
    }
    float* op = out + ((size_t)n*COUT + co0)*HOUT*WOUT + (size_t)oy*WOUT + xb;
    #pragma unroll
    for (int j = 0; j < CG/2; j++)
        #pragma unroll
        for (int p = 0; p < PX; p++) {
            float2 a = unpack2(acc[p][j]);
            if (RELU) { a.x = fmaxf(a.x, 0.f); a.y = fmaxf(a.y, 0.f); }
            op[(size_t)(2*j)  *HOUT*WOUT + p] = a.x;
            op[(size_t)(2*j+1)*HOUT*WOUT + p] = a.y;
        }
}

// ---------------- legacy per-pixel conv (tiny tail kernels) ----------------
template<int CIN,int COUT,int K,int S,int P,int HIN,int WIN,bool RELU>
__global__ __launch_bounds__(128) void conv_k(
    const float* __restrict__ in, const float* __restrict__ w,
    const float* __restrict__ bias, float* __restrict__ out)
{
    constexpr int HOUT = (HIN + 2*P - K)/S + 1;
    constexpr int WOUT = (WIN + 2*P - K)/S + 1;
    constexpr int COUTP = (COUT + 3) & ~3;
    extern __shared__ float sw[];
    float* sb = sw + CIN*K*K*COUTP;
    for (int i = threadIdx.x; i < CIN*K*K*COUTP; i += blockDim.x) {
        int co = i % COUTP; int r = i / COUTP;
        sw[i] = (co < COUT) ? w[co*CIN*K*K + r] : 0.f;
    }
    for (int i = threadIdx.x; i < COUTP; i += blockDim.x)
        sb[i] = (i < COUT) ? bias[i] : 0.f;
    __syncthreads();

    int idx = blockIdx.x*blockDim.x + threadIdx.x;
    if (idx >= NB*HOUT*WOUT) return;
    int ox = idx % WOUT; int oy = (idx/WOUT) % HOUT; int n = idx/(WOUT*HOUT);

    float acc[COUTP];
    #pragma unroll
    for (int c = 0; c < COUTP; c++) acc[c] = sb[c];

    const float* inp = in + (size_t)n*CIN*HIN*WIN;
    #pragma unroll 1
    for (int ci = 0; ci < CIN; ci++) {
        #pragma unroll
        for (int ky = 0; ky < K; ky++) {
            int iy = oy*S - P + ky;
            if (iy < 0 || iy >= HIN) continue;
            #pragma unroll
            for (int kx = 0; kx < K; kx++) {
                int ix = ox*S - P + kx;
                if (ix < 0 || ix >= WIN) continue;
                float v = __ldg(&inp[(size_t)ci*HIN*WIN + (size_t)iy*WIN + ix]);
                const float* wp = &sw[((ci*K+ky)*K+kx)*COUTP];
                #pragma unroll
                for (int co = 0; co < COUTP; co += 4) {
                    float4 w4 = *reinterpret_cast<const float4*>(wp + co);
                    acc[co+0] = fmaf(v, w4.x, acc[co+0]);
                    acc[co+1] = fmaf(v, w4.y, acc[co+1]);
                    acc[co+2] = fmaf(v, w4.z, acc[co+2]);
                    acc[co+3] = fmaf(v, w4.w, acc[co+3]);
                }
            }
        }
    }
    float* op = out + ((size_t)n*COUT*HOUT + (size_t)oy)*WOUT + ox;
    #pragma unroll
    for (int co = 0; co < COUT; co++) {
        float v = acc[co];
        if (RELU) v = fmaxf(v, 0.f);
        op[(size_t)co*HOUT*WOUT] = v;
    }
}

// ---------------- conv7: 1x1, 8->1 over 4x4 -> blur[n][16] -----------------
__global__ void conv7_k(const float* __restrict__ t6, const float* __restrict__ w,
                        const float* __restrict__ b, float* __restrict__ blur)
{
    int i = blockIdx.x*blockDim.x + threadIdx.x;
    if (i >= NB*16) return;
    int n = i >> 4, p = i & 15;
    float acc = b[0];
    #pragma unroll
    for (int ci = 0; ci < 8; ci++)
        acc = fmaf(t6[(n*8 + ci)*16 + p], w[ci], acc);
    blur[i] = fmaxf(acc, 0.f);
}

// ---------------- blur precompute: r1 blur contribution per border combo ---
// combo = vy*3+vx; vy/vx: 0 = top/left edge (first tap row/col invalid),
// 1 = interior (all taps), 2 = bottom/right edge (last tap row/col invalid).
__global__ void blurpre_k(const float* __restrict__ blur, const float* __restrict__ r1w,
                          const float* __restrict__ pw, float* __restrict__ contrib,
                          float* __restrict__ pwblur)
{
    int n = blockIdx.x;          // 0..127
    int co = threadIdx.x;        // 0..63
    float s[9];
    #pragma unroll
    for (int q = 0; q < 9; q++) s[q] = 0.f;
    for (int ci = 0; ci < 16; ci++) {
        float bv = blur[n*16 + ci];
        const float* tw = r1w + ((size_t)co*48 + ci)*9;
        float t[9];
        #pragma unroll
        for (int q = 0; q < 9; q++) t[q] = tw[q];
        float cs[3][3];
        #pragma unroll
        for (int ky = 0; ky < 3; ky++) {
            cs[ky][0] = t[ky*3+1] + t[ky*3+2];          // left edge: kx in {1,2}
            cs[ky][1] = t[ky*3+0] + t[ky*3+1] + t[ky*3+2];
            cs[ky][2] = t[ky*3+0] + t[ky*3+1];          // right edge: kx in {0,1}
        }
        #pragma unroll
        for (int vx = 0; vx < 3; vx++) {
            float r0 = cs[1][vx] + cs[2][vx];           // top edge: ky in {1,2}
            float r1v = cs[0][vx] + cs[1][vx] + cs[2][vx];
            float r2 = cs[0][vx] + cs[1][vx];           // bottom edge
            s[0*3+vx] = fmaf(bv, r0,  s[0*3+vx]);
            s[1*3+vx] = fmaf(bv, r1v, s[1*3+vx]);
            s[2*3+vx] = fmaf(bv, r2,  s[2*3+vx]);
        }
    }
    #pragma unroll
    for (int q = 0; q < 9; q++) contrib[((size_t)n*9 + q)*64 + co] = s[q];

    if (co < 20) {
        float q = 0.f;
        for (int ci = 0; ci < 16; ci++)
            q = fmaf(blur[n*16 + ci], pw[co*48 + ci], q);
        pwblur[n*20 + co] = q;
    }
}

// ---------------- r1 conv over ds channels only (blur part precomputed) ----
__global__ __launch_bounds__(128) void conv_r1p_k(
    const float* __restrict__ ds, const float* __restrict__ w,
    const float* __restrict__ bias, const float* __restrict__ contrib,
    float* __restrict__ out)
{
    constexpr int CG = 32, PX = 2, NP = CG/2, IW = 4;
    extern __shared__ float sw[];            // 32*9*32 + 32
    float* sb = sw + 32*9*CG;
    const int co0 = blockIdx.y * CG;
    for (int i = threadIdx.x; i < 32*9*CG; i += blockDim.x) {
        int co = i % CG; int r = i / CG;       // r = ci*9 + tap
        int ci = r / 9, tap = r % 9;
        sw[i] = w[((size_t)(co0+co)*48 + 16 + ci)*9 + tap];
    }
    for (int i = threadIdx.x; i < CG; i += blockDim.x) sb[i] = bias[co0 + i];
    __syncthreads();

    int idx = blockIdx.x*blockDim.x + threadIdx.x;
    if (idx >= NB*64*32) return;
    int xb = (idx & 31) * PX;
    int oy = (idx >> 5) & 63;
    int n  = idx >> 11;

    int vy = (oy == 0) ? 0 : ((oy == 63) ? 2 : 1);
    u64 acc[PX][NP];
    #pragma unroll
    for (int p = 0; p < PX; p++) {
        int ox = xb + p;
        int vx = (ox == 0) ? 0 : ((ox == 63) ? 2 : 1);
        const float* cp = &contrib[((size_t)n*9 + vy*3 + vx)*64 + co0];
        #pragma unroll
        for (int j = 0; j < NP; j++)
            acc[p][j] = pack2(sb[2*j] + cp[2*j], sb[2*j+1] + cp[2*j+1]);
    }

    const float* dsp = ds + (size_t)n*32*4096;
    const int ix0 = xb - 1;
    #pragma unroll 1
    for (int ci = 0; ci < 32; ci++) {
        #pragma unroll
        for (int ky = 0; ky < 3; ky++) {
            int iy = oy - 1 + ky;
            if (iy < 0 || iy >= 64) continue;
            const float* row = dsp + (size_t)ci*4096 + iy*64;
            u64 v2[IW];
            #pragma unroll
            for (int j = 0; j < IW; j++) {
                int ix = ix0 + j;
                v2[j] = bcast2((ix >= 0 && ix < 64) ? __ldg(row + ix) : 0.f);
            }
            #pragma unroll
            for (int kx = 0; kx < 3; kx++) {
                const float* wp = &sw[((ci*3+ky)*3+kx)*CG];
                #pragma unroll
                for (int j = 0; j < NP; j += 2) {
                    ulonglong2 wq = *reinterpret_cast<const ulonglong2*>(wp + 2*j);
                    #pragma unroll
                    for (int p = 0; p < PX; p++) {
                        fma2(acc[p][j],   v2[p+kx], wq.x);
                        fma2(acc[p][j+1], v2[p+kx], wq.y);
                    }
                }
            }
        }
    }
    float* op = out + ((size_t)n*64 + co0)*4096 + oy*64 + xb;
    #pragma unroll
    for (int j = 0; j < NP; j++)
        #pragma unroll
        for (int p = 0; p < PX; p++) {
            float2 a = unpack2(acc[p][j]);
            op[(size_t)(2*j)  *4096 + p] = a.x;
            op[(size_t)(2*j+1)*4096 + p] = a.y;
        }
}

// ---------------- BatchNorm: deterministic 2-stage stats (float4) ----------
template<int C, int HW>
__global__ void bn_part_k(const float* __restrict__ x, float* __restrict__ part)
{
    int c = blockIdx.x;
    float s = 0.f, s2 = 0.f;
    constexpr int HW4 = HW/4;
    const int per = NB*HW4;
    for (int i = blockIdx.y*blockDim.x + threadIdx.x; i < per; i += gridDim.y*blockDim.x) {
        int n = i / HW4; int j = i - n*HW4;
        float4 v = *reinterpret_cast<const float4*>(&x[((size_t)n*C + c)*HW + j*4]);
        s  += (v.x + v.y) + (v.z + v.w);
        s2 += (v.x*v.x + v.y*v.y) + (v.z*v.z + v.w*v.w);
    }
    __shared__ float rs[256], rs2[256];
    rs[threadIdx.x] = s; rs2[threadIdx.x] = s2;
    __syncthreads();
    for (int o = blockDim.x/2; o > 0; o >>= 1) {
        if (threadIdx.x < o) {
            rs[threadIdx.x]  += rs[threadIdx.x + o];
            rs2[threadIdx.x] += rs2[threadIdx.x + o];
        }
        __syncthreads();
    }
    if (threadIdx.x == 0) {
        part[c*32 + blockIdx.y]        = rs[0];
        part[C*32 + c*32 + blockIdx.y] = rs2[0];
    }
}

template<int C, int HW>
__global__ void bn_fin_k(const float* __restrict__ part, const float* __restrict__ g,
                         const float* __restrict__ be, float* __restrict__ scale,
                         float* __restrict__ shift)
{
    int c = threadIdx.x;
    if (c >= C) return;
    float s = 0.f, s2 = 0.f;
    for (int b = 0; b < 32; b++) { s += part[c*32 + b]; s2 += part[C*32 + c*32 + b]; }
    const float cnt = (float)NB * (float)HW;
    float mu  = s / cnt;
    float var = s2 / cnt - mu*mu;
    float sc  = g[c] * rsqrtf(var + 1e-5f);
    scale[c] = sc;
    shift[c] = be[c] - mu*sc;
}

// ---------------- bn2 apply + pointwise(ds) + pwblur residual (in place) ---
__global__ __launch_bounds__(128) void bn2pw_k(
    float* __restrict__ r2, const float* __restrict__ pwblur,
    const float* __restrict__ ds, const float* __restrict__ pw,
    const float* __restrict__ pb, const float* __restrict__ scale,
    const float* __restrict__ shift)
{
    __shared__ float sw[32*20];   // transposed [ci][co], ds channels only
    __shared__ float sb[20], ssc[20], ssh[20];
    for (int i = threadIdx.x; i < 32*20; i += blockDim.x) {
        int co = i % 20, ci = i / 20;
        sw[i] = pw[co*48 + 16 + ci];
    }
    if (threadIdx.x < 20) {
        sb[threadIdx.x]  = pb[threadIdx.x];
        ssc[threadIdx.x] = scale[threadIdx.x];
        ssh[threadIdx.x] = shift[threadIdx.x];
    }
    __syncthreads();

    int idx = blockIdx.x*blockDim.x + threadIdx.x;
    if (idx >= NB*4096) return;
    int p = idx & 4095; int n = idx >> 12;

    u64 acc[10];
    const float* pbl = &pwblur[n*20];
    #pragma unroll
    for (int j = 0; j < 10; j++)
        acc[j] = pack2(sb[2*j] + pbl[2*j], sb[2*j+1] + pbl[2*j+1]);

    const float* dsp = ds + (size_t)n*32*4096 + p;
    #pragma unroll 1
    for (int ci = 0; ci < 32; ci++) {
        u64 v = bcast2(__ldg(&dsp[(size_t)ci*4096]));
        const float* wp = &sw[ci*20];
        #pragma unroll
        for (int j = 0; j < 10; j += 2) {
            ulonglong2 wq = *reinterpret_cast<const ulonglong2*>(wp + 2*j);
            fma2(acc[j],   v, wq.x);
            fma2(acc[j+1], v, wq.y);
        }
    }
    float* rp = r2 + (size_t)n*20*4096 + p;
    #pragma unroll
    for (int j = 0; j < 10; j++) {
        float2 a = unpack2(acc[j]);
        int c = 2*j;
        rp[(size_t)c    *4096] = fmaf(rp[(size_t)c    *4096], ssc[c],   ssh[c])   + a.x;
        rp[(size_t)(c+1)*4096] = fmaf(rp[(size_t)(c+1)*4096], ssc[c+1], ssh[c+1]) + a.y;
    }
}

// ---------------- final: u2 1x1 (30->16) + relu + pixel_shuffle(4) + sigmoid
__global__ __launch_bounds__(128) void final_k(
    const float* __restrict__ u1, const float* __restrict__ w,
    const float* __restrict__ b, float* __restrict__ out)
{
    __shared__ float sw[30*16];   // transposed [ci][co]
    __shared__ float sb[16];
    for (int i = threadIdx.x; i < 30*16; i += blockDim.x) {
        int co = i % 16, ci = i / 16;
        sw[i] = w[co*30 + ci];
    }
    if (threadIdx.x < 16) sb[threadIdx.x] = b[threadIdx.x];
    __syncthreads();

    int idx = blockIdx.x*blockDim.x + threadIdx.x;
    if (idx >= NB*4096) return;
    int wq = idx & 63; int h = (idx >> 6) & 63; int n = idx >> 12;

    u64 acc[8];
    #pragma unroll
    for (int j = 0; j < 8; j++) acc[j] = pack2(sb[2*j], sb[2*j+1]);

    const float* up = u1 + (size_t)n*30*4096 + h*64 + wq;
    #pragma unroll 1
    for (int ci = 0; ci < 30; ci++) {
        u64 v = bcast2(__ldg(&up[(size_t)ci*4096]));
        const float* wp = &sw[ci*16];
        #pragma unroll
        for (int j = 0; j < 8; j += 2) {
            ulonglong2 wqv = *reinterpret_cast<const ulonglong2*>(wp + 2*j);
            fma2(acc[j],   v, wqv.x);
            fma2(acc[j+1], v, wqv.y);
        }
    }
    float* op = out + (size_t)n*65536;
    #pragma unroll
    for (int j = 0; j < 8; j++) {
        float2 a = unpack2(acc[j]);
        #pragma unroll
        for (int h2 = 0; h2 < 2; h2++) {
            int c = 2*j + h2;
            float v = fmaxf(h2 ? a.y : a.x, 0.f);
            v = 1.f / (1.f + expf(-v));
            op[(h*4 + (c >> 2))*256 + wq*4 + (c & 3)] = v;
        }
    }
}

// ---------------------------------------------------------------------------
extern "C" void kernel_launch(void* const* d_in, const int* in_sizes, int n_in,
                              void* d_out, int out_size)
{
    const float* x1  = (const float*)d_in[0];
    const float* c1w = (const float*)d_in[1];  const float* c1b = (const float*)d_in[2];
    const float* c2w = (const float*)d_in[3];  const float* c2b = (const float*)d_in[4];
    const float* c3w = (const float*)d_in[5];  const float* c3b = (const float*)d_in[6];
    const float* c4w = (const float*)d_in[7];  const float* c4b = (const float*)d_in[8];
    const float* c5w = (const float*)d_in[9];  const float* c5b = (const float*)d_in[10];
    const float* c6w = (const float*)d_in[11]; const float* c6b = (const float*)d_in[12];
    const float* c7w = (const float*)d_in[13]; const float* c7b = (const float*)d_in[14];
    const float* r1w = (const float*)d_in[15]; const float* r1b = (const float*)d_in[16];
    const float* g1  = (const float*)d_in[17]; const float* be1 = (const float*)d_in[18];
    const float* r2w = (const float*)d_in[19]; const float* r2b = (const float*)d_in[20];
    const float* g2  = (const float*)d_in[21]; const float* be2 = (const float*)d_in[22];
    const float* pw  = (const float*)d_in[23]; const float* pb  = (const float*)d_in[24];
    const float* u1w = (const float*)d_in[25]; const float* u1b = (const float*)d_in[26];
    const float* u2w = (const float*)d_in[27]; const float* u2b = (const float*)d_in[28];

    float *t1,*ds,*t3,*t4,*t5,*t6,*blur,*r1,*r2,*u1,*part,*scale,*shift,*contrib,*pwblur;
    cudaGetSymbolAddress((void**)&t1,     g_t1);
    cudaGetSymbolAddress((void**)&ds,     g_ds);
    cudaGetSymbolAddress((void**)&t3,     g_t3);
    cudaGetSymbolAddress((void**)&t4,     g_t4);
    cudaGetSymbolAddress((void**)&t5,     g_t5);
    cudaGetSymbolAddress((void**)&t6,     g_t6);
    cudaGetSymbolAddress((void**)&blur,   g_blur);
    cudaGetSymbolAddress((void**)&r1,     g_r1);
    cudaGetSymbolAddress((void**)&r2,     g_r2);
    cudaGetSymbolAddress((void**)&u1,     g_u1);
    cudaGetSymbolAddress((void**)&part,   g_part);
    cudaGetSymbolAddress((void**)&scale,  g_scale);
    cudaGetSymbolAddress((void**)&shift,  g_shift);
    cudaGetSymbolAddress((void**)&contrib,g_contrib);
    cudaGetSymbolAddress((void**)&pwblur, g_pwblur);

    auto smemL = [](int cin, int coutp, int k) { return (size_t)(cin*k*k*coutp + coutp)*4; };
    auto smemP = [](int cin, int cgp, int k, bool bnin) {
        return (size_t)(cin*k*k*cgp + cgp + (bnin ? 2*cin : 0))*4;
    };

    cudaFuncSetAttribute((const void*)conv_k<20,30,5,2,2,16,16,true>,
                         cudaFuncAttributeMaxDynamicSharedMemorySize, (int)smemL(20,32,5));

    // ---------------- encoder ----------------
    convp_k<1,8,8,4,3,2,1,256,256,true,false>
        <<<(NB*128*32+127)/128,128, smemP(1,8,3,false)>>>(x1, c1w, c1b, nullptr, nullptr, t1);
    convp_k<8,32,32,2,5,2,2,128,128,true,false>
        <<<(NB*64*32+127)/128,128, smemP(8,32,5,false)>>>(t1, c2w, c2b, nullptr, nullptr, ds);
    conv_k<32,4,3,2,1, 64, 64,false><<<(NB*32*32+127)/128,128, smemL(32,4,3)>>> (ds, c3w, c3b, t3);
    conv_k<4,20,3,2,1, 32, 32,true><<<(NB*16*16+127)/128,128, smemL(4,20,3)>>>  (t3, c4w, c4b, t4);
    conv_k<20,30,5,2,2,16, 16,true><<<(NB*8*8  +127)/128,128, smemL(20,32,5)>>> (t4, c5w, c5b, t5);
    conv_k<30, 8,3,2,1,  8,  8,true><<<(NB*4*4 +127)/128,128, smemL(30,8,3)>>>  (t5, c6w, c6b, t6);
    conv7_k<<<(NB*16+127)/128,128>>>(t6, c7w, c7b, blur);

    // blur contributions (r1 border combos + pointwise)
    blurpre_k<<<NB,64>>>(blur, r1w, pw, contrib, pwblur);

    // ---------------- residual block with training-mode BN ----------------
    {
        dim3 g((NB*64*32+127)/128, 2);
        conv_r1p_k<<<g,128, (32*9*32 + 32)*4>>>(ds, r1w, r1b, contrib, r1);
    }
    { dim3 g(64,32); bn_part_k<64,4096><<<g,256>>>(r1, part); }
    bn_fin_k<64,4096><<<1,64>>>(part, g1, be1, scale, shift);

    // r2 with fused bn1-apply + relu on input
    convp_k<64,20,20,2,3,1,1,64,64,false,true>
        <<<(NB*64*32+127)/128,128, smemP(64,20,3,true)>>>(r1, r2w, r2b, scale, shift, r2);
    { dim3 g(20,32); bn_part_k<20,4096><<<g,256>>>(r2, part); }
    bn_fin_k<20,4096><<<1,32>>>(part, g2, be2, scale, shift);
    bn2pw_k<<<(NB*4096+127)/128,128>>>(r2, pwblur, ds, pw, pb, scale, shift);

    // ---------------- upsample head ----------------
    convp_k<20,30,30,2,3,1,1,64,64,true,false>
        <<<(NB*64*32+127)/128,128, smemP(20,32,3,false)>>>(r2, u1w, u1b, nullptr, nullptr, u1);
    final_k<<<(NB*4096+127)/128,128>>>(u1, u2w, u2b, (float*)d_out);
}

// round 6
// speedup vs baseline: 2.4211x; 1.2721x over previous
#include <cuda_runtime.h>
#include <cuda_bf16.h>
#include <math.h>

#define NB 128

// ---------------- scratch (device globals; no allocation allowed) ----------
__device__ float g_t1[(size_t)NB*8*128*128];
__device__ float g_ds[(size_t)NB*32*64*64];
__device__ float g_t3[(size_t)NB*4*32*32];
__device__ float g_t4[(size_t)NB*20*16*16];
__device__ float g_t5[(size_t)NB*30*8*8];
__device__ float g_t6[(size_t)NB*8*4*4];
__device__ float g_blur[NB*16];
__device__ float g_r1[(size_t)NB*64*64*64];
__device__ float g_r2[(size_t)NB*20*64*64];
__device__ float g_u1[(size_t)NB*30*64*64];
__device__ float g_part[2*64*32];
__device__ float g_scale[64];
__device__ float g_shift[64];
__device__ float g_contrib[NB*9*64];   // blur-part of r1 per (n, border-combo, co)
__device__ float g_pwblur[NB*20];      // blur-part of pointwise conv per (n, co)

// ---------------- packed f32x2 helpers (kept for small fused kernels) ------
typedef unsigned long long u64;
static __device__ __forceinline__ u64 pack2(float x, float y) {
    u64 r; asm("mov.b64 %0, {%1, %2};" : "=l"(r) : "f"(x), "f"(y)); return r;
}
static __device__ __forceinline__ u64 bcast2(float x) { return pack2(x, x); }
static __device__ __forceinline__ void fma2(u64& d, u64 a, u64 b) {
    asm("fma.rn.f32x2 %0, %1, %2, %0;" : "+l"(d) : "l"(a), "l"(b));
}
static __device__ __forceinline__ float2 unpack2(u64 v) {
    float2 r; asm("mov.b64 {%0, %1}, %2;" : "=f"(r.x), "=f"(r.y) : "l"(v)); return r;
}

static __device__ __forceinline__ unsigned to_tf32(float v) {
    unsigned u; asm("cvt.rna.tf32.f32 %0, %1;" : "=r"(u) : "f"(v)); return u;
}

// =====================================================================
// Tensor-core 3x3 s1 p1 conv on 64x64 images (implicit GEMM, tf32 mma).
// Block: one image n, 4 output rows (M=256 px), 512 threads = 16 warps,
// each warp one m16 tile x all COUT n-tiles. K = CIN*9, CINC-chunked.
// Weights staged [co][k] with k-stride KS ≡ 4 (mod 32) -> conflict-free
// B-fragment LDS. Input halo tile (CINC x 6 x 68) staged as tf32.
// =====================================================================
__host__ __device__ constexpr int ceil8i(int x) { return (x + 7) & ~7; }
__host__ __device__ constexpr int padKS(int kp) { return kp + ((4 - (kp & 31)) + 32) % 32; }

template<int CIN,int CINC,int WCIN,int CIOFF,int COUT,int COUTP,bool RELU,bool BNIN,bool CONTRIB>
__global__ __launch_bounds__(512) void tc_conv3_k(
    const float* __restrict__ in, const float* __restrict__ w,
    const float* __restrict__ bias, const float* __restrict__ bnsc,
    const float* __restrict__ bnsh, const float* __restrict__ contrib,
    float* __restrict__ out)
{
    constexpr int CHUNKS = CIN / CINC;
    static_assert(CIN % CINC == 0 && COUTP % 8 == 0, "");
    constexpr int KC  = CINC*9;
    constexpr int KCP = ceil8i(KC);
    constexpr int KP  = CHUNKS*KCP;
    constexpr int KS  = padKS(KP);
    constexpr int IN_S = CINC*6*68;
    constexpr int NT = COUTP/8;
    extern __shared__ unsigned sm[];
    unsigned* in_s = sm;
    unsigned* w_s  = sm + IN_S;

    const int n   = blockIdx.y;
    const int oy0 = blockIdx.x * 4;
    const int tid = threadIdx.x;
    const int lane = tid & 31;
    const int mt  = tid >> 5;          // warp id = m-tile (0..15)
    const int tg  = lane & 3;          // threadID_in_group
    const int gid = lane >> 2;         // groupID

    // ---- stage weights once: w_s[co][kg], tf32, zero-padded ----
    for (int idx = tid; idx < COUTP*KS; idx += 512) {
        int nn = idx / KS; int kg = idx - nn*KS;
        int chunk = kg / KCP; int kin = kg - chunk*KCP;
        float val = 0.f;
        if (nn < COUT && chunk < CHUNKS && kin < KC) {
            int ci = chunk*CINC + kin/9;
            int tap = kin % 9;
            val = w[((size_t)nn*WCIN + CIOFF + ci)*9 + tap];
        }
        w_s[idx] = to_tf32(val);
    }

    float acc[NT][4];
    #pragma unroll
    for (int nt = 0; nt < NT; nt++)
        #pragma unroll
        for (int e = 0; e < 4; e++) acc[nt][e] = 0.f;

    const int base = (mt >> 2)*68 + (mt & 3)*16 + gid;

    for (int chunk = 0; chunk < CHUNKS; chunk++) {
        __syncthreads();
        const int ci0 = chunk*CINC;
        for (int idx = tid; idx < CINC*6*66; idx += 512) {
            int ci = idx / (6*66); int rem = idx - ci*(6*66);
            int ry = rem / 66; int cx = rem - ry*66;
            int iy = oy0 - 1 + ry; int ix = cx - 1;
            float val = 0.f;
            if ((unsigned)iy < 64u && (unsigned)ix < 64u) {
                val = in[((size_t)n*CIN + ci0 + ci)*4096 + iy*64 + ix];
                if (BNIN) val = fmaxf(fmaf(val, bnsc[ci0+ci], bnsh[ci0+ci]), 0.f);
            }
            in_s[(ci*6 + ry)*68 + cx] = to_tf32(val);
        }
        __syncthreads();

        #pragma unroll 1
        for (int ks = 0; ks < KCP/8; ks++) {
            int k0 = ks*8 + tg, k1 = k0 + 4;
            int cia = k0/9, tap0 = k0 - cia*9;
            int cib = k1/9, tap1 = k1 - cib*9;
            int t0 = (cia*6 + tap0/3)*68 + tap0 - (tap0/3)*3;
            int t1 = (cib*6 + tap1/3)*68 + tap1 - (tap1/3)*3;
            unsigned a0 = in_s[t0 + base];
            unsigned a1 = in_s[t0 + base + 8];
            unsigned a2 = in_s[t1 + base];
            unsigned a3 = in_s[t1 + base + 8];
            const unsigned* wb = w_s + chunk*KCP + ks*8 + tg + (size_t)gid*KS;
            #pragma unroll
            for (int nt = 0; nt < NT; nt++) {
                unsigned b0 = wb[(size_t)(nt*8)*KS];
                unsigned b1 = wb[(size_t)(nt*8)*KS + 4];
                asm volatile(
                  "mma.sync.aligned.m16n8k8.row.col.f32.tf32.tf32.f32 "
                  "{%0,%1,%2,%3}, {%4,%5,%6,%7}, {%8,%9}, {%0,%1,%2,%3};"
                  : "+f"(acc[nt][0]), "+f"(acc[nt][1]),
                    "+f"(acc[nt][2]), "+f"(acc[nt][3])
                  : "r"(a0), "r"(a1), "r"(a2), "r"(a3), "r"(b0), "r"(b1));
            }
        }
    }

    // ---- epilogue ----
    const int oy = oy0 + (mt >> 2);
    const int x0 = (mt & 3)*16;
    const int vy = (oy == 0) ? 0 : ((oy == 63) ? 2 : 1);
    #pragma unroll
    for (int half = 0; half < 2; half++) {
        int m = gid + half*8;
        int x = x0 + m;
        int vx = (x == 0) ? 0 : ((x == 63) ? 2 : 1);
        const float* cp = CONTRIB ? &contrib[((size_t)n*9 + vy*3 + vx)*64] : nullptr;
        float* op = out + (size_t)n*COUT*4096 + (size_t)oy*64 + x;
        #pragma unroll
        for (int nt = 0; nt < NT; nt++) {
            #pragma unroll
            for (int e = 0; e < 2; e++) {
                int co = nt*8 + 2*tg + e;
                if (co < COUT) {
                    float v = acc[nt][half*2 + e] + bias[co];
                    if (CONTRIB) v += cp[co];
                    if (RELU) v = fmaxf(v, 0.f);
                    op[(size_t)co*4096] = v;
                }
            }
        }
    }
}

// =====================================================================
// Packed direct conv (fp32) for conv1/conv2 (strided, fp32-exact path).
// =====================================================================
template<int CIN,int COUT,int CG,int PX,int K,int S,int P,int HIN,int WIN,bool RELU>
__global__ __launch_bounds__(128) void convp_k(
    const float* __restrict__ in, const float* __restrict__ w,
    const float* __restrict__ bias, float* __restrict__ out)
{
    constexpr int HOUT = (HIN + 2*P - K)/S + 1;
    constexpr int WOUT = (WIN + 2*P - K)/S + 1;
    constexpr int CGP  = (CG + 3) & ~3;
    constexpr int NP   = CGP/2;
    constexpr int IW   = (PX-1)*S + K;
    static_assert(WOUT % PX == 0 && CG % 2 == 0, "");
    extern __shared__ float sw[];
    float* sb  = sw + CIN*K*K*CGP;
    const int co0 = blockIdx.y * CG;
    for (int i = threadIdx.x; i < CIN*K*K*CGP; i += blockDim.x) {
        int co = i % CGP; int r = i / CGP;
        sw[i] = (co < CG) ? w[(size_t)(co0+co)*CIN*K*K + r] : 0.f;
    }
    for (int i = threadIdx.x; i < CGP; i += blockDim.x)
        sb[i] = (i < CG) ? bias[co0 + i] : 0.f;
    __syncthreads();

    constexpr int XB = WOUT / PX;
    int idx = blockIdx.x*blockDim.x + threadIdx.x;
    if (idx >= NB*HOUT*XB) return;
    int xb = (idx % XB) * PX;
    int oy = (idx / XB) % HOUT;
    int n  = idx / (XB*HOUT);

    u64 acc[PX][NP];
    #pragma unroll
    for (int p = 0; p < PX; p++)
        #pragma unroll
        for (int j = 0; j < NP; j++) acc[p][j] = pack2(sb[2*j], sb[2*j+1]);

    const float* inp = in + (size_t)n*CIN*HIN*WIN;
    const int ix0 = xb*S - P;
    #pragma unroll 1
    for (int ci = 0; ci < CIN; ci++) {
        #pragma unroll
        for (int ky = 0; ky < K; ky++) {
            int iy = oy*S - P + ky;
            if (iy < 0 || iy >= HIN) continue;
            const float* row = inp + (size_t)ci*HIN*WIN + (size_t)iy*WIN;
            u64 v2[IW];
            #pragma unroll
            for (int j = 0; j < IW; j++) {
                int ix = ix0 + j;
                v2[j] = bcast2((ix >= 0 && ix < WIN) ? __ldg(row + ix) : 0.f);
            }
            #pragma unroll
            for (int kx = 0; kx < K; kx++) {
                const float* wp = &sw[((ci*K+ky)*K+kx)*CGP];
                #pragma unroll
                for (int j = 0; j < NP; j += 2) {
                    ulonglong2 wq = *reinterpret_cast<const ulonglong2*>(wp + 2*j);
                    #pragma unroll
                    for (int p = 0; p < PX; p++) {
                        fma2(acc[p][j],   v2[p*S+kx], wq.x);
                        fma2(acc[p][j+1], v2[p*S+kx], wq.y);
                    }
                }
            }
        }
    }
    float* op = out + ((size_t)n*COUT + co0)*HOUT*WOUT + (size_t)oy*WOUT + xb;
    #pragma unroll
    for (int j = 0; j < CG/2; j++)
        #pragma unroll
        for (int p = 0; p < PX; p++) {
            float2 a = unpack2(acc[p][j]);
            if (RELU) { a.x = fmaxf(a.x, 0.f); a.y = fmaxf(a.y, 0.f); }
            op[(size_t)(2*j)  *HOUT*WOUT + p] = a.x;
            op[(size_t)(2*j+1)*HOUT*WOUT + p] = a.y;
        }
}

// ---------------- legacy per-pixel conv (tiny tail kernels) ----------------
template<int CIN,int COUT,int K,int S,int P,int HIN,int WIN,bool RELU>
__global__ __launch_bounds__(128) void conv_k(
    const float* __restrict__ in, const float* __restrict__ w,
    const float* __restrict__ bias, float* __restrict__ out)
{
    constexpr int HOUT = (HIN + 2*P - K)/S + 1;
    constexpr int WOUT = (WIN + 2*P - K)/S + 1;
    constexpr int COUTP = (COUT + 3) & ~3;
    extern __shared__ float sw[];
    float* sb = sw + CIN*K*K*COUTP;
    for (int i = threadIdx.x; i < CIN*K*K*COUTP; i += blockDim.x) {
        int co = i % COUTP; int r = i / COUTP;
        sw[i] = (co < COUT) ? w[co*CIN*K*K + r] : 0.f;
    }
    for (int i = threadIdx.x; i < COUTP; i += blockDim.x)
        sb[i] = (i < COUT) ? bias[i] : 0.f;
    __syncthreads();

    int idx = blockIdx.x*blockDim.x + threadIdx.x;
    if (idx >= NB*HOUT*WOUT) return;
    int ox = idx % WOUT; int oy = (idx/WOUT) % HOUT; int n = idx/(WOUT*HOUT);

    float acc[COUTP];
    #pragma unroll
    for (int c = 0; c < COUTP; c++) acc[c] = sb[c];

    const float* inp = in + (size_t)n*CIN*HIN*WIN;
    #pragma unroll 1
    for (int ci = 0; ci < CIN; ci++) {
        #pragma unroll
        for (int ky = 0; ky < K; ky++) {
            int iy = oy*S - P + ky;
            if (iy < 0 || iy >= HIN) continue;
            #pragma unroll
            for (int kx = 0; kx < K; kx++) {
                int ix = ox*S - P + kx;
                if (ix < 0 || ix >= WIN) continue;
                float v = __ldg(&inp[(size_t)ci*HIN*WIN + (size_t)iy*WIN + ix]);
                const float* wp = &sw[((ci*K+ky)*K+kx)*COUTP];
                #pragma unroll
                for (int co = 0; co < COUTP; co += 4) {
                    float4 w4 = *reinterpret_cast<const float4*>(wp + co);
                    acc[co+0] = fmaf(v, w4.x, acc[co+0]);
                    acc[co+1] = fmaf(v, w4.y, acc[co+1]);
                    acc[co+2] = fmaf(v, w4.z, acc[co+2]);
                    acc[co+3] = fmaf(v, w4.w, acc[co+3]);
                }
            }
        }
    }
    float* op = out + ((size_t)n*COUT*HOUT + (size_t)oy)*WOUT + ox;
    #pragma unroll
    for (int co = 0; co < COUT; co++) {
        float v = acc[co];
        if (RELU) v = fmaxf(v, 0.f);
        op[(size_t)co*HOUT*WOUT] = v;
    }
}

// ---------------- conv7: 1x1, 8->1 over 4x4 -> blur[n][16] -----------------
__global__ void conv7_k(const float* __restrict__ t6, const float* __restrict__ w,
                        const float* __restrict__ b, float* __restrict__ blur)
{
    int i = blockIdx.x*blockDim.x + threadIdx.x;
    if (i >= NB*16) return;
    int n = i >> 4, p = i & 15;
    float acc = b[0];
    #pragma unroll
    for (int ci = 0; ci < 8; ci++)
        acc = fmaf(t6[(n*8 + ci)*16 + p], w[ci], acc);
    blur[i] = fmaxf(acc, 0.f);
}

// ---------------- blur precompute: r1 blur contribution per border combo ---
__global__ void blurpre_k(const float* __restrict__ blur, const float* __restrict__ r1w,
                          const float* __restrict__ pw, float* __restrict__ contrib,
                          float* __restrict__ pwblur)
{
    int n = blockIdx.x;
    int co = threadIdx.x;
    float s[9];
    #pragma unroll
    for (int q = 0; q < 9; q++) s[q] = 0.f;
    for (int ci = 0; ci < 16; ci++) {
        float bv = blur[n*16 + ci];
        const float* tw = r1w + ((size_t)co*48 + ci)*9;
        float t[9];
        #pragma unroll
        for (int q = 0; q < 9; q++) t[q] = tw[q];
        float cs[3][3];
        #pragma unroll
        for (int ky = 0; ky < 3; ky++) {
            cs[ky][0] = t[ky*3+1] + t[ky*3+2];
            cs[ky][1] = t[ky*3+0] + t[ky*3+1] + t[ky*3+2];
            cs[ky][2] = t[ky*3+0] + t[ky*3+1];
        }
        #pragma unroll
        for (int vx = 0; vx < 3; vx++) {
            float r0 = cs[1][vx] + cs[2][vx];
            float r1v = cs[0][vx] + cs[1][vx] + cs[2][vx];
            float r2 = cs[0][vx] + cs[1][vx];
            s[0*3+vx] = fmaf(bv, r0,  s[0*3+vx]);
            s[1*3+vx] = fmaf(bv, r1v, s[1*3+vx]);
            s[2*3+vx] = fmaf(bv, r2,  s[2*3+vx]);
        }
    }
    #pragma unroll
    for (int q = 0; q < 9; q++) contrib[((size_t)n*9 + q)*64 + co] = s[q];

    if (co < 20) {
        float q = 0.f;
        for (int ci = 0; ci < 16; ci++)
            q = fmaf(blur[n*16 + ci], pw[co*48 + ci], q);
        pwblur[n*20 + co] = q;
    }
}

// ---------------- BatchNorm: deterministic 2-stage stats (float4) ----------
template<int C, int HW>
__global__ void bn_part_k(const float* __restrict__ x, float* __restrict__ part)
{
    int c = blockIdx.x;
    float s = 0.f, s2 = 0.f;
    constexpr int HW4 = HW/4;
    const int per = NB*HW4;
    for (int i = blockIdx.y*blockDim.x + threadIdx.x; i < per; i += gridDim.y*blockDim.x) {
        int n = i / HW4; int j = i - n*HW4;
        float4 v = *reinterpret_cast<const float4*>(&x[((size_t)n*C + c)*HW + j*4]);
        s  += (v.x + v.y) + (v.z + v.w);
        s2 += (v.x*v.x + v.y*v.y) + (v.z*v.z + v.w*v.w);
    }
    __shared__ float rs[256], rs2[256];
    rs[threadIdx.x] = s; rs2[threadIdx.x] = s2;
    __syncthreads();
    for (int o = blockDim.x/2; o > 0; o >>= 1) {
        if (threadIdx.x < o) {
            rs[threadIdx.x]  += rs[threadIdx.x + o];
            rs2[threadIdx.x] += rs2[threadIdx.x + o];
        }
        __syncthreads();
    }
    if (threadIdx.x == 0) {
        part[c*32 + blockIdx.y]        = rs[0];
        part[C*32 + c*32 + blockIdx.y] = rs2[0];
    }
}

template<int C, int HW>
__global__ void bn_fin_k(const float* __restrict__ part, const float* __restrict__ g,
                         const float* __restrict__ be, float* __restrict__ scale,
                         float* __restrict__ shift)
{
    int c = threadIdx.x;
    if (c >= C) return;
    float s = 0.f, s2 = 0.f;
    for (int b = 0; b < 32; b++) { s += part[c*32 + b]; s2 += part[C*32 + c*32 + b]; }
    const float cnt = (float)NB * (float)HW;
    float mu  = s / cnt;
    float var = s2 / cnt - mu*mu;
    float sc  = g[c] * rsqrtf(var + 1e-5f);
    scale[c] = sc;
    shift[c] = be[c] - mu*sc;
}

// ---------------- bn2 apply + pointwise(ds) + pwblur residual (in place) ---
__global__ __launch_bounds__(128) void bn2pw_k(
    float* __restrict__ r2, const float* __restrict__ pwblur,
    const float* __restrict__ ds, const float* __restrict__ pw,
    const float* __restrict__ pb, const float* __restrict__ scale,
    const float* __restrict__ shift)
{
    __shared__ float sw[32*20];
    __shared__ float sb[20], ssc[20], ssh[20];
    for (int i = threadIdx.x; i < 32*20; i += blockDim.x) {
        int co = i % 20, ci = i / 20;
        sw[i] = pw[co*48 + 16 + ci];
    }
    if (threadIdx.x < 20) {
        sb[threadIdx.x]  = pb[threadIdx.x];
        ssc[threadIdx.x] = scale[threadIdx.x];
        ssh[threadIdx.x] = shift[threadIdx.x];
    }
    __syncthreads();

    int idx = blockIdx.x*blockDim.x + threadIdx.x;
    if (idx >= NB*4096) return;
    int p = idx & 4095; int n = idx >> 12;

    u64 acc[10];
    const float* pbl = &pwblur[n*20];
    #pragma unroll
    for (int j = 0; j < 10; j++)
        acc[j] = pack2(sb[2*j] + pbl[2*j], sb[2*j+1] + pbl[2*j+1]);

    const float* dsp = ds + (size_t)n*32*4096 + p;
    #pragma unroll 1
    for (int ci = 0; ci < 32; ci++) {
        u64 v = bcast2(__ldg(&dsp[(size_t)ci*4096]));
        const float* wp = &sw[ci*20];
        #pragma unroll
        for (int j = 0; j < 10; j += 2) {
            ulonglong2 wq = *reinterpret_cast<const ulonglong2*>(wp + 2*j);
            fma2(acc[j],   v, wq.x);
            fma2(acc[j+1], v, wq.y);
        }
    }
    float* rp = r2 + (size_t)n*20*4096 + p;
    #pragma unroll
    for (int j = 0; j < 10; j++) {
        float2 a = unpack2(acc[j]);
        int c = 2*j;
        rp[(size_t)c    *4096] = fmaf(rp[(size_t)c    *4096], ssc[c],   ssh[c])   + a.x;
        rp[(size_t)(c+1)*4096] = fmaf(rp[(size_t)(c+1)*4096], ssc[c+1], ssh[c+1]) + a.y;
    }
}

// ---------------- final: u2 1x1 (30->16) + relu + pixel_shuffle(4) + sigmoid
__global__ __launch_bounds__(128) void final_k(
    const float* __restrict__ u1, const float* __restrict__ w,
    const float* __restrict__ b, float* __restrict__ out)
{
    __shared__ float sw[30*16];
    __shared__ float sb[16];
    for (int i = threadIdx.x; i < 30*16; i += blockDim.x) {
        int co = i % 16, ci = i / 16;
        sw[i] = w[co*30 + ci];
    }
    if (threadIdx.x < 16) sb[threadIdx.x] = b[threadIdx.x];
    __syncthreads();

    int idx = blockIdx.x*blockDim.x + threadIdx.x;
    if (idx >= NB*4096) return;
    int wq = idx & 63; int h = (idx >> 6) & 63; int n = idx >> 12;

    u64 acc[8];
    #pragma unroll
    for (int j = 0; j < 8; j++) acc[j] = pack2(sb[2*j], sb[2*j+1]);

    const float* up = u1 + (size_t)n*30*4096 + h*64 + wq;
    #pragma unroll 1
    for (int ci = 0; ci < 30; ci++) {
        u64 v = bcast2(__ldg(&up[(size_t)ci*4096]));
        const float* wp = &sw[ci*16];
        #pragma unroll
        for (int j = 0; j < 8; j += 2) {
            ulonglong2 wqv = *reinterpret_cast<const ulonglong2*>(wp + 2*j);
            fma2(acc[j],   v, wqv.x);
            fma2(acc[j+1], v, wqv.y);
        }
    }
    float* op = out + (size_t)n*65536;
    #pragma unroll
    for (int j = 0; j < 8; j++) {
        float2 a = unpack2(acc[j]);
        #pragma unroll
        for (int h2 = 0; h2 < 2; h2++) {
            int c = 2*j + h2;
            float v = fmaxf(h2 ? a.y : a.x, 0.f);
            v = 1.f / (1.f + expf(-v));
            op[(h*4 + (c >> 2))*256 + wq*4 + (c & 3)] = v;
        }
    }
}

// ---------------------------------------------------------------------------
extern "C" void kernel_launch(void* const* d_in, const int* in_sizes, int n_in,
                              void* d_out, int out_size)
{
    const float* x1  = (const float*)d_in[0];
    const float* c1w = (const float*)d_in[1];  const float* c1b = (const float*)d_in[2];
    const float* c2w = (const float*)d_in[3];  const float* c2b = (const float*)d_in[4];
    const float* c3w = (const float*)d_in[5];  const float* c3b = (const float*)d_in[6];
    const float* c4w = (const float*)d_in[7];  const float* c4b = (const float*)d_in[8];
    const float* c5w = (const float*)d_in[9];  const float* c5b = (const float*)d_in[10];
    const float* c6w = (const float*)d_in[11]; const float* c6b = (const float*)d_in[12];
    const float* c7w = (const float*)d_in[13]; const float* c7b = (const float*)d_in[14];
    const float* r1w = (const float*)d_in[15]; const float* r1b = (const float*)d_in[16];
    const float* g1  = (const float*)d_in[17]; const float* be1 = (const float*)d_in[18];
    const float* r2w = (const float*)d_in[19]; const float* r2b = (const float*)d_in[20];
    const float* g2  = (const float*)d_in[21]; const float* be2 = (const float*)d_in[22];
    const float* pw  = (const float*)d_in[23]; const float* pb  = (const float*)d_in[24];
    const float* u1w = (const float*)d_in[25]; const float* u1b = (const float*)d_in[26];
    const float* u2w = (const float*)d_in[27]; const float* u2b = (const float*)d_in[28];

    float *t1,*ds,*t3,*t4,*t5,*t6,*blur,*r1,*r2,*u1,*part,*scale,*shift,*contrib,*pwblur;
    cudaGetSymbolAddress((void**)&t1,     g_t1);
    cudaGetSymbolAddress((void**)&ds,     g_ds);
    cudaGetSymbolAddress((void**)&t3,     g_t3);
    cudaGetSymbolAddress((void**)&t4,     g_t4);
    cudaGetSymbolAddress((void**)&t5,     g_t5);
    cudaGetSymbolAddress((void**)&t6,     g_t6);
    cudaGetSymbolAddress((void**)&blur,   g_blur);
    cudaGetSymbolAddress((void**)&r1,     g_r1);
    cudaGetSymbolAddress((void**)&r2,     g_r2);
    cudaGetSymbolAddress((void**)&u1,     g_u1);
    cudaGetSymbolAddress((void**)&part,   g_part);
    cudaGetSymbolAddress((void**)&scale,  g_scale);
    cudaGetSymbolAddress((void**)&shift,  g_shift);
    cudaGetSymbolAddress((void**)&contrib,g_contrib);
    cudaGetSymbolAddress((void**)&pwblur, g_pwblur);

    auto smemL = [](int cin, int coutp, int k) { return (size_t)(cin*k*k*coutp + coutp)*4; };
    auto smemP = [](int cin, int cgp, int k) { return (size_t)(cin*k*k*cgp + cgp)*4; };
    auto smemTC = [](int cinc, int coutp, int ks) { return (size_t)(cinc*6*68 + coutp*ks)*4; };

    // tc conv smem sizes
    const int KS_r1 = padKS(2*ceil8i(16*9));   // 292
    const int KS_r2 = padKS(4*ceil8i(16*9));   // 580
    const int KS_u1 = padKS(1*ceil8i(20*9));   // 196
    size_t sm_r1 = smemTC(16, 64, KS_r1);
    size_t sm_r2 = smemTC(16, 24, KS_r2);
    size_t sm_u1 = smemTC(20, 32, KS_u1);

    cudaFuncSetAttribute((const void*)conv_k<20,30,5,2,2,16,16,true>,
                         cudaFuncAttributeMaxDynamicSharedMemorySize, (int)smemL(20,32,5));
    cudaFuncSetAttribute((const void*)tc_conv3_k<32,16,48,16,64,64,false,false,true>,
                         cudaFuncAttributeMaxDynamicSharedMemorySize, (int)sm_r1);
    cudaFuncSetAttribute((const void*)tc_conv3_k<64,16,64,0,20,24,false,true,false>,
                         cudaFuncAttributeMaxDynamicSharedMemorySize, (int)sm_r2);
    cudaFuncSetAttribute((const void*)tc_conv3_k<20,20,20,0,30,32,true,false,false>,
                         cudaFuncAttributeMaxDynamicSharedMemorySize, (int)sm_u1);

    // ---------------- encoder ----------------
    convp_k<1,8,8,4,3,2,1,256,256,true>
        <<<(NB*128*32+127)/128,128, smemP(1,8,3)>>>(x1, c1w, c1b, t1);
    convp_k<8,32,32,2,5,2,2,128,128,true>
        <<<(NB*64*32+127)/128,128, smemP(8,32,5)>>>(t1, c2w, c2b, ds);
    conv_k<32,4,3,2,1, 64, 64,false><<<(NB*32*32+127)/128,128, smemL(32,4,3)>>> (ds, c3w, c3b, t3);
    conv_k<4,20,3,2,1, 32, 32,true><<<(NB*16*16+127)/128,128, smemL(4,20,3)>>>  (t3, c4w, c4b, t4);
    conv_k<20,30,5,2,2,16, 16,true><<<(NB*8*8  +127)/128,128, smemL(20,32,5)>>> (t4, c5w, c5b, t5);
    conv_k<30, 8,3,2,1,  8,  8,true><<<(NB*4*4 +127)/128,128, smemL(30,8,3)>>>  (t5, c6w, c6b, t6);
    conv7_k<<<(NB*16+127)/128,128>>>(t6, c7w, c7b, blur);

    blurpre_k<<<NB,64>>>(blur, r1w, pw, contrib, pwblur);

    // ---------------- residual block with training-mode BN ----------------
    // r1: ds-part via tensor cores, blur-part via precomputed contrib
    tc_conv3_k<32,16,48,16,64,64,false,false,true>
        <<<dim3(16,NB),512, sm_r1>>>(ds, r1w, r1b, nullptr, nullptr, contrib, r1);
    { dim3 g(64,32); bn_part_k<64,4096><<<g,256>>>(r1, part); }
    bn_fin_k<64,4096><<<1,64>>>(part, g1, be1, scale, shift);

    // r2 with fused bn1-apply + relu on input (tensor cores)
    tc_conv3_k<64,16,64,0,20,24,false,true,false>
        <<<dim3(16,NB),512, sm_r2>>>(r1, r2w, r2b, scale, shift, nullptr, r2);
    { dim3 g(20,32); bn_part_k<20,4096><<<g,256>>>(r2, part); }
    bn_fin_k<20,4096><<<1,32>>>(part, g2, be2, scale, shift);
    bn2pw_k<<<(NB*4096+127)/128,128>>>(r2, pwblur, ds, pw, pb, scale, shift);

    // ---------------- upsample head ----------------
    tc_conv3_k<20,20,20,0,30,32,true,false,false>
        <<<dim3(16,NB),512, sm_u1>>>(r2, u1w, u1b, nullptr, nullptr, nullptr, u1);
    final_k<<<(NB*4096+127)/128,128>>>(u1, u2w, u2b, (float*)d_out);
}

// round 7
// speedup vs baseline: 2.7696x; 1.1440x over previous
#include <cuda_runtime.h>
#include <cuda_bf16.h>
#include <math.h>

#define NB 128

// ---------------- scratch (device globals; no allocation allowed) ----------
__device__ float g_t1[(size_t)NB*8*128*128];
__device__ float g_ds[(size_t)NB*32*64*64];
__device__ float g_t3[(size_t)NB*4*32*32];
__device__ float g_t4[(size_t)NB*20*16*16];
__device__ float g_t5[(size_t)NB*30*8*8];
__device__ float g_t6[(size_t)NB*8*4*4];
__device__ float g_blur[NB*16];
__device__ float g_r1[(size_t)NB*64*64*64];
__device__ float g_r2[(size_t)NB*20*64*64];
__device__ float g_u1[(size_t)NB*30*64*64];
__device__ float g_part[2*64*32];
__device__ float g_scale[64];
__device__ float g_shift[64];
__device__ float g_contrib[NB*9*64];
__device__ float g_pwblur[NB*20];

// ---------------- helpers ----------------
typedef unsigned long long u64;
static __device__ __forceinline__ u64 pack2(float x, float y) {
    u64 r; asm("mov.b64 %0, {%1, %2};" : "=l"(r) : "f"(x), "f"(y)); return r;
}
static __device__ __forceinline__ u64 bcast2(float x) { return pack2(x, x); }
static __device__ __forceinline__ void fma2(u64& d, u64 a, u64 b) {
    asm("fma.rn.f32x2 %0, %1, %2, %0;" : "+l"(d) : "l"(a), "l"(b));
}
static __device__ __forceinline__ float2 unpack2(u64 v) {
    float2 r; asm("mov.b64 {%0, %1}, %2;" : "=f"(r.x), "=f"(r.y) : "l"(v)); return r;
}
static __device__ __forceinline__ unsigned to_tf32(float v) {
    unsigned u; asm("cvt.rna.tf32.f32 %0, %1;" : "=r"(u) : "f"(v)); return u;
}
static __device__ __forceinline__ u64 packtf2(float x, float y) {
    return (u64)to_tf32(x) | ((u64)to_tf32(y) << 32);
}
static __device__ __forceinline__ void mma_tf32(
    float* acc, unsigned a0, unsigned a1, unsigned a2, unsigned a3,
    unsigned b0, unsigned b1)
{
    asm volatile(
      "mma.sync.aligned.m16n8k8.row.col.f32.tf32.tf32.f32 "
      "{%0,%1,%2,%3}, {%4,%5,%6,%7}, {%8,%9}, {%0,%1,%2,%3};"
      : "+f"(acc[0]), "+f"(acc[1]), "+f"(acc[2]), "+f"(acc[3])
      : "r"(a0), "r"(a1), "r"(a2), "r"(a3), "r"(b0), "r"(b1));
}

__host__ __device__ constexpr int ceil8i(int x) { return (x + 7) & ~7; }
// pad u64-per-co stride to ≡ 4 (mod 16) -> optimal 2-phase LDS.64 B loads
__host__ __device__ constexpr int pad64(int x) { return x + ((4 - (x & 15)) + 16) % 16; }

// =====================================================================
// Tensor-core 3x3 s1 p1 conv on 64x64 images (implicit GEMM, tf32 mma).
// Fully unrolled k loop; A offsets from shared int2 LUT; B weights as
// (k, k+4) u64 pairs with per-co stride P64 (≡4 mod 16).
// =====================================================================
template<int CIN,int CINC,int WCIN,int CIOFF,int COUT,int COUTP,bool RELU,bool BNIN,bool CONTRIB>
__global__ __launch_bounds__(512) void tc_conv3_k(
    const float* __restrict__ in, const float* __restrict__ w,
    const float* __restrict__ bias, const float* __restrict__ bnsc,
    const float* __restrict__ bnsh, const float* __restrict__ contrib,
    float* __restrict__ out)
{
    constexpr int CHUNKS = CIN / CINC;
    static_assert(CIN % CINC == 0 && COUTP % 8 == 0, "");
    constexpr int KC   = CINC*9;
    constexpr int KCP  = ceil8i(KC);
    constexpr int KP   = CHUNKS*KCP;
    constexpr int P64  = pad64(KP/2);
    constexpr int IN_S = CINC*6*68;
    constexpr int NT   = COUTP/8;
    constexpr int NKS  = KCP/8;
    extern __shared__ unsigned smu[];
    unsigned* in_s = smu;                              // IN_S words
    u64*  w2_s = (u64*)(smu + IN_S);                   // COUTP*P64
    int2* lut_s = (int2*)(w2_s + (size_t)COUTP*P64);   // NKS*4

    const int n   = blockIdx.y;
    const int oy0 = blockIdx.x * 4;
    const int tid = threadIdx.x;
    const int lane = tid & 31;
    const int mt  = tid >> 5;
    const int tg  = lane & 3;
    const int gid = lane >> 2;

    // ---- stage weights (paired (k, k+4) u64) ----
    for (int idx = tid; idx < COUTP*(KP/8)*4; idx += 512) {
        int tg_ = idx & 3; int rest = idx >> 2;
        int kgrp = rest % (KP/8); int co = rest / (KP/8);
        int k0 = kgrp*8 + tg_; int k1 = k0 + 4;
        int chunk = k0 / KCP;                  // same chunk for k0,k1 (KCP%8==0)
        int kin0 = k0 - chunk*KCP, kin1 = k1 - chunk*KCP;
        float v0 = 0.f, v1 = 0.f;
        if (co < COUT && kin0 < KC)
            v0 = w[((size_t)co*WCIN + CIOFF + chunk*CINC + kin0/9)*9 + kin0%9];
        if (co < COUT && kin1 < KC)
            v1 = w[((size_t)co*WCIN + CIOFF + chunk*CINC + kin1/9)*9 + kin1%9];
        w2_s[(size_t)co*P64 + kgrp*4 + tg_] = packtf2(v0, v1);
    }
    // ---- stage A-offset LUT (chunk-local, same for all chunks) ----
    for (int j = tid; j < NKS*4; j += 512) {
        int ks = j >> 2, tg_ = j & 3;
        int k0 = ks*8 + tg_, k1 = k0 + 4;
        int t0 = 0, t1 = 0;
        if (k0 < KC) { int c = k0/9, tp = k0%9; t0 = (c*6 + tp/3)*68 + tp%3; }
        if (k1 < KC) { int c = k1/9, tp = k1%9; t1 = (c*6 + tp/3)*68 + tp%3; }
        lut_s[j] = make_int2(t0, t1);
    }

    float acc[NT][4];
    #pragma unroll
    for (int nt = 0; nt < NT; nt++)
        #pragma unroll
        for (int e = 0; e < 4; e++) acc[nt][e] = 0.f;

    const int base = (mt >> 2)*68 + (mt & 3)*16 + gid;

    for (int chunk = 0; chunk < CHUNKS; chunk++) {
        __syncthreads();
        const int ci0 = chunk*CINC;
        for (int idx = tid; idx < CINC*6*66; idx += 512) {
            int ci = idx / (6*66); int rem = idx - ci*(6*66);
            int ry = rem / 66; int cx = rem - ry*66;
            int iy = oy0 - 1 + ry; int ix = cx - 1;
            float val = 0.f;
            if ((unsigned)iy < 64u && (unsigned)ix < 64u) {
                val = in[((size_t)n*CIN + ci0 + ci)*4096 + iy*64 + ix];
                if (BNIN) val = fmaxf(fmaf(val, bnsc[ci0+ci], bnsh[ci0+ci]), 0.f);
            }
            in_s[(ci*6 + ry)*68 + cx] = to_tf32(val);
        }
        __syncthreads();

        const u64* wc = w2_s + chunk*NKS*4 + tg + (size_t)gid*P64;
        #pragma unroll
        for (int ks = 0; ks < NKS; ks++) {
            int2 tt = lut_s[ks*4 + tg];
            unsigned a0 = in_s[tt.x + base];
            unsigned a1 = in_s[tt.x + base + 8];
            unsigned a2 = in_s[tt.y + base];
            unsigned a3 = in_s[tt.y + base + 8];
            #pragma unroll
            for (int nt = 0; nt < NT; nt++) {
                u64 bb = wc[ks*4 + (size_t)(nt*8)*P64];
                mma_tf32(acc[nt], a0, a1, a2, a3, (unsigned)bb, (unsigned)(bb >> 32));
            }
        }
    }

    // ---- epilogue ----
    const int oy = oy0 + (mt >> 2);
    const int x0 = (mt & 3)*16;
    const int vy = (oy == 0) ? 0 : ((oy == 63) ? 2 : 1);
    #pragma unroll
    for (int half = 0; half < 2; half++) {
        int x = x0 + gid + half*8;
        int vx = (x == 0) ? 0 : ((x == 63) ? 2 : 1);
        const float* cp = CONTRIB ? &contrib[((size_t)n*9 + vy*3 + vx)*64] : nullptr;
        float* op = out + (size_t)n*COUT*4096 + (size_t)oy*64 + x;
        #pragma unroll
        for (int nt = 0; nt < NT; nt++) {
            #pragma unroll
            for (int e = 0; e < 2; e++) {
                int co = nt*8 + 2*tg + e;
                if (co < COUT) {
                    float v = acc[nt][half*2 + e] + bias[co];
                    if (CONTRIB) v += cp[co];
                    if (RELU) v = fmaxf(v, 0.f);
                    op[(size_t)co*4096] = v;
                }
            }
        }
    }
}

// =====================================================================
// Tensor-core conv2: 8->32, k5, s2, p2, 128->64 (implicit GEMM, tf32).
// Block: one image, 4 output rows x 64 cols (M=256), 16 warps.
// K = 8*25 = 200 (25 k-groups), single chunk. P64 = 100 (≡4 mod 16).
// =====================================================================
__global__ __launch_bounds__(512) void tc_conv2_k(
    const float* __restrict__ in, const float* __restrict__ w,
    const float* __restrict__ bias, float* __restrict__ out)
{
    constexpr int IN_S = 8*11*132;       // 11616 words
    extern __shared__ unsigned smu[];
    unsigned* in_s = smu;
    u64*  w2_s = (u64*)(smu + IN_S);     // 32*100
    int2* lut_s = (int2*)(w2_s + 32*100);// 100

    const int n   = blockIdx.y;
    const int oy0 = blockIdx.x * 4;
    const int tid = threadIdx.x;
    const int lane = tid & 31;
    const int mt  = tid >> 5;
    const int tg  = lane & 3;
    const int gid = lane >> 2;

    // weights: k = ci*25 + ky*5 + kx (natural layout), pairs (k, k+4)
    for (int idx = tid; idx < 32*25*4; idx += 512) {
        int tg_ = idx & 3; int rest = idx >> 2;
        int kgrp = rest % 25; int co = rest / 25;
        int k0 = kgrp*8 + tg_;
        w2_s[(size_t)co*100 + kgrp*4 + tg_] =
            packtf2(w[(size_t)co*200 + k0], w[(size_t)co*200 + k0 + 4]);
    }
    // lut: k -> (ci,ky,kx) -> word offset (ci*11 + ky)*132 + kx
    for (int j = tid; j < 100; j += 512) {
        int ks = j >> 2, tg_ = j & 3;
        int k0 = ks*8 + tg_, k1 = k0 + 4;
        int c0 = k0/25, r0 = k0%25, c1 = k1/25, r1 = k1%25;
        lut_s[j] = make_int2((c0*11 + r0/5)*132 + r0%5,
                             (c1*11 + r1/5)*132 + r1%5);
    }
    // input tile: 8 ch x 11 rows x 131 cols ; iy = 2*oy0-2+ry, ix = cx-2
    for (int idx = tid; idx < 8*11*131; idx += 512) {
        int ci = idx / (11*131); int rem = idx - ci*(11*131);
        int ry = rem / 131; int cx = rem - ry*131;
        int iy = 2*oy0 - 2 + ry; int ix = cx - 2;
        float val = 0.f;
        if ((unsigned)iy < 128u && (unsigned)ix < 128u)
            val = in[((size_t)n*8 + ci)*16384 + iy*128 + ix];
        in_s[(ci*11 + ry)*132 + cx] = to_tf32(val);
    }
    __syncthreads();

    float acc[4][4];
    #pragma unroll
    for (int nt = 0; nt < 4; nt++)
        #pragma unroll
        for (int e = 0; e < 4; e++) acc[nt][e] = 0.f;

    // A addr = lut + dy*264 + 2*x ; x = x0 + m, m rows: gid (+8)
    const int base = (mt >> 2)*264 + (mt & 3)*32 + 2*gid;
    const u64* wc = w2_s + tg + (size_t)gid*100;
    #pragma unroll
    for (int ks = 0; ks < 25; ks++) {
        int2 tt = lut_s[ks*4 + tg];
        unsigned a0 = in_s[tt.x + base];
        unsigned a1 = in_s[tt.x + base + 16];
        unsigned a2 = in_s[tt.y + base];
        unsigned a3 = in_s[tt.y + base + 16];
        #pragma unroll
        for (int nt = 0; nt < 4; nt++) {
            u64 bb = wc[ks*4 + (size_t)(nt*8)*100];
            mma_tf32(acc[nt], a0, a1, a2, a3, (unsigned)bb, (unsigned)(bb >> 32));
        }
    }

    const int oy = oy0 + (mt >> 2);
    const int x0 = (mt & 3)*16;
    #pragma unroll
    for (int half = 0; half < 2; half++) {
        int x = x0 + gid + half*8;
        float* op = out + (size_t)n*32*4096 + (size_t)oy*64 + x;
        #pragma unroll
        for (int nt = 0; nt < 4; nt++) {
            #pragma unroll
            for (int e = 0; e < 2; e++) {
                int co = nt*8 + 2*tg + e;
                float v = fmaxf(acc[nt][half*2 + e] + bias[co], 0.f);
                op[(size_t)co*4096] = v;
            }
        }
    }
}

// =====================================================================
// Packed direct conv (fp32) — conv1 only.
// =====================================================================
template<int CIN,int COUT,int CG,int PX,int K,int S,int P,int HIN,int WIN,bool RELU>
__global__ __launch_bounds__(128) void convp_k(
    const float* __restrict__ in, const float* __restrict__ w,
    const float* __restrict__ bias, float* __restrict__ out)
{
    constexpr int HOUT = (HIN + 2*P - K)/S + 1;
    constexpr int WOUT = (WIN + 2*P - K)/S + 1;
    constexpr int CGP  = (CG + 3) & ~3;
    constexpr int NP   = CGP/2;
    constexpr int IW   = (PX-1)*S + K;
    extern __shared__ float sw[];
    float* sb  = sw + CIN*K*K*CGP;
    const int co0 = blockIdx.y * CG;
    for (int i = threadIdx.x; i < CIN*K*K*CGP; i += blockDim.x) {
        int co = i % CGP; int r = i / CGP;
        sw[i] = (co < CG) ? w[(size_t)(co0+co)*CIN*K*K + r] : 0.f;
    }
    for (int i = threadIdx.x; i < CGP; i += blockDim.x)
        sb[i] = (i < CG) ? bias[co0 + i] : 0.f;
    __syncthreads();

    constexpr int XB = WOUT / PX;
    int idx = blockIdx.x*blockDim.x + threadIdx.x;
    if (idx >= NB*HOUT*XB) return;
    int xb = (idx % XB) * PX;
    int oy = (idx / XB) % HOUT;
    int n  = idx / (XB*HOUT);

    u64 acc[PX][NP];
    #pragma unroll
    for (int p = 0; p < PX; p++)
        #pragma unroll
        for (int j = 0; j < NP; j++) acc[p][j] = pack2(sb[2*j], sb[2*j+1]);

    const float* inp = in + (size_t)n*CIN*HIN*WIN;
    const int ix0 = xb*S - P;
    #pragma unroll 1
    for (int ci = 0; ci < CIN; ci++) {
        #pragma unroll
        for (int ky = 0; ky < K; ky++) {
            int iy = oy*S - P + ky;
            if (iy < 0 || iy >= HIN) continue;
            const float* row = inp + (size_t)ci*HIN*WIN + (size_t)iy*WIN;
            u64 v2[IW];
            #pragma unroll
            for (int j = 0; j < IW; j++) {
                int ix = ix0 + j;
                v2[j] = bcast2((ix >= 0 && ix < WIN) ? __ldg(row + ix) : 0.f);
            }
            #pragma unroll
            for (int kx = 0; kx < K; kx++) {
                const float* wp = &sw[((ci*K+ky)*K+kx)*CGP];
                #pragma unroll
                for (int j = 0; j < NP; j += 2) {
                    ulonglong2 wq = *reinterpret_cast<const ulonglong2*>(wp + 2*j);
                    #pragma unroll
                    for (int p = 0; p < PX; p++) {
                        fma2(acc[p][j],   v2[p*S+kx], wq.x);
                        fma2(acc[p][j+1], v2[p*S+kx], wq.y);
                    }
                }
            }
        }
    }
    float* op = out + ((size_t)n*COUT + co0)*HOUT*WOUT + (size_t)oy*WOUT + xb;
    #pragma unroll
    for (int j = 0; j < CG/2; j++)
        #pragma unroll
        for (int p = 0; p < PX; p++) {
            float2 a = unpack2(acc[p][j]);
            if (RELU) { a.x = fmaxf(a.x, 0.f); a.y = fmaxf(a.y, 0.f); }
            op[(size_t)(2*j)  *HOUT*WOUT + p] = a.x;
            op[(size_t)(2*j+1)*HOUT*WOUT + p] = a.y;
        }
}

// ---------------- legacy per-pixel conv (tiny tail kernels) ----------------
template<int CIN,int COUT,int K,int S,int P,int HIN,int WIN,bool RELU>
__global__ __launch_bounds__(128) void conv_k(
    const float* __restrict__ in, const float* __restrict__ w,
    const float* __restrict__ bias, float* __restrict__ out)
{
    constexpr int HOUT = (HIN + 2*P - K)/S + 1;
    constexpr int WOUT = (WIN + 2*P - K)/S + 1;
    constexpr int COUTP = (COUT + 3) & ~3;
    extern __shared__ float sw[];
    float* sb = sw + CIN*K*K*COUTP;
    for (int i = threadIdx.x; i < CIN*K*K*COUTP; i += blockDim.x) {
        int co = i % COUTP; int r = i / COUTP;
        sw[i] = (co < COUT) ? w[co*CIN*K*K + r] : 0.f;
    }
    for (int i = threadIdx.x; i < COUTP; i += blockDim.x)
        sb[i] = (i < COUT) ? bias[i] : 0.f;
    __syncthreads();

    int idx = blockIdx.x*blockDim.x + threadIdx.x;
    if (idx >= NB*HOUT*WOUT) return;
    int ox = idx % WOUT; int oy = (idx/WOUT) % HOUT; int n = idx/(WOUT*HOUT);

    float acc[COUTP];
    #pragma unroll
    for (int c = 0; c < COUTP; c++) acc[c] = sb[c];

    const float* inp = in + (size_t)n*CIN*HIN*WIN;
    #pragma unroll 1
    for (int ci = 0; ci < CIN; ci++) {
        #pragma unroll
        for (int ky = 0; ky < K; ky++) {
            int iy = oy*S - P + ky;
            if (iy < 0 || iy >= HIN) continue;
            #pragma unroll
            for (int kx = 0; kx < K; kx++) {
                int ix = ox*S - P + kx;
                if (ix < 0 || ix >= WIN) continue;
                float v = __ldg(&inp[(size_t)ci*HIN*WIN + (size_t)iy*WIN + ix]);
                const float* wp = &sw[((ci*K+ky)*K+kx)*COUTP];
                #pragma unroll
                for (int co = 0; co < COUTP; co += 4) {
                    float4 w4 = *reinterpret_cast<const float4*>(wp + co);
                    acc[co+0] = fmaf(v, w4.x, acc[co+0]);
                    acc[co+1] = fmaf(v, w4.y, acc[co+1]);
                    acc[co+2] = fmaf(v, w4.z, acc[co+2]);
                    acc[co+3] = fmaf(v, w4.w, acc[co+3]);
                }
            }
        }
    }
    float* op = out + ((size_t)n*COUT*HOUT + (size_t)oy)*WOUT + ox;
    #pragma unroll
    for (int co = 0; co < COUT; co++) {
        float v = acc[co];
        if (RELU) v = fmaxf(v, 0.f);
        op[(size_t)co*HOUT*WOUT] = v;
    }
}

// ---------------- conv7: 1x1, 8->1 over 4x4 -> blur[n][16] -----------------
__global__ void conv7_k(const float* __restrict__ t6, const float* __restrict__ w,
                        const float* __restrict__ b, float* __restrict__ blur)
{
    int i = blockIdx.x*blockDim.x + threadIdx.x;
    if (i >= NB*16) return;
    int n = i >> 4, p = i & 15;
    float acc = b[0];
    #pragma unroll
    for (int ci = 0; ci < 8; ci++)
        acc = fmaf(t6[(n*8 + ci)*16 + p], w[ci], acc);
    blur[i] = fmaxf(acc, 0.f);
}

// ---------------- blur precompute ------------------------------------------
__global__ void blurpre_k(const float* __restrict__ blur, const float* __restrict__ r1w,
                          const float* __restrict__ pw, float* __restrict__ contrib,
                          float* __restrict__ pwblur)
{
    int n = blockIdx.x;
    int co = threadIdx.x;
    float s[9];
    #pragma unroll
    for (int q = 0; q < 9; q++) s[q] = 0.f;
    for (int ci = 0; ci < 16; ci++) {
        float bv = blur[n*16 + ci];
        const float* tw = r1w + ((size_t)co*48 + ci)*9;
        float t[9];
        #pragma unroll
        for (int q = 0; q < 9; q++) t[q] = tw[q];
        float cs[3][3];
        #pragma unroll
        for (int ky = 0; ky < 3; ky++) {
            cs[ky][0] = t[ky*3+1] + t[ky*3+2];
            cs[ky][1] = t[ky*3+0] + t[ky*3+1] + t[ky*3+2];
            cs[ky][2] = t[ky*3+0] + t[ky*3+1];
        }
        #pragma unroll
        for (int vx = 0; vx < 3; vx++) {
            float r0 = cs[1][vx] + cs[2][vx];
            float r1v = cs[0][vx] + cs[1][vx] + cs[2][vx];
            float r2 = cs[0][vx] + cs[1][vx];
            s[0*3+vx] = fmaf(bv, r0,  s[0*3+vx]);
            s[1*3+vx] = fmaf(bv, r1v, s[1*3+vx]);
            s[2*3+vx] = fmaf(bv, r2,  s[2*3+vx]);
        }
    }
    #pragma unroll
    for (int q = 0; q < 9; q++) contrib[((size_t)n*9 + q)*64 + co] = s[q];

    if (co < 20) {
        float q = 0.f;
        for (int ci = 0; ci < 16; ci++)
            q = fmaf(blur[n*16 + ci], pw[co*48 + ci], q);
        pwblur[n*20 + co] = q;
    }
}

// ---------------- BatchNorm stats ------------------------------------------
template<int C, int HW>
__global__ void bn_part_k(const float* __restrict__ x, float* __restrict__ part)
{
    int c = blockIdx.x;
    float s = 0.f, s2 = 0.f;
    constexpr int HW4 = HW/4;
    const int per = NB*HW4;
    for (int i = blockIdx.y*blockDim.x + threadIdx.x; i < per; i += gridDim.y*blockDim.x) {
        int n = i / HW4; int j = i - n*HW4;
        float4 v = *reinterpret_cast<const float4*>(&x[((size_t)n*C + c)*HW + j*4]);
        s  += (v.x + v.y) + (v.z + v.w);
        s2 += (v.x*v.x + v.y*v.y) + (v.z*v.z + v.w*v.w);
    }
    __shared__ float rs[256], rs2[256];
    rs[threadIdx.x] = s; rs2[threadIdx.x] = s2;
    __syncthreads();
    for (int o = blockDim.x/2; o > 0; o >>= 1) {
        if (threadIdx.x < o) {
            rs[threadIdx.x]  += rs[threadIdx.x + o];
            rs2[threadIdx.x] += rs2[threadIdx.x + o];
        }
        __syncthreads();
    }
    if (threadIdx.x == 0) {
        part[c*32 + blockIdx.y]        = rs[0];
        part[C*32 + c*32 + blockIdx.y] = rs2[0];
    }
}

template<int C, int HW>
__global__ void bn_fin_k(const float* __restrict__ part, const float* __restrict__ g,
                         const float* __restrict__ be, float* __restrict__ scale,
                         float* __restrict__ shift)
{
    int c = threadIdx.x;
    if (c >= C) return;
    float s = 0.f, s2 = 0.f;
    for (int b = 0; b < 32; b++) { s += part[c*32 + b]; s2 += part[C*32 + c*32 + b]; }
    const float cnt = (float)NB * (float)HW;
    float mu  = s / cnt;
    float var = s2 / cnt - mu*mu;
    float sc  = g[c] * rsqrtf(var + 1e-5f);
    scale[c] = sc;
    shift[c] = be[c] - mu*sc;
}

// ---------------- bn2 apply + pointwise(ds) + pwblur residual --------------
__global__ __launch_bounds__(128) void bn2pw_k(
    float* __restrict__ r2, const float* __restrict__ pwblur,
    const float* __restrict__ ds, const float* __restrict__ pw,
    const float* __restrict__ pb, const float* __restrict__ scale,
    const float* __restrict__ shift)
{
    __shared__ float sw[32*20];
    __shared__ float sb[20], ssc[20], ssh[20];
    for (int i = threadIdx.x; i < 32*20; i += blockDim.x) {
        int co = i % 20, ci = i / 20;
        sw[i] = pw[co*48 + 16 + ci];
    }
    if (threadIdx.x < 20) {
        sb[threadIdx.x]  = pb[threadIdx.x];
        ssc[threadIdx.x] = scale[threadIdx.x];
        ssh[threadIdx.x] = shift[threadIdx.x];
    }
    __syncthreads();

    int idx = blockIdx.x*blockDim.x + threadIdx.x;
    if (idx >= NB*4096) return;
    int p = idx & 4095; int n = idx >> 12;

    u64 acc[10];
    const float* pbl = &pwblur[n*20];
    #pragma unroll
    for (int j = 0; j < 10; j++)
        acc[j] = pack2(sb[2*j] + pbl[2*j], sb[2*j+1] + pbl[2*j+1]);

    const float* dsp = ds + (size_t)n*32*4096 + p;
    #pragma unroll 1
    for (int ci = 0; ci < 32; ci++) {
        u64 v = bcast2(__ldg(&dsp[(size_t)ci*4096]));
        const float* wp = &sw[ci*20];
        #pragma unroll
        for (int j = 0; j < 10; j += 2) {
            ulonglong2 wq = *reinterpret_cast<const ulonglong2*>(wp + 2*j);
            fma2(acc[j],   v, wq.x);
            fma2(acc[j+1], v, wq.y);
        }
    }
    float* rp = r2 + (size_t)n*20*4096 + p;
    #pragma unroll
    for (int j = 0; j < 10; j++) {
        float2 a = unpack2(acc[j]);
        int c = 2*j;
        rp[(size_t)c    *4096] = fmaf(rp[(size_t)c    *4096], ssc[c],   ssh[c])   + a.x;
        rp[(size_t)(c+1)*4096] = fmaf(rp[(size_t)(c+1)*4096], ssc[c+1], ssh[c+1]) + a.y;
    }
}

// ---------------- final: u2 1x1 + relu + pixel_shuffle(4) + sigmoid --------
__global__ __launch_bounds__(128) void final_k(
    const float* __restrict__ u1, const float* __restrict__ w,
    const float* __restrict__ b, float* __restrict__ out)
{
    __shared__ float sw[30*16];
    __shared__ float sb[16];
    for (int i = threadIdx.x; i < 30*16; i += blockDim.x) {
        int co = i % 16, ci = i / 16;
        sw[i] = w[co*30 + ci];
    }
    if (threadIdx.x < 16) sb[threadIdx.x] = b[threadIdx.x];
    __syncthreads();

    int idx = blockIdx.x*blockDim.x + threadIdx.x;
    if (idx >= NB*4096) return;
    int wq = idx & 63; int h = (idx >> 6) & 63; int n = idx >> 12;

    u64 acc[8];
    #pragma unroll
    for (int j = 0; j < 8; j++) acc[j] = pack2(sb[2*j], sb[2*j+1]);

    const float* up = u1 + (size_t)n*30*4096 + h*64 + wq;
    #pragma unroll 1
    for (int ci = 0; ci < 30; ci++) {
        u64 v = bcast2(__ldg(&up[(size_t)ci*4096]));
        const float* wp = &sw[ci*16];
        #pragma unroll
        for (int j = 0; j < 8; j += 2) {
            ulonglong2 wqv = *reinterpret_cast<const ulonglong2*>(wp + 2*j);
            fma2(acc[j],   v, wqv.x);
            fma2(acc[j+1], v, wqv.y);
        }
    }
    float* op = out + (size_t)n*65536;
    #pragma unroll
    for (int j = 0; j < 8; j++) {
        float2 a = unpack2(acc[j]);
        #pragma unroll
        for (int h2 = 0; h2 < 2; h2++) {
            int c = 2*j + h2;
            float v = fmaxf(h2 ? a.y : a.x, 0.f);
            v = 1.f / (1.f + expf(-v));
            op[(h*4 + (c >> 2))*256 + wq*4 + (c & 3)] = v;
        }
    }
}

// ---------------------------------------------------------------------------
extern "C" void kernel_launch(void* const* d_in, const int* in_sizes, int n_in,
                              void* d_out, int out_size)
{
    const float* x1  = (const float*)d_in[0];
    const float* c1w = (const float*)d_in[1];  const float* c1b = (const float*)d_in[2];
    const float* c2w = (const float*)d_in[3];  const float* c2b = (const float*)d_in[4];
    const float* c3w = (const float*)d_in[5];  const float* c3b = (const float*)d_in[6];
    const float* c4w = (const float*)d_in[7];  const float* c4b = (const float*)d_in[8];
    const float* c5w = (const float*)d_in[9];  const float* c5b = (const float*)d_in[10];
    const float* c6w = (const float*)d_in[11]; const float* c6b = (const float*)d_in[12];
    const float* c7w = (const float*)d_in[13]; const float* c7b = (const float*)d_in[14];
    const float* r1w = (const float*)d_in[15]; const float* r1b = (const float*)d_in[16];
    const float* g1  = (const float*)d_in[17]; const float* be1 = (const float*)d_in[18];
    const float* r2w = (const float*)d_in[19]; const float* r2b = (const float*)d_in[20];
    const float* g2  = (const float*)d_in[21]; const float* be2 = (const float*)d_in[22];
    const float* pw  = (const float*)d_in[23]; const float* pb  = (const float*)d_in[24];
    const float* u1w = (const float*)d_in[25]; const float* u1b = (const float*)d_in[26];
    const float* u2w = (const float*)d_in[27]; const float* u2b = (const float*)d_in[28];

    float *t1,*ds,*t3,*t4,*t5,*t6,*blur,*r1,*r2,*u1,*part,*scale,*shift,*contrib,*pwblur;
    cudaGetSymbolAddress((void**)&t1,     g_t1);
    cudaGetSymbolAddress((void**)&ds,     g_ds);
    cudaGetSymbolAddress((void**)&t3,     g_t3);
    cudaGetSymbolAddress((void**)&t4,     g_t4);
    cudaGetSymbolAddress((void**)&t5,     g_t5);
    cudaGetSymbolAddress((void**)&t6,     g_t6);
    cudaGetSymbolAddress((void**)&blur,   g_blur);
    cudaGetSymbolAddress((void**)&r1,     g_r1);
    cudaGetSymbolAddress((void**)&r2,     g_r2);
    cudaGetSymbolAddress((void**)&u1,     g_u1);
    cudaGetSymbolAddress((void**)&part,   g_part);
    cudaGetSymbolAddress((void**)&scale,  g_scale);
    cudaGetSymbolAddress((void**)&shift,  g_shift);
    cudaGetSymbolAddress((void**)&contrib,g_contrib);
    cudaGetSymbolAddress((void**)&pwblur, g_pwblur);

    auto smemL = [](int cin, int coutp, int k) { return (size_t)(cin*k*k*coutp + coutp)*4; };
    auto smemP = [](int cin, int cgp, int k) { return (size_t)(cin*k*k*cgp + cgp)*4; };
    // tc smem: in tile + paired weights + LUT
    auto smemTC = [](int cinc, int coutp, int kp, int kcp) {
        return (size_t)(cinc*6*68)*4 + (size_t)coutp*pad64(kp/2)*8 + (size_t)(kcp/8)*4*8;
    };
    size_t sm_r1 = smemTC(16, 64, 2*ceil8i(16*9), ceil8i(16*9));
    size_t sm_r2 = smemTC(16, 24, 4*ceil8i(16*9), ceil8i(16*9));
    size_t sm_u1 = smemTC(20, 32, 1*ceil8i(20*9), ceil8i(20*9));
    size_t sm_c2 = (size_t)(8*11*132)*4 + (size_t)32*100*8 + 100*8;

    cudaFuncSetAttribute((const void*)conv_k<20,30,5,2,2,16,16,true>,
                         cudaFuncAttributeMaxDynamicSharedMemorySize, (int)smemL(20,32,5));
    cudaFuncSetAttribute((const void*)tc_conv3_k<32,16,48,16,64,64,false,false,true>,
                         cudaFuncAttributeMaxDynamicSharedMemorySize, (int)sm_r1);
    cudaFuncSetAttribute((const void*)tc_conv3_k<64,16,64,0,20,24,false,true,false>,
                         cudaFuncAttributeMaxDynamicSharedMemorySize, (int)sm_r2);
    cudaFuncSetAttribute((const void*)tc_conv3_k<20,20,20,0,30,32,true,false,false>,
                         cudaFuncAttributeMaxDynamicSharedMemorySize, (int)sm_u1);
    cudaFuncSetAttribute((const void*)tc_conv2_k,
                         cudaFuncAttributeMaxDynamicSharedMemorySize, (int)sm_c2);

    // ---------------- encoder ----------------
    convp_k<1,8,8,4,3,2,1,256,256,true>
        <<<(NB*128*32+127)/128,128, smemP(1,8,3)>>>(x1, c1w, c1b, t1);
    tc_conv2_k<<<dim3(16,NB),512, sm_c2>>>(t1, c2w, c2b, ds);
    conv_k<32,4,3,2,1, 64, 64,false><<<(NB*32*32+127)/128,128, smemL(32,4,3)>>> (ds, c3w, c3b, t3);
    conv_k<4,20,3,2,1, 32, 32,true><<<(NB*16*16+127)/128,128, smemL(4,20,3)>>>  (t3, c4w, c4b, t4);
    conv_k<20,30,5,2,2,16, 16,true><<<(NB*8*8  +127)/128,128, smemL(20,32,5)>>> (t4, c5w, c5b, t5);
    conv_k<30, 8,3,2,1,  8,  8,true><<<(NB*4*4 +127)/128,128, smemL(30,8,3)>>>  (t5, c6w, c6b, t6);
    conv7_k<<<(NB*16+127)/128,128>>>(t6, c7w, c7b, blur);

    blurpre_k<<<NB,64>>>(blur, r1w, pw, contrib, pwblur);

    // ---------------- residual block with training-mode BN ----------------
    tc_conv3_k<32,16,48,16,64,64,false,false,true>
        <<<dim3(16,NB),512, sm_r1>>>(ds, r1w, r1b, nullptr, nullptr, contrib, r1);
    { dim3 g(64,32); bn_part_k<64,4096><<<g,256>>>(r1, part); }
    bn_fin_k<64,4096><<<1,64>>>(part, g1, be1, scale, shift);

    tc_conv3_k<64,16,64,0,20,24,false,true,false>
        <<<dim3(16,NB),512, sm_r2>>>(r1, r2w, r2b, scale, shift, nullptr, r2);
    { dim3 g(20,32); bn_part_k<20,4096><<<g,256>>>(r2, part); }
    bn_fin_k<20,4096><<<1,32>>>(part, g2, be2, scale, shift);
    bn2pw_k<<<(NB*4096+127)/128,128>>>(r2, pwblur, ds, pw, pb, scale, shift);

    // ---------------- upsample head ----------------
    tc_conv3_k<20,20,20,0,30,32,true,false,false>
        <<<dim3(16,NB),512, sm_u1>>>(r2, u1w, u1b, nullptr, nullptr, nullptr, u1);
    final_k<<<(NB*4096+127)/128,128>>>(u1, u2w, u2b, (float*)d_out);
}

// round 9
// speedup vs baseline: 3.0024x; 1.0840x over previous
#include <cuda_runtime.h>
#include <cuda_bf16.h>
#include <math.h>

#define NB 128

// ---------------- scratch (device globals; no allocation allowed) ----------
__device__ float g_t1[(size_t)NB*8*128*128];
__device__ float g_ds[(size_t)NB*32*64*64];
__device__ float g_t3[(size_t)NB*4*32*32];
__device__ float g_t4[(size_t)NB*20*16*16];
__device__ float g_t5[(size_t)NB*30*8*8];
__device__ float g_t6[(size_t)NB*8*4*4];
__device__ float g_blur[NB*16];
__device__ float g_r1[(size_t)NB*64*64*64];
__device__ float g_r2[(size_t)NB*20*64*64];
__device__ float g_u1[(size_t)NB*30*64*64];
__device__ float g_part[2*64*32];
__device__ float g_scale[64];
__device__ float g_shift[64];
__device__ float g_contrib[NB*9*64];
__device__ float g_pwblur[NB*20];

typedef unsigned long long u64;
// pre-packed tf32 weight buffers (filled once per launch by pack kernels)
__device__ __align__(16) u64 g_wp_r1[64*148];
__device__ __align__(16) u64 g_wp_r2[24*292];
__device__ __align__(16) u64 g_wp_u1[32*100];
__device__ __align__(16) u64 g_wp_c2[32*100];

// ---------------- helpers ----------------
static __device__ __forceinline__ u64 pack2(float x, float y) {
    u64 r; asm("mov.b64 %0, {%1, %2};" : "=l"(r) : "f"(x), "f"(y)); return r;
}
static __device__ __forceinline__ u64 bcast2(float x) { return pack2(x, x); }
static __device__ __forceinline__ void fma2(u64& d, u64 a, u64 b) {
    asm("fma.rn.f32x2 %0, %1, %2, %0;" : "+l"(d) : "l"(a), "l"(b));
}
static __device__ __forceinline__ float2 unpack2(u64 v) {
    float2 r; asm("mov.b64 {%0, %1}, %2;" : "=f"(r.x), "=f"(r.y) : "l"(v)); return r;
}
static __device__ __forceinline__ unsigned to_tf32(float v) {
    unsigned u; asm("cvt.rna.tf32.f32 %0, %1;" : "=r"(u) : "f"(v)); return u;
}
static __device__ __forceinline__ u64 packtf2(float x, float y) {
    return (u64)to_tf32(x) | ((u64)to_tf32(y) << 32);
}
static __device__ __forceinline__ void mma_tf32(
    float* acc, unsigned a0, unsigned a1, unsigned a2, unsigned a3,
    unsigned b0, unsigned b1)
{
    asm volatile(
      "mma.sync.aligned.m16n8k8.row.col.f32.tf32.tf32.f32 "
      "{%0,%1,%2,%3}, {%4,%5,%6,%7}, {%8,%9}, {%0,%1,%2,%3};"
      : "+f"(acc[0]), "+f"(acc[1]), "+f"(acc[2]), "+f"(acc[3])
      : "r"(a0), "r"(a1), "r"(a2), "r"(a3), "r"(b0), "r"(b1));
}

__host__ __device__ constexpr int ceil8i(int x) { return (x + 7) & ~7; }
__host__ __device__ constexpr int pad64(int x) { return x + ((4 - (x & 15)) + 16) % 16; }

// =====================================================================
// Weight pre-pack kernels: write (k, k+4) tf32 u64 pairs with per-co
// stride P64 (≡4 mod 16) into global scratch. Runs once per launch.
// =====================================================================
template<int CIN,int CINC,int WCIN,int CIOFF,int COUT,int COUTP>
__global__ void pack3_k(const float* __restrict__ w, u64* __restrict__ wp)
{
    constexpr int KC  = CINC*9;
    constexpr int KCP = ceil8i(KC);
    constexpr int KP  = (CIN/CINC)*KCP;
    constexpr int P64 = pad64(KP/2);
    int idx = blockIdx.x*blockDim.x + threadIdx.x;
    if (idx >= COUTP*P64) return;
    int co = idx / P64; int j = idx - co*P64;
    u64 val = 0;
    if (j < (KP/8)*4) {
        int kgrp = j >> 2, tg = j & 3;
        int k0 = kgrp*8 + tg, k1 = k0 + 4;
        int chunk = k0 / KCP;
        int kin0 = k0 - chunk*KCP, kin1 = k1 - chunk*KCP;
        float v0 = 0.f, v1 = 0.f;
        if (co < COUT && kin0 < KC)
            v0 = w[((size_t)co*WCIN + CIOFF + chunk*CINC + kin0/9)*9 + kin0%9];
        if (co < COUT && kin1 < KC)
            v1 = w[((size_t)co*WCIN + CIOFF + chunk*CINC + kin1/9)*9 + kin1%9];
        val = packtf2(v0, v1);
    }
    wp[idx] = val;
}

__global__ void pack2p_k(const float* __restrict__ w, u64* __restrict__ wp)
{
    int idx = blockIdx.x*blockDim.x + threadIdx.x;   // 32*100
    if (idx >= 32*100) return;
    int co = idx / 100; int j = idx - co*100;
    int kgrp = j >> 2, tg = j & 3;
    int k0 = kgrp*8 + tg;
    wp[idx] = packtf2(w[(size_t)co*200 + k0], w[(size_t)co*200 + k0 + 4]);
}

// =====================================================================
// Tensor-core 3x3 s1 p1 conv on 64x64 images (implicit GEMM, tf32 mma).
// Weights pre-packed in global; staging = straight ulonglong2 copy.
// =====================================================================
template<int CIN,int CINC,int WCIN,int CIOFF,int COUT,int COUTP,bool RELU,bool BNIN,bool CONTRIB>
__global__ __launch_bounds__(512) void tc_conv3_k(
    const float* __restrict__ in, const u64* __restrict__ wp,
    const float* __restrict__ bias, const float* __restrict__ bnsc,
    const float* __restrict__ bnsh, const float* __restrict__ contrib,
    float* __restrict__ out)
{
    constexpr int CHUNKS = CIN / CINC;
    static_assert(CIN % CINC == 0 && COUTP % 8 == 0, "");
    constexpr int KC   = CINC*9;
    constexpr int KCP  = ceil8i(KC);
    constexpr int KP   = CHUNKS*KCP;
    constexpr int P64  = pad64(KP/2);
    constexpr int IN_S = CINC*6*68;
    constexpr int NT   = COUTP/8;
    constexpr int NKS  = KCP/8;
    extern __shared__ unsigned smu[];
    unsigned* in_s = smu;                              // IN_S words
    u64*  w2_s = (u64*)(smu + IN_S);                   // COUTP*P64
    int2* lut_s = (int2*)(w2_s + (size_t)COUTP*P64);   // NKS*4

    const int n   = blockIdx.y;
    const int oy0 = blockIdx.x * 4;
    const int tid = threadIdx.x;
    const int lane = tid & 31;
    const int mt  = tid >> 5;
    const int tg  = lane & 3;
    const int gid = lane >> 2;

    // ---- stage pre-packed weights (vector copy) ----
    {
        ulonglong2* d = (ulonglong2*)w2_s;
        const ulonglong2* s = (const ulonglong2*)wp;
        for (int i = tid; i < COUTP*P64/2; i += 512) d[i] = s[i];
    }
    // ---- A-offset LUT (chunk-local) ----
    for (int j = tid; j < NKS*4; j += 512) {
        int ks = j >> 2, tg_ = j & 3;
        int k0 = ks*8 + tg_, k1 = k0 + 4;
        int t0 = 0, t1 = 0;
        if (k0 < KC) { int c = k0/9, tp = k0%9; t0 = (c*6 + tp/3)*68 + tp%3; }
        if (k1 < KC) { int c = k1/9, tp = k1%9; t1 = (c*6 + tp/3)*68 + tp%3; }
        lut_s[j] = make_int2(t0, t1);
    }

    float acc[NT][4];
    #pragma unroll
    for (int nt = 0; nt < NT; nt++)
        #pragma unroll
        for (int e = 0; e < 4; e++) acc[nt][e] = 0.f;

    const int base = (mt >> 2)*68 + (mt & 3)*16 + gid;

    for (int chunk = 0; chunk < CHUNKS; chunk++) {
        __syncthreads();
        const int ci0 = chunk*CINC;
        for (int idx = tid; idx < CINC*6*66; idx += 512) {
            int ci = idx / (6*66); int rem = idx - ci*(6*66);
            int ry = rem / 66; int cx = rem - ry*66;
            int iy = oy0 - 1 + ry; int ix = cx - 1;
            float val = 0.f;
            if ((unsigned)iy < 64u && (unsigned)ix < 64u) {
                val = in[((size_t)n*CIN + ci0 + ci)*4096 + iy*64 + ix];
                if (BNIN) val = fmaxf(fmaf(val, bnsc[ci0+ci], bnsh[ci0+ci]), 0.f);
            }
            in_s[(ci*6 + ry)*68 + cx] = to_tf32(val);
        }
        __syncthreads();

        const u64* wc = w2_s + chunk*NKS*4 + tg + (size_t)gid*P64;
        #pragma unroll
        for (int ks = 0; ks < NKS; ks++) {
            int2 tt = lut_s[ks*4 + tg];
            unsigned a0 = in_s[tt.x + base];
            unsigned a1 = in_s[tt.x + base + 8];
            unsigned a2 = in_s[tt.y + base];
            unsigned a3 = in_s[tt.y + base + 8];
            #pragma unroll
            for (int nt = 0; nt < NT; nt++) {
                u64 bb = wc[ks*4 + (size_t)(nt*8)*P64];
                mma_tf32(acc[nt], a0, a1, a2, a3, (unsigned)bb, (unsigned)(bb >> 32));
            }
        }
    }

    // ---- epilogue ----
    const int oy = oy0 + (mt >> 2);
    const int x0 = (mt & 3)*16;
    const int vy = (oy == 0) ? 0 : ((oy == 63) ? 2 : 1);
    #pragma unroll
    for (int half = 0; half < 2; half++) {
        int x = x0 + gid + half*8;
        int vx = (x == 0) ? 0 : ((x == 63) ? 2 : 1);
        const float* cp = CONTRIB ? &contrib[((size_t)n*9 + vy*3 + vx)*64] : nullptr;
        float* op = out + (size_t)n*COUT*4096 + (size_t)oy*64 + x;
        #pragma unroll
        for (int nt = 0; nt < NT; nt++) {
            #pragma unroll
            for (int e = 0; e < 2; e++) {
                int co = nt*8 + 2*tg + e;
                if (co < COUT) {
                    float v = acc[nt][half*2 + e] + bias[co];
                    if (CONTRIB) v += cp[co];
                    if (RELU) v = fmaxf(v, 0.f);
                    op[(size_t)co*4096] = v;
                }
            }
        }
    }
}

// =====================================================================
// Tensor-core conv2: 8->32, k5, s2, p2, 128->64 (implicit GEMM, tf32).
// =====================================================================
__global__ __launch_bounds__(512) void tc_conv2_k(
    const float* __restrict__ in, const u64* __restrict__ wp,
    const float* __restrict__ bias, float* __restrict__ out)
{
    constexpr int IN_S = 8*11*132;
    extern __shared__ unsigned smu[];
    unsigned* in_s = smu;
    u64*  w2_s = (u64*)(smu + IN_S);     // 32*100
    int2* lut_s = (int2*)(w2_s + 32*100);// 100

    const int n   = blockIdx.y;
    const int oy0 = blockIdx.x * 4;
    const int tid = threadIdx.x;
    const int lane = tid & 31;
    const int mt  = tid >> 5;
    const int tg  = lane & 3;
    const int gid = lane >> 2;

    {
        ulonglong2* d = (ulonglong2*)w2_s;
        const ulonglong2* s = (const ulonglong2*)wp;
        for (int i = tid; i < 32*100/2; i += 512) d[i] = s[i];
    }
    for (int j = tid; j < 100; j += 512) {
        int ks = j >> 2, tg_ = j & 3;
        int k0 = ks*8 + tg_, k1 = k0 + 4;
        int c0 = k0/25, r0 = k0%25, c1 = k1/25, r1 = k1%25;
        lut_s[j] = make_int2((c0*11 + r0/5)*132 + r0%5,
                             (c1*11 + r1/5)*132 + r1%5);
    }
    for (int idx = tid; idx < 8*11*131; idx += 512) {
        int ci = idx / (11*131); int rem = idx - ci*(11*131);
        int ry = rem / 131; int cx = rem - ry*131;
        int iy = 2*oy0 - 2 + ry; int ix = cx - 2;
        float val = 0.f;
        if ((unsigned)iy < 128u && (unsigned)ix < 128u)
            val = in[((size_t)n*8 + ci)*16384 + iy*128 + ix];
        in_s[(ci*11 + ry)*132 + cx] = to_tf32(val);
    }
    __syncthreads();

    float acc[4][4];
    #pragma unroll
    for (int nt = 0; nt < 4; nt++)
        #pragma unroll
        for (int e = 0; e < 4; e++) acc[nt][e] = 0.f;

    const int base = (mt >> 2)*264 + (mt & 3)*32 + 2*gid;
    const u64* wc = w2_s + tg + (size_t)gid*100;
    #pragma unroll
    for (int ks = 0; ks < 25; ks++) {
        int2 tt = lut_s[ks*4 + tg];
        unsigned a0 = in_s[tt.x + base];
        unsigned a1 = in_s[tt.x + base + 16];
        unsigned a2 = in_s[tt.y + base];
        unsigned a3 = in_s[tt.y + base + 16];
        #pragma unroll
        for (int nt = 0; nt < 4; nt++) {
            u64 bb = wc[ks*4 + (size_t)(nt*8)*100];
            mma_tf32(acc[nt], a0, a1, a2, a3, (unsigned)bb, (unsigned)(bb >> 32));
        }
    }

    const int oy = oy0 + (mt >> 2);
    const int x0 = (mt & 3)*16;
    #pragma unroll
    for (int half = 0; half < 2; half++) {
        int x = x0 + gid + half*8;
        float* op = out + (size_t)n*32*4096 + (size_t)oy*64 + x;
        #pragma unroll
        for (int nt = 0; nt < 4; nt++) {
            #pragma unroll
            for (int e = 0; e < 2; e++) {
                int co = nt*8 + 2*tg + e;
                float v = fmaxf(acc[nt][half*2 + e] + bias[co], 0.f);
                op[(size_t)co*4096] = v;
            }
        }
    }
}

// =====================================================================
// Packed direct conv (fp32) — conv1 only.
// =====================================================================
template<int CIN,int COUT,int CG,int PX,int K,int S,int P,int HIN,int WIN,bool RELU>
__global__ __launch_bounds__(128) void convp_k(
    const float* __restrict__ in, const float* __restrict__ w,
    const float* __restrict__ bias, float* __restrict__ out)
{
    constexpr int HOUT = (HIN + 2*P - K)/S + 1;
    constexpr int WOUT = (WIN + 2*P - K)/S + 1;
    constexpr int CGP  = (CG + 3) & ~3;
    constexpr int NP   = CGP/2;
    constexpr int IW   = (PX-1)*S + K;
    extern __shared__ float sw[];
    float* sb  = sw + CIN*K*K*CGP;
    const int co0 = blockIdx.y * CG;
    for (int i = threadIdx.x; i < CIN*K*K*CGP; i += blockDim.x) {
        int co = i % CGP; int r = i / CGP;
        sw[i] = (co < CG) ? w[(size_t)(co0+co)*CIN*K*K + r] : 0.f;
    }
    for (int i = threadIdx.x; i < CGP; i += blockDim.x)
        sb[i] = (i < CG) ? bias[co0 + i] : 0.f;
    __syncthreads();

    constexpr int XB = WOUT / PX;
    int idx = blockIdx.x*blockDim.x + threadIdx.x;
    if (idx >= NB*HOUT*XB) return;
    int xb = (idx % XB) * PX;
    int oy = (idx / XB) % HOUT;
    int n  = idx / (XB*HOUT);

    u64 acc[PX][NP];
    #pragma unroll
    for (int p = 0; p < PX; p++)
        #pragma unroll
        for (int j = 0; j < NP; j++) acc[p][j] = pack2(sb[2*j], sb[2*j+1]);

    const float* inp = in + (size_t)n*CIN*HIN*WIN;
    const int ix0 = xb*S - P;
    #pragma unroll 1
    for (int ci = 0; ci < CIN; ci++) {
        #pragma unroll
        for (int ky = 0; ky < K; ky++) {
            int iy = oy*S - P + ky;
            if (iy < 0 || iy >= HIN) continue;
            const float* row = inp + (size_t)ci*HIN*WIN + (size_t)iy*WIN;
            u64 v2[IW];
            #pragma unroll
            for (int j = 0; j < IW; j++) {
                int ix = ix0 + j;
                v2[j] = bcast2((ix >= 0 && ix < WIN) ? __ldg(row + ix) : 0.f);
            }
            #pragma unroll
            for (int kx = 0; kx < K; kx++) {
                const float* wpp = &sw[((ci*K+ky)*K+kx)*CGP];
                #pragma unroll
                for (int j = 0; j < NP; j += 2) {
                    ulonglong2 wq = *reinterpret_cast<const ulonglong2*>(wpp + 2*j);
                    #pragma unroll
                    for (int p = 0; p < PX; p++) {
                        fma2(acc[p][j],   v2[p*S+kx], wq.x);
                        fma2(acc[p][j+1], v2[p*S+kx], wq.y);
                    }
                }
            }
        }
    }
    float* op = out + ((size_t)n*COUT + co0)*HOUT*WOUT + (size_t)oy*WOUT + xb;
    #pragma unroll
    for (int j = 0; j < CG/2; j++)
        #pragma unroll
        for (int p = 0; p < PX; p++) {
            float2 a = unpack2(acc[p][j]);
            if (RELU) { a.x = fmaxf(a.x, 0.f); a.y = fmaxf(a.y, 0.f); }
            op[(size_t)(2*j)  *HOUT*WOUT + p] = a.x;
            op[(size_t)(2*j+1)*HOUT*WOUT + p] = a.y;
        }
}

// ---------------- legacy per-pixel conv (tiny tail kernels) ----------------
template<int CIN,int COUT,int K,int S,int P,int HIN,int WIN,bool RELU>
__global__ __launch_bounds__(128) void conv_k(
    const float* __restrict__ in, const float* __restrict__ w,
    const float* __restrict__ bias, float* __restrict__ out)
{
    constexpr int HOUT = (HIN + 2*P - K)/S + 1;
    constexpr int WOUT = (WIN + 2*P - K)/S + 1;
    constexpr int COUTP = (COUT + 3) & ~3;
    extern __shared__ float sw[];
    float* sb = sw + CIN*K*K*COUTP;
    for (int i = threadIdx.x; i < CIN*K*K*COUTP; i += blockDim.x) {
        int co = i % COUTP; int r = i / COUTP;
        sw[i] = (co < COUT) ? w[co*CIN*K*K + r] : 0.f;
    }
    for (int i = threadIdx.x; i < COUTP; i += blockDim.x)
        sb[i] = (i < COUT) ? bias[i] : 0.f;
    __syncthreads();

    int idx = blockIdx.x*blockDim.x + threadIdx.x;
    if (idx >= NB*HOUT*WOUT) return;
    int ox = idx % WOUT; int oy = (idx/WOUT) % HOUT; int n = idx/(WOUT*HOUT);

    float acc[COUTP];
    #pragma unroll
    for (int c = 0; c < COUTP; c++) acc[c] = sb[c];

    const float* inp = in + (size_t)n*CIN*HIN*WIN;
    #pragma unroll 1
    for (int ci = 0; ci < CIN; ci++) {
        #pragma unroll
        for (int ky = 0; ky < K; ky++) {
            int iy = oy*S - P + ky;
            if (iy < 0 || iy >= HIN) continue;
            #pragma unroll
            for (int kx = 0; kx < K; kx++) {
                int ix = ox*S - P + kx;
                if (ix < 0 || ix >= WIN) continue;
                float v = __ldg(&inp[(size_t)ci*HIN*WIN + (size_t)iy*WIN + ix]);
                const float* wpp = &sw[((ci*K+ky)*K+kx)*COUTP];
                #pragma unroll
                for (int co = 0; co < COUTP; co += 4) {
                    float4 w4 = *reinterpret_cast<const float4*>(wpp + co);
                    acc[co+0] = fmaf(v, w4.x, acc[co+0]);
                    acc[co+1] = fmaf(v, w4.y, acc[co+1]);
                    acc[co+2] = fmaf(v, w4.z, acc[co+2]);
                    acc[co+3] = fmaf(v, w4.w, acc[co+3]);
                }
            }
        }
    }
    float* op = out + ((size_t)n*COUT*HOUT + (size_t)oy)*WOUT + ox;
    #pragma unroll
    for (int co = 0; co < COUT; co++) {
        float v = acc[co];
        if (RELU) v = fmaxf(v, 0.f);
        op[(size_t)co*HOUT*WOUT] = v;
    }
}

// ---------------- conv7: 1x1, 8->1 over 4x4 -> blur[n][16] -----------------
__global__ void conv7_k(const float* __restrict__ t6, const float* __restrict__ w,
                        const float* __restrict__ b, float* __restrict__ blur)
{
    int i = blockIdx.x*blockDim.x + threadIdx.x;
    if (i >= NB*16) return;
    int n = i >> 4, p = i & 15;
    float acc = b[0];
    #pragma unroll
    for (int ci = 0; ci < 8; ci++)
        acc = fmaf(t6[(n*8 + ci)*16 + p], w[ci], acc);
    blur[i] = fmaxf(acc, 0.f);
}

// ---------------- blur precompute ------------------------------------------
__global__ void blurpre_k(const float* __restrict__ blur, const float* __restrict__ r1w,
                          const float* __restrict__ pw, float* __restrict__ contrib,
                          float* __restrict__ pwblur)
{
    int n = blockIdx.x;
    int co = threadIdx.x;
    float s[9];
    #pragma unroll
    for (int q = 0; q < 9; q++) s[q] = 0.f;
    for (int ci = 0; ci < 16; ci++) {
        float bv = blur[n*16 + ci];
        const float* tw = r1w + ((size_t)co*48 + ci)*9;
        float t[9];
        #pragma unroll
        for (int q = 0; q < 9; q++) t[q] = tw[q];
        float cs[3][3];
        #pragma unroll
        for (int ky = 0; ky < 3; ky++) {
            cs[ky][0] = t[ky*3+1] + t[ky*3+2];
            cs[ky][1] = t[ky*3+0] + t[ky*3+1] + t[ky*3+2];
            cs[ky][2] = t[ky*3+0] + t[ky*3+1];
        }
        #pragma unroll
        for (int vx = 0; vx < 3; vx++) {
            float r0 = cs[1][vx] + cs[2][vx];
            float r1v = cs[0][vx] + cs[1][vx] + cs[2][vx];
            float r2 = cs[0][vx] + cs[1][vx];
            s[0*3+vx] = fmaf(bv, r0,  s[0*3+vx]);
            s[1*3+vx] = fmaf(bv, r1v, s[1*3+vx]);
            s[2*3+vx] = fmaf(bv, r2,  s[2*3+vx]);
        }
    }
    #pragma unroll
    for (int q = 0; q < 9; q++) contrib[((size_t)n*9 + q)*64 + co] = s[q];

    if (co < 20) {
        float q = 0.f;
        for (int ci = 0; ci < 16; ci++)
            q = fmaf(blur[n*16 + ci], pw[co*48 + ci], q);
        pwblur[n*20 + co] = q;
    }
}

// ---------------- BatchNorm stats ------------------------------------------
template<int C, int HW>
__global__ void bn_part_k(const float* __restrict__ x, float* __restrict__ part)
{
    int c = blockIdx.x;
    float s = 0.f, s2 = 0.f;
    constexpr int HW4 = HW/4;
    const int per = NB*HW4;
    for (int i = blockIdx.y*blockDim.x + threadIdx.x; i < per; i += gridDim.y*blockDim.x) {
        int n = i / HW4; int j = i - n*HW4;
        float4 v = *reinterpret_cast<const float4*>(&x[((size_t)n*C + c)*HW + j*4]);
        s  += (v.x + v.y) + (v.z + v.w);
        s2 += (v.x*v.x + v.y*v.y) + (v.z*v.z + v.w*v.w);
    }
    __shared__ float rs[256], rs2[256];
    rs[threadIdx.x] = s; rs2[threadIdx.x] = s2;
    __syncthreads();
    for (int o = blockDim.x/2; o > 0; o >>= 1) {
        if (threadIdx.x < o) {
            rs[threadIdx.x]  += rs[threadIdx.x + o];
            rs2[threadIdx.x] += rs2[threadIdx.x + o];
        }
        __syncthreads();
    }
    if (threadIdx.x == 0) {
        part[c*32 + blockIdx.y]        = rs[0];
        part[C*32 + c*32 + blockIdx.y] = rs2[0];
    }
}

template<int C, int HW>
__global__ void bn_fin_k(const float* __restrict__ part, const float* __restrict__ g,
                         const float* __restrict__ be, float* __restrict__ scale,
                         float* __restrict__ shift)
{
    int c = threadIdx.x;
    if (c >= C) return;
    float s = 0.f, s2 = 0.f;
    for (int b = 0; b < 32; b++) { s += part[c*32 + b]; s2 += part[C*32 + c*32 + b]; }
    const float cnt = (float)NB * (float)HW;
    float mu  = s / cnt;
    float var = s2 / cnt - mu*mu;
    float sc  = g[c] * rsqrtf(var + 1e-5f);
    scale[c] = sc;
    shift[c] = be[c] - mu*sc;
}

// ---------------- bn2 apply + pointwise(ds) + pwblur residual --------------
__global__ __launch_bounds__(128) void bn2pw_k(
    float* __restrict__ r2, const float* __restrict__ pwblur,
    const float* __restrict__ ds, const float* __restrict__ pw,
    const float* __restrict__ pb, const float* __restrict__ scale,
    const float* __restrict__ shift)
{
    __shared__ float sw[32*20];
    __shared__ float sb[20], ssc[20], ssh[20];
    for (int i = threadIdx.x; i < 32*20; i += blockDim.x) {
        int co = i % 20, ci = i / 20;
        sw[i] = pw[co*48 + 16 + ci];
    }
    if (threadIdx.x < 20) {
        sb[threadIdx.x]  = pb[threadIdx.x];
        ssc[threadIdx.x] = scale[threadIdx.x];
        ssh[threadIdx.x] = shift[threadIdx.x];
    }
    __syncthreads();

    int idx = blockIdx.x*blockDim.x + threadIdx.x;
    if (idx >= NB*4096) return;
    int p = idx & 4095; int n = idx >> 12;

    u64 acc[10];
    const float* pbl = &pwblur[n*20];
    #pragma unroll
    for (int j = 0; j < 10; j++)
        acc[j] = pack2(sb[2*j] + pbl[2*j], sb[2*j+1] + pbl[2*j+1]);

    const float* dsp = ds + (size_t)n*32*4096 + p;
    #pragma unroll 1
    for (int ci = 0; ci < 32; ci++) {
        u64 v = bcast2(__ldg(&dsp[(size_t)ci*4096]));
        const float* wpp = &sw[ci*20];
        #pragma unroll
        for (int j = 0; j < 10; j += 2) {
            ulonglong2 wq = *reinterpret_cast<const ulonglong2*>(wpp + 2*j);
            fma2(acc[j],   v, wq.x);
            fma2(acc[j+1], v, wq.y);
        }
    }
    float* rp = r2 + (size_t)n*20*4096 + p;
    #pragma unroll
    for (int j = 0; j < 10; j++) {
        float2 a = unpack2(acc[j]);
        int c = 2*j;
        rp[(size_t)c    *4096] = fmaf(rp[(size_t)c    *4096], ssc[c],   ssh[c])   + a.x;
        rp[(size_t)(c+1)*4096] = fmaf(rp[(size_t)(c+1)*4096], ssc[c+1], ssh[c+1]) + a.y;
    }
}

// ---------------- final: u2 1x1 + relu + pixel_shuffle(4) + sigmoid --------
__global__ __launch_bounds__(128) void final_k(
    const float* __restrict__ u1, const float* __restrict__ w,
    const float* __restrict__ b, float* __restrict__ out)
{
    __shared__ float sw[30*16];
    __shared__ float sb[16];
    for (int i = threadIdx.x; i < 30*16; i += blockDim.x) {
        int co = i % 16, ci = i / 16;
        sw[i] = w[co*30 + ci];
    }
    if (threadIdx.x < 16) sb[threadIdx.x] = b[threadIdx.x];
    __syncthreads();

    int idx = blockIdx.x*blockDim.x + threadIdx.x;
    if (idx >= NB*4096) return;
    int wq = idx & 63; int h = (idx >> 6) & 63; int n = idx >> 12;

    u64 acc[8];
    #pragma unroll
    for (int j = 0; j < 8; j++) acc[j] = pack2(sb[2*j], sb[2*j+1]);

    const float* up = u1 + (size_t)n*30*4096 + h*64 + wq;
    #pragma unroll 1
    for (int ci = 0; ci < 30; ci++) {
        u64 v = bcast2(__ldg(&up[(size_t)ci*4096]));
        const float* wpp = &sw[ci*16];
        #pragma unroll
        for (int j = 0; j < 8; j += 2) {
            ulonglong2 wqv = *reinterpret_cast<const ulonglong2*>(wpp + 2*j);
            fma2(acc[j],   v, wqv.x);
            fma2(acc[j+1], v, wqv.y);
        }
    }
    float* op = out + (size_t)n*65536;
    #pragma unroll
    for (int j = 0; j < 8; j++) {
        float2 a = unpack2(acc[j]);
        #pragma unroll
        for (int h2 = 0; h2 < 2; h2++) {
            int c = 2*j + h2;
            float v = fmaxf(h2 ? a.y : a.x, 0.f);
            v = 1.f / (1.f + expf(-v));
            op[(h*4 + (c >> 2))*256 + wq*4 + (c & 3)] = v;
        }
    }
}

// ---------------------------------------------------------------------------
extern "C" void kernel_launch(void* const* d_in, const int* in_sizes, int n_in,
                              void* d_out, int out_size)
{
    const float* x1  = (const float*)d_in[0];
    const float* c1w = (const float*)d_in[1];  const float* c1b = (const float*)d_in[2];
    const float* c2w = (const float*)d_in[3];  const float* c2b = (const float*)d_in[4];
    const float* c3w = (const float*)d_in[5];  const float* c3b = (const float*)d_in[6];
    const float* c4w = (const float*)d_in[7];  const float* c4b = (const float*)d_in[8];
    const float* c5w = (const float*)d_in[9];  const float* c5b = (const float*)d_in[10];
    const float* c6w = (const float*)d_in[11]; const float* c6b = (const float*)d_in[12];
    const float* c7w = (const float*)d_in[13]; const float* c7b = (const float*)d_in[14];
    const float* r1w = (const float*)d_in[15]; const float* r1b = (const float*)d_in[16];
    const float* g1  = (const float*)d_in[17]; const float* be1 = (const float*)d_in[18];
    const float* r2w = (const float*)d_in[19]; const float* r2b = (const float*)d_in[20];
    const float* g2  = (const float*)d_in[21]; const float* be2 = (const float*)d_in[22];
    const float* pw  = (const float*)d_in[23]; const float* pb  = (const float*)d_in[24];
    const float* u1w = (const float*)d_in[25]; const float* u1b = (const float*)d_in[26];
    const float* u2w = (const float*)d_in[27]; const float* u2b = (const float*)d_in[28];

    float *t1,*ds,*t3,*t4,*t5,*t6,*blur,*r1,*r2,*u1,*part,*scale,*shift,*contrib,*pwblur;
    cudaGetSymbolAddress((void**)&t1,     g_t1);
    cudaGetSymbolAddress((void**)&ds,     g_ds);
    cudaGetSymbolAddress((void**)&t3,     g_t3);
    cudaGetSymbolAddress((void**)&t4,     g_t4);
    cudaGetSymbolAddress((void**)&t5,     g_t5);
    cudaGetSymbolAddress((void**)&t6,     g_t6);
    cudaGetSymbolAddress((void**)&blur,   g_blur);
    cudaGetSymbolAddress((void**)&r1,     g_r1);
    cudaGetSymbolAddress((void**)&r2,     g_r2);
    cudaGetSymbolAddress((void**)&u1,     g_u1);
    cudaGetSymbolAddress((void**)&part,   g_part);
    cudaGetSymbolAddress((void**)&scale,  g_scale);
    cudaGetSymbolAddress((void**)&shift,  g_shift);
    cudaGetSymbolAddress((void**)&contrib,g_contrib);
    cudaGetSymbolAddress((void**)&pwblur, g_pwblur);

    u64 *wp_r1, *wp_r2, *wp_u1, *wp_c2;
    cudaGetSymbolAddress((void**)&wp_r1, g_wp_r1);
    cudaGetSymbolAddress((void**)&wp_r2, g_wp_r2);
    cudaGetSymbolAddress((void**)&wp_u1, g_wp_u1);
    cudaGetSymbolAddress((void**)&wp_c2, g_wp_c2);

    auto smemL = [](int cin, int coutp, int k) { return (size_t)(cin*k*k*coutp + coutp)*4; };
    auto smemP = [](int cin, int cgp, int k) { return (size_t)(cin*k*k*cgp + cgp)*4; };
    auto smemTC = [](int cinc, int coutp, int kp, int kcp) {
        return (size_t)(cinc*6*68)*4 + (size_t)coutp*pad64(kp/2)*8 + (size_t)(kcp/8)*4*8;
    };
    size_t sm_r1 = smemTC(16, 64, 2*ceil8i(16*9), ceil8i(16*9));
    size_t sm_r2 = smemTC(16, 24, 4*ceil8i(16*9), ceil8i(16*9));
    size_t sm_u1 = smemTC(20, 32, 1*ceil8i(20*9), ceil8i(20*9));
    size_t sm_c2 = (size_t)(8*11*132)*4 + (size_t)32*100*8 + 100*8;

    cudaFuncSetAttribute((const void*)conv_k<20,30,5,2,2,16,16,true>,
                         cudaFuncAttributeMaxDynamicSharedMemorySize, (int)smemL(20,32,5));
    cudaFuncSetAttribute((const void*)tc_conv3_k<32,16,48,16,64,64,false,false,true>,
                         cudaFuncAttributeMaxDynamicSharedMemorySize, (int)sm_r1);
    cudaFuncSetAttribute((const void*)tc_conv3_k<64,16,64,0,20,24,false,true,false>,
                         cudaFuncAttributeMaxDynamicSharedMemorySize, (int)sm_r2);
    cudaFuncSetAttribute((const void*)tc_conv3_k<20,20,20,0,30,32,true,false,false>,
                         cudaFuncAttributeMaxDynamicSharedMemorySize, (int)sm_u1);
    cudaFuncSetAttribute((const void*)tc_conv2_k,
                         cudaFuncAttributeMaxDynamicSharedMemorySize, (int)sm_c2);

    // ---------------- weight pre-pack (cheap, once per launch) -------------
    pack3_k<32,16,48,16,64,64><<<(64*148+127)/128,128>>>(r1w, wp_r1);
    pack3_k<64,16,64,0,20,24><<<(24*292+127)/128,128>>>(r2w, wp_r2);
    pack3_k<20,20,20,0,30,32><<<(32*100+127)/128,128>>>(u1w, wp_u1);
    pack2p_k<<<(32*100+127)/128,128>>>(c2w, wp_c2);

    // ---------------- encoder ----------------
    convp_k<1,8,8,4,3,2,1,256,256,true>
        <<<(NB*128*32+127)/128,128, smemP(1,8,3)>>>(x1, c1w, c1b, t1);
    tc_conv2_k<<<dim3(16,NB),512, sm_c2>>>(t1, wp_c2, c2b, ds);
    conv_k<32,4,3,2,1, 64, 64,false><<<(NB*32*32+127)/128,128, smemL(32,4,3)>>> (ds, c3w, c3b, t3);
    conv_k<4,20,3,2,1, 32, 32,true><<<(NB*16*16+127)/128,128, smemL(4,20,3)>>>  (t3, c4w, c4b, t4);
    conv_k<20,30,5,2,2,16, 16,true><<<(NB*8*8  +127)/128,128, smemL(20,32,5)>>> (t4, c5w, c5b, t5);
    conv_k<30, 8,3,2,1,  8,  8,true><<<(NB*4*4 +127)/128,128, smemL(30,8,3)>>>  (t5, c6w, c6b, t6);
    conv7_k<<<(NB*16+127)/128,128>>>(t6, c7w, c7b, blur);

    blurpre_k<<<NB,64>>>(blur, r1w, pw, contrib, pwblur);

    // ---------------- residual block with training-mode BN ----------------
    tc_conv3_k<32,16,48,16,64,64,false,false,true>
        <<<dim3(16,NB),512, sm_r1>>>(ds, wp_r1, r1b, nullptr, nullptr, contrib, r1);
    { dim3 g(64,32); bn_part_k<64,4096><<<g,256>>>(r1, part); }
    bn_fin_k<64,4096><<<1,64>>>(part, g1, be1, scale, shift);

    tc_conv3_k<64,16,64,0,20,24,false,true,false>
        <<<dim3(16,NB),512, sm_r2>>>(r1, wp_r2, r2b, scale, shift, nullptr, r2);
    { dim3 g(20,32); bn_part_k<20,4096><<<g,256>>>(r2, part); }
    bn_fin_k<20,4096><<<1,32>>>(part, g2, be2, scale, shift);
    bn2pw_k<<<(NB*4096+127)/128,128>>>(r2, pwblur, ds, pw, pb, scale, shift);

    // ---------------- upsample head ----------------
    tc_conv3_k<20,20,20,0,30,32,true,false,false>
        <<<dim3(16,NB),512, sm_u1>>>(r2, wp_u1, u1b, nullptr, nullptr, nullptr, u1);
    final_k<<<(NB*4096+127)/128,128>>>(u1, u2w, u2b, (float*)d_out);
}

// round 11
// speedup vs baseline: 3.2316x; 1.0764x over previous
#include <cuda_runtime.h>
#include <cuda_bf16.h>
#include <math.h>

#define NB 128

// ---------------- scratch (device globals; no allocation allowed) ----------
__device__ float g_t1[(size_t)NB*8*128*128];
__device__ float g_ds[(size_t)NB*32*64*64];
__device__ float g_t3[(size_t)NB*4*32*32];
__device__ float g_r1[(size_t)NB*64*64*64];
__device__ float g_r2[(size_t)NB*20*64*64];
__device__ float g_u1[(size_t)NB*30*64*64];
__device__ float g_part[2*64*2048];            // per-block BN partials
__device__ float g_scale[64];
__device__ float g_shift[64];
__device__ float g_contrib[NB*9*64];
__device__ float g_pwblur[NB*20];

typedef unsigned long long u64;
// pre-packed tf32 weight buffers (filled once per launch)
__device__ __align__(16) u64 g_wp_r1[64*148];
__device__ __align__(16) u64 g_wp_r2[24*292];
__device__ __align__(16) u64 g_wp_u1[32*100];
__device__ __align__(16) u64 g_wp_c2[32*100];
__device__ __align__(16) u64 g_wp_c1[8*20];

// ---------------- helpers ----------------
static __device__ __forceinline__ u64 pack2(float x, float y) {
    u64 r; asm("mov.b64 %0, {%1, %2};" : "=l"(r) : "f"(x), "f"(y)); return r;
}
static __device__ __forceinline__ u64 bcast2(float x) { return pack2(x, x); }
static __device__ __forceinline__ void fma2(u64& d, u64 a, u64 b) {
    asm("fma.rn.f32x2 %0, %1, %2, %0;" : "+l"(d) : "l"(a), "l"(b));
}
static __device__ __forceinline__ float2 unpack2(u64 v) {
    float2 r; asm("mov.b64 {%0, %1}, %2;" : "=f"(r.x), "=f"(r.y) : "l"(v)); return r;
}
static __device__ __forceinline__ unsigned to_tf32(float v) {
    unsigned u; asm("cvt.rna.tf32.f32 %0, %1;" : "=r"(u) : "f"(v)); return u;
}
static __device__ __forceinline__ u64 packtf2(float x, float y) {
    return (u64)to_tf32(x) | ((u64)to_tf32(y) << 32);
}
static __device__ __forceinline__ void mma_tf32(
    float* acc, unsigned a0, unsigned a1, unsigned a2, unsigned a3,
    unsigned b0, unsigned b1)
{
    asm volatile(
      "mma.sync.aligned.m16n8k8.row.col.f32.tf32.tf32.f32 "
      "{%0,%1,%2,%3}, {%4,%5,%6,%7}, {%8,%9}, {%0,%1,%2,%3};"
      : "+f"(acc[0]), "+f"(acc[1]), "+f"(acc[2]), "+f"(acc[3])
      : "r"(a0), "r"(a1), "r"(a2), "r"(a3), "r"(b0), "r"(b1));
}

__host__ __device__ constexpr int ceil8i(int x) { return (x + 7) & ~7; }
__host__ __device__ constexpr int pad64(int x) { return x + ((4 - (x & 15)) + 16) % 16; }

// =====================================================================
// Weight pre-pack kernels
// =====================================================================
template<int CIN,int CINC,int WCIN,int CIOFF,int COUT,int COUTP>
__global__ void pack3_k(const float* __restrict__ w, u64* __restrict__ wp)
{
    constexpr int KC  = CINC*9;
    constexpr int KCP = ceil8i(KC);
    constexpr int KP  = (CIN/CINC)*KCP;
    constexpr int P64 = pad64(KP/2);
    int idx = blockIdx.x*blockDim.x + threadIdx.x;
    if (idx >= COUTP*P64) return;
    int co = idx / P64; int j = idx - co*P64;
    u64 val = 0;
    if (j < (KP/8)*4) {
        int kgrp = j >> 2, tg = j & 3;
        int k0 = kgrp*8 + tg, k1 = k0 + 4;
        int chunk = k0 / KCP;
        int kin0 = k0 - chunk*KCP, kin1 = k1 - chunk*KCP;
        float v0 = 0.f, v1 = 0.f;
        if (co < COUT && kin0 < KC)
            v0 = w[((size_t)co*WCIN + CIOFF + chunk*CINC + kin0/9)*9 + kin0%9];
        if (co < COUT && kin1 < KC)
            v1 = w[((size_t)co*WCIN + CIOFF + chunk*CINC + kin1/9)*9 + kin1%9];
        val = packtf2(v0, v1);
    }
    wp[idx] = val;
}

__global__ void pack2p_k(const float* __restrict__ w, u64* __restrict__ wp)
{
    int idx = blockIdx.x*blockDim.x + threadIdx.x;   // 32*100
    if (idx >= 32*100) return;
    int co = idx / 100; int j = idx - co*100;
    int kgrp = j >> 2, tg = j & 3;
    int k0 = kgrp*8 + tg;
    wp[idx] = packtf2(w[(size_t)co*200 + k0], w[(size_t)co*200 + k0 + 4]);
}

// =====================================================================
// Tensor-core 3x3 s1 p1 conv on 64x64 images. Optional fused input BN
// (BNIN), blur contrib (CONTRIB), and per-block BN stats (STATS).
// =====================================================================
template<int CIN,int CINC,int WCIN,int CIOFF,int COUT,int COUTP,bool RELU,bool BNIN,bool CONTRIB,bool STATS>
__global__ __launch_bounds__(512) void tc_conv3_k(
    const float* __restrict__ in, const u64* __restrict__ wp,
    const float* __restrict__ bias, const float* __restrict__ bnsc,
    const float* __restrict__ bnsh, const float* __restrict__ contrib,
    float* __restrict__ out, float* __restrict__ bnpart)
{
    constexpr int CHUNKS = CIN / CINC;
    static_assert(CIN % CINC == 0 && COUTP % 8 == 0, "");
    constexpr int KC   = CINC*9;
    constexpr int KCP  = ceil8i(KC);
    constexpr int KP   = CHUNKS*KCP;
    constexpr int P64  = pad64(KP/2);
    constexpr int IN_S = (CINC*6*68 + 3) & ~3;   // 16B-aligned boundary
    constexpr int NT   = COUTP/8;
    constexpr int NKS  = KCP/8;
    extern __shared__ unsigned smu[];
    unsigned* in_s = smu;
    u64*  w2_s = (u64*)(smu + IN_S);                   // COUTP*P64
    int2* lut_s = (int2*)(w2_s + (size_t)COUTP*P64);   // NKS*4
    float* st_s = (float*)(lut_s + NKS*4);             // 16*COUTP*2 (STATS)

    const int n   = blockIdx.y;
    const int oy0 = blockIdx.x * 4;
    const int tid = threadIdx.x;
    const int lane = tid & 31;
    const int mt  = tid >> 5;
    const int tg  = lane & 3;
    const int gid = lane >> 2;

    {
        ulonglong2* d = (ulonglong2*)w2_s;
        const ulonglong2* s = (const ulonglong2*)wp;
        for (int i = tid; i < COUTP*P64/2; i += 512) d[i] = s[i];
    }
    for (int j = tid; j < NKS*4; j += 512) {
        int ks = j >> 2, tg_ = j & 3;
        int k0 = ks*8 + tg_, k1 = k0 + 4;
        int t0 = 0, t1 = 0;
        if (k0 < KC) { int c = k0/9, tp = k0%9; t0 = (c*6 + tp/3)*68 + tp%3; }
        if (k1 < KC) { int c = k1/9, tp = k1%9; t1 = (c*6 + tp/3)*68 + tp%3; }
        lut_s[j] = make_int2(t0, t1);
    }

    float acc[NT][4];
    #pragma unroll
    for (int nt = 0; nt < NT; nt++)
        #pragma unroll
        for (int e = 0; e < 4; e++) acc[nt][e] = 0.f;

    const int base = (mt >> 2)*68 + (mt & 3)*16 + gid;

    for (int chunk = 0; chunk < CHUNKS; chunk++) {
        __syncthreads();
        const int ci0 = chunk*CINC;
        for (int idx = tid; idx < CINC*6*66; idx += 512) {
            int ci = idx / (6*66); int rem = idx - ci*(6*66);
            int ry = rem / 66; int cx = rem - ry*66;
            int iy = oy0 - 1 + ry; int ix = cx - 1;
            float val = 0.f;
            if ((unsigned)iy < 64u && (unsigned)ix < 64u) {
                val = in[((size_t)n*CIN + ci0 + ci)*4096 + iy*64 + ix];
                if (BNIN) val = fmaxf(fmaf(val, bnsc[ci0+ci], bnsh[ci0+ci]), 0.f);
            }
            in_s[(ci*6 + ry)*68 + cx] = to_tf32(val);
        }
        __syncthreads();

        const u64* wc = w2_s + chunk*NKS*4 + tg + (size_t)gid*P64;
        #pragma unroll
        for (int ks = 0; ks < NKS; ks++) {
            int2 tt = lut_s[ks*4 + tg];
            unsigned a0 = in_s[tt.x + base];
            unsigned a1 = in_s[tt.x + base + 8];
            unsigned a2 = in_s[tt.y + base];
            unsigned a3 = in_s[tt.y + base + 8];
            #pragma unroll
            for (int nt = 0; nt < NT; nt++) {
                u64 bb = wc[ks*4 + (size_t)(nt*8)*P64];
                mma_tf32(acc[nt], a0, a1, a2, a3, (unsigned)bb, (unsigned)(bb >> 32));
            }
        }
    }

    // ---- epilogue ----
    const int oy = oy0 + (mt >> 2);
    const int x0 = (mt & 3)*16;
    const int vy = (oy == 0) ? 0 : ((oy == 63) ? 2 : 1);
    float sacc[NT][2], s2acc[NT][2];
    if (STATS) {
        #pragma unroll
        for (int nt = 0; nt < NT; nt++) { sacc[nt][0]=sacc[nt][1]=0.f; s2acc[nt][0]=s2acc[nt][1]=0.f; }
    }
    #pragma unroll
    for (int half = 0; half < 2; half++) {
        int x = x0 + gid + half*8;
        int vx = (x == 0) ? 0 : ((x == 63) ? 2 : 1);
        const float* cp = CONTRIB ? &contrib[((size_t)n*9 + vy*3 + vx)*64] : nullptr;
        float* op = out + (size_t)n*COUT*4096 + (size_t)oy*64 + x;
        #pragma unroll
        for (int nt = 0; nt < NT; nt++) {
            #pragma unroll
            for (int e = 0; e < 2; e++) {
                int co = nt*8 + 2*tg + e;
                float bv = (co < COUT) ? bias[co] : 0.f;
                float v = acc[nt][half*2 + e] + bv;
                if (CONTRIB) v += (co < COUT) ? cp[co] : 0.f;
                if (RELU) v = fmaxf(v, 0.f);
                if (co < COUT) op[(size_t)co*4096] = v;
                if (STATS) { sacc[nt][e] += v; s2acc[nt][e] += v*v; }
            }
        }
    }
    if (STATS) {
        #pragma unroll
        for (int nt = 0; nt < NT; nt++) {
            #pragma unroll
            for (int e = 0; e < 2; e++) {
                float s = sacc[nt][e], s2 = s2acc[nt][e];
                s  += __shfl_xor_sync(0xffffffffu, s, 4);
                s2 += __shfl_xor_sync(0xffffffffu, s2, 4);
                s  += __shfl_xor_sync(0xffffffffu, s, 8);
                s2 += __shfl_xor_sync(0xffffffffu, s2, 8);
                s  += __shfl_xor_sync(0xffffffffu, s, 16);
                s2 += __shfl_xor_sync(0xffffffffu, s2, 16);
                if (gid == 0) {
                    int co = nt*8 + 2*tg + e;
                    st_s[(mt*COUTP + co)*2 + 0] = s;
                    st_s[(mt*COUTP + co)*2 + 1] = s2;
                }
            }
        }
        __syncthreads();
        if (tid < COUT) {
            float S = 0.f, S2 = 0.f;
            #pragma unroll
            for (int wq = 0; wq < 16; wq++) {
                S  += st_s[(wq*COUTP + tid)*2 + 0];
                S2 += st_s[(wq*COUTP + tid)*2 + 1];
            }
            int blk = blockIdx.y*gridDim.x + blockIdx.x;   // n*16 + oy0/4, < 2048
            bnpart[(size_t)tid*2048 + blk] = S;
            bnpart[(size_t)COUT*2048 + (size_t)tid*2048 + blk] = S2;
        }
    }
}

// =====================================================================
// Tensor-core conv2: 8->32, k5, s2, p2, 128->64.
// =====================================================================
__global__ __launch_bounds__(512) void tc_conv2_k(
    const float* __restrict__ in, const u64* __restrict__ wp,
    const float* __restrict__ bias, float* __restrict__ out)
{
    constexpr int IN_S = 8*11*132;   // 11616 words, 16B-aligned
    extern __shared__ unsigned smu[];
    unsigned* in_s = smu;
    u64*  w2_s = (u64*)(smu + IN_S);     // 32*100
    int2* lut_s = (int2*)(w2_s + 32*100);// 100

    const int n   = blockIdx.y;
    const int oy0 = blockIdx.x * 4;
    const int tid = threadIdx.x;
    const int lane = tid & 31;
    const int mt  = tid >> 5;
    const int tg  = lane & 3;
    const int gid = lane >> 2;

    {
        ulonglong2* d = (ulonglong2*)w2_s;
        const ulonglong2* s = (const ulonglong2*)wp;
        for (int i = tid; i < 32*100/2; i += 512) d[i] = s[i];
    }
    for (int j = tid; j < 100; j += 512) {
        int ks = j >> 2, tg_ = j & 3;
        int k0 = ks*8 + tg_, k1 = k0 + 4;
        int c0 = k0/25, r0 = k0%25, c1 = k1/25, r1 = k1%25;
        lut_s[j] = make_int2((c0*11 + r0/5)*132 + r0%5,
                             (c1*11 + r1/5)*132 + r1%5);
    }
    for (int idx = tid; idx < 8*11*131; idx += 512) {
        int ci = idx / (11*131); int rem = idx - ci*(11*131);
        int ry = rem / 131; int cx = rem - ry*131;
        int iy = 2*oy0 - 2 + ry; int ix = cx - 2;
        float val = 0.f;
        if ((unsigned)iy < 128u && (unsigned)ix < 128u)
            val = in[((size_t)n*8 + ci)*16384 + iy*128 + ix];
        in_s[(ci*11 + ry)*132 + cx] = to_tf32(val);
    }
    __syncthreads();

    float acc[4][4];
    #pragma unroll
    for (int nt = 0; nt < 4; nt++)
        #pragma unroll
        for (int e = 0; e < 4; e++) acc[nt][e] = 0.f;

    const int base = (mt >> 2)*264 + (mt & 3)*32 + 2*gid;
    const u64* wc = w2_s + tg + (size_t)gid*100;
    #pragma unroll
    for (int ks = 0; ks < 25; ks++) {
        int2 tt = lut_s[ks*4 + tg];
        unsigned a0 = in_s[tt.x + base];
        unsigned a1 = in_s[tt.x + base + 16];
        unsigned a2 = in_s[tt.y + base];
        unsigned a3 = in_s[tt.y + base + 16];
        #pragma unroll
        for (int nt = 0; nt < 4; nt++) {
            u64 bb = wc[ks*4 + (size_t)(nt*8)*100];
            mma_tf32(acc[nt], a0, a1, a2, a3, (unsigned)bb, (unsigned)(bb >> 32));
        }
    }

    const int oy = oy0 + (mt >> 2);
    const int x0 = (mt & 3)*16;
    #pragma unroll
    for (int half = 0; half < 2; half++) {
        int x = x0 + gid + half*8;
        float* op = out + (size_t)n*32*4096 + (size_t)oy*64 + x;
        #pragma unroll
        for (int nt = 0; nt < 4; nt++) {
            #pragma unroll
            for (int e = 0; e < 2; e++) {
                int co = nt*8 + 2*tg + e;
                float v = fmaxf(acc[nt][half*2 + e] + bias[co], 0.f);
                op[(size_t)co*4096] = v;
            }
        }
    }
}

// =====================================================================
// Tensor-core conv1: 1->8, k3, s2, p1, 256->128. Block: 2 out rows x 128.
// =====================================================================
__global__ __launch_bounds__(512) void tc_conv1_k(
    const float* __restrict__ in, const u64* __restrict__ wp,
    const float* __restrict__ bias, float* __restrict__ out)
{
    constexpr int P64 = 20;
    constexpr int IN_RAW = 5*258;                  // 1290
    constexpr int IN_S = (IN_RAW + 3) & ~3;        // 1292 -> 16B-aligned boundary
    extern __shared__ unsigned smu[];
    unsigned* in_s = smu;
    u64*  w2_s = (u64*)(smu + IN_S);     // 8*20
    int2* lut_s = (int2*)(w2_s + 8*20);  // 8

    const int n   = blockIdx.y;
    const int oy0 = blockIdx.x * 2;
    const int tid = threadIdx.x;
    const int lane = tid & 31;
    const int mt  = tid >> 5;
    const int tg  = lane & 3;
    const int gid = lane >> 2;

    if (tid < 80) {
        ((ulonglong2*)w2_s)[tid] = ((const ulonglong2*)wp)[tid];
    }
    if (tid < 8) {
        int ks = tid >> 2, tg_ = tid & 3;
        int k0 = ks*8 + tg_, k1 = k0 + 4;
        int t0 = (k0 < 9) ? (k0/3)*258 + k0%3 : 0;
        int t1 = (k1 < 9) ? (k1/3)*258 + k1%3 : 0;
        lut_s[tid] = make_int2(t0, t1);
    }
    for (int idx = tid; idx < IN_RAW; idx += 512) {
        int ry = idx / 258; int cx = idx - ry*258;
        int iy = 2*oy0 - 1 + ry; int ix = cx - 1;
        float val = 0.f;
        if ((unsigned)iy < 256u && (unsigned)ix < 256u)
            val = in[(size_t)n*65536 + iy*256 + ix];
        in_s[idx] = to_tf32(val);
    }
    __syncthreads();

    float acc[4] = {0.f, 0.f, 0.f, 0.f};
    const int base = (mt >> 3)*516 + ((mt & 7)*16 + gid)*2;
    #pragma unroll
    for (int ks = 0; ks < 2; ks++) {
        int2 tt = lut_s[ks*4 + tg];
        unsigned a0 = in_s[tt.x + base];
        unsigned a1 = in_s[tt.x + base + 16];
        unsigned a2 = in_s[tt.y + base];
        unsigned a3 = in_s[tt.y + base + 16];
        u64 bb = w2_s[ks*4 + tg + (size_t)gid*P64];
        mma_tf32(acc, a0, a1, a2, a3, (unsigned)bb, (unsigned)(bb >> 32));
    }

    const int oy = oy0 + (mt >> 3);
    const int x0 = (mt & 7)*16;
    #pragma unroll
    for (int half = 0; half < 2; half++) {
        int x = x0 + gid + half*8;
        float* op = out + (size_t)n*8*16384 + (size_t)oy*128 + x;
        #pragma unroll
        for (int e = 0; e < 2; e++) {
            int co = 2*tg + e;
            float v = fmaxf(acc[half*2 + e] + bias[co], 0.f);
            op[(size_t)co*16384] = v;
        }
    }
}

// ---------------- legacy per-pixel conv (conv3 only) -----------------------
template<int CIN,int COUT,int K,int S,int P,int HIN,int WIN,bool RELU>
__global__ __launch_bounds__(128) void conv_k(
    const float* __restrict__ in, const float* __restrict__ w,
    const float* __restrict__ bias, float* __restrict__ out)
{
    constexpr int HOUT = (HIN + 2*P - K)/S + 1;
    constexpr int WOUT = (WIN + 2*P - K)/S + 1;
    constexpr int COUTP = (COUT + 3) & ~3;
    extern __shared__ float sw[];
    float* sb = sw + CIN*K*K*COUTP;
    for (int i = threadIdx.x; i < CIN*K*K*COUTP; i += blockDim.x) {
        int co = i % COUTP; int r = i / COUTP;
        sw[i] = (co < COUT) ? w[co*CIN*K*K + r] : 0.f;
    }
    for (int i = threadIdx.x; i < COUTP; i += blockDim.x)
        sb[i] = (i < COUT) ? bias[i] : 0.f;
    __syncthreads();

    int idx = blockIdx.x*blockDim.x + threadIdx.x;
    if (idx >= NB*HOUT*WOUT) return;
    int ox = idx % WOUT; int oy = (idx/WOUT) % HOUT; int n = idx/(WOUT*HOUT);

    float acc[COUTP];
    #pragma unroll
    for (int c = 0; c < COUTP; c++) acc[c] = sb[c];

    const float* inp = in + (size_t)n*CIN*HIN*WIN;
    #pragma unroll 1
    for (int ci = 0; ci < CIN; ci++) {
        #pragma unroll
        for (int ky = 0; ky < K; ky++) {
            int iy = oy*S - P + ky;
            if (iy < 0 || iy >= HIN) continue;
            #pragma unroll
            for (int kx = 0; kx < K; kx++) {
                int ix = ox*S - P + kx;
                if (ix < 0 || ix >= WIN) continue;
                float v = __ldg(&inp[(size_t)ci*HIN*WIN + (size_t)iy*WIN + ix]);
                const float* wpp = &sw[((ci*K+ky)*K+kx)*COUTP];
                #pragma unroll
                for (int co = 0; co < COUTP; co += 4) {
                    float4 w4 = *reinterpret_cast<const float4*>(wpp + co);
                    acc[co+0] = fmaf(v, w4.x, acc[co+0]);
                    acc[co+1] = fmaf(v, w4.y, acc[co+1]);
                    acc[co+2] = fmaf(v, w4.z, acc[co+2]);
                    acc[co+3] = fmaf(v, w4.w, acc[co+3]);
                }
            }
        }
    }
    float* op = out + ((size_t)n*COUT*HOUT + (size_t)oy)*WOUT + ox;
    #pragma unroll
    for (int co = 0; co < COUT; co++) {
        float v = acc[co];
        if (RELU) v = fmaxf(v, 0.f);
        op[(size_t)co*HOUT*WOUT] = v;
    }
}

// =====================================================================
// Fused tail: conv4 -> conv5 -> conv6 -> conv7 -> blur precompute.
// One block per image, 256 threads, all intermediates in smem.
// =====================================================================
__global__ __launch_bounds__(256) void tail_k(
    const float* __restrict__ t3g,
    const float* __restrict__ c4w, const float* __restrict__ c4b,
    const float* __restrict__ c5w, const float* __restrict__ c5b,
    const float* __restrict__ c6w, const float* __restrict__ c6b,
    const float* __restrict__ c7w, const float* __restrict__ c7b,
    const float* __restrict__ r1w, const float* __restrict__ pw,
    float* __restrict__ contrib, float* __restrict__ pwblur)
{
    extern __shared__ float sm[];
    float* t3s = sm;                 // 4096
    float* w4  = t3s + 4096;         // 36*20 = 720
    float* b4  = w4 + 720;           // 20
    float* t4s = b4 + 20;            // 5120
    float* w5  = t4s + 5120;         // 500*32 = 16000
    float* b5  = w5 + 16000;         // 32
    float* t5s = b5 + 32;            // 1920
    float* w6  = t5s + 1920;         // 270*8 = 2160
    float* b6  = w6 + 2160;          // 8
    float* t6s = b6 + 8;             // 128
    float* w7  = t6s + 128;          // 8
    float* b7  = w7 + 8;             // 1
    float* blur_s = b7 + 1;          // 16

    const int n = blockIdx.x;
    const int tid = threadIdx.x;

    for (int i = tid; i < 4096; i += 256) t3s[i] = t3g[(size_t)n*4096 + i];
    for (int i = tid; i < 720; i += 256) { int co = i % 20, r = i / 20; w4[i] = c4w[co*36 + r]; }
    if (tid < 20) b4[tid] = c4b[tid];
    for (int i = tid; i < 16000; i += 256) {
        int co = i & 31, r = i >> 5;
        w5[i] = (co < 30) ? c5w[co*500 + r] : 0.f;
    }
    if (tid < 32) b5[tid] = (tid < 30) ? c5b[tid] : 0.f;
    for (int i = tid; i < 2160; i += 256) { int co = i & 7, r = i >> 3; w6[i] = c6w[co*270 + r]; }
    if (tid < 8) b6[tid] = c6b[tid];
    if (tid < 8) w7[tid] = c7w[tid];
    if (tid == 0) b7[0] = c7b[0];
    __syncthreads();

    // ---- conv4: 4->20, k3 s2 p1, 32->16 ----
    {
        int oy = tid >> 4, ox = tid & 15;
        u64 acc[10];
        #pragma unroll
        for (int j = 0; j < 10; j++) acc[j] = pack2(b4[2*j], b4[2*j+1]);
        #pragma unroll 1
        for (int ci = 0; ci < 4; ci++) {
            #pragma unroll
            for (int ky = 0; ky < 3; ky++) {
                int iy = 2*oy - 1 + ky;
                if ((unsigned)iy >= 32u) continue;
                #pragma unroll
                for (int kx = 0; kx < 3; kx++) {
                    int ix = 2*ox - 1 + kx;
                    if ((unsigned)ix >= 32u) continue;
                    u64 v = bcast2(t3s[ci*1024 + iy*32 + ix]);
                    const float* wr = &w4[((ci*3+ky)*3+kx)*20];
                    #pragma unroll
                    for (int j = 0; j < 10; j += 2) {
                        ulonglong2 wq = *reinterpret_cast<const ulonglong2*>(wr + 2*j);
                        fma2(acc[j],   v, wq.x);
                        fma2(acc[j+1], v, wq.y);
                    }
                }
            }
        }
        #pragma unroll
        for (int j = 0; j < 10; j++) {
            float2 a = unpack2(acc[j]);
            t4s[(2*j)  *256 + tid] = fmaxf(a.x, 0.f);
            t4s[(2*j+1)*256 + tid] = fmaxf(a.y, 0.f);
        }
    }
    __syncthreads();

    // ---- conv5: 20->30, k5 s2 p2, 16->8 ----
    {
        int px = tid & 63, grp = tid >> 6;
        int oy = px >> 3, ox = px & 7;
        u64 acc[4];
        #pragma unroll
        for (int j = 0; j < 4; j++) acc[j] = pack2(b5[grp*8+2*j], b5[grp*8+2*j+1]);
        #pragma unroll 1
        for (int ci = 0; ci < 20; ci++) {
            #pragma unroll
            for (int ky = 0; ky < 5; ky++) {
                int iy = 2*oy - 2 + ky;
                if ((unsigned)iy >= 16u) continue;
                #pragma unroll
                for (int kx = 0; kx < 5; kx++) {
                    int ix = 2*ox - 2 + kx;
                    if ((unsigned)ix >= 16u) continue;
                    u64 v = bcast2(t4s[ci*256 + iy*16 + ix]);
                    const float* wr = &w5[((ci*5+ky)*5+kx)*32 + grp*8];
                    #pragma unroll
                    for (int j = 0; j < 4; j += 2) {
                        ulonglong2 wq = *reinterpret_cast<const ulonglong2*>(wr + 2*j);
                        fma2(acc[j],   v, wq.x);
                        fma2(acc[j+1], v, wq.y);
                    }
                }
            }
        }
        #pragma unroll
        for (int j = 0; j < 4; j++) {
            float2 a = unpack2(acc[j]);
            int c0 = grp*8 + 2*j;
            if (c0   < 30) t5s[(c0)  *64 + px] = fmaxf(a.x, 0.f);
            if (c0+1 < 30) t5s[(c0+1)*64 + px] = fmaxf(a.y, 0.f);
        }
    }
    __syncthreads();

    // ---- conv6: 30->8, k3 s2 p1, 8->4 ----
    if (tid < 16) {
        int oy = tid >> 2, ox = tid & 3;
        u64 acc[4];
        #pragma unroll
        for (int j = 0; j < 4; j++) acc[j] = pack2(b6[2*j], b6[2*j+1]);
        #pragma unroll 1
        for (int ci = 0; ci < 30; ci++) {
            #pragma unroll
            for (int ky = 0; ky < 3; ky++) {
                int iy = 2*oy - 1 + ky;
                if ((unsigned)iy >= 8u) continue;
                #pragma unroll
                for (int kx = 0; kx < 3; kx++) {
                    int ix = 2*ox - 1 + kx;
                    if ((unsigned)ix >= 8u) continue;
                    u64 v = bcast2(t5s[ci*64 + iy*8 + ix]);
                    const float* wr = &w6[((ci*3+ky)*3+kx)*8];
                    #pragma unroll
                    for (int j = 0; j < 4; j += 2) {
                        ulonglong2 wq = *reinterpret_cast<const ulonglong2*>(wr + 2*j);
                        fma2(acc[j],   v, wq.x);
                        fma2(acc[j+1], v, wq.y);
                    }
                }
            }
        }
        #pragma unroll
        for (int j = 0; j < 4; j++) {
            float2 a = unpack2(acc[j]);
            t6s[(2*j)  *16 + tid] = fmaxf(a.x, 0.f);
            t6s[(2*j+1)*16 + tid] = fmaxf(a.y, 0.f);
        }
    }
    __syncthreads();

    // ---- conv7 (1x1, 8->1) + relu -> blur_s[16] ----
    if (tid < 16) {
        float acc = b7[0];
        #pragma unroll
        for (int ci = 0; ci < 8; ci++)
            acc = fmaf(t6s[ci*16 + tid], w7[ci], acc);
        blur_s[tid] = fmaxf(acc, 0.f);
    }
    __syncthreads();

    // ---- blur precompute: contrib (64 threads) + pwblur (20 threads) ----
    if (tid < 64) {
        int co = tid;
        float s[9];
        #pragma unroll
        for (int q = 0; q < 9; q++) s[q] = 0.f;
        for (int ci = 0; ci < 16; ci++) {
            float bv = blur_s[ci];
            const float* tw = r1w + ((size_t)co*48 + ci)*9;
            float t[9];
            #pragma unroll
            for (int q = 0; q < 9; q++) t[q] = tw[q];
            float cs[3][3];
            #pragma unroll
            for (int ky = 0; ky < 3; ky++) {
                cs[ky][0] = t[ky*3+1] + t[ky*3+2];
                cs[ky][1] = t[ky*3+0] + t[ky*3+1] + t[ky*3+2];
                cs[ky][2] = t[ky*3+0] + t[ky*3+1];
            }
            #pragma unroll
            for (int vx = 0; vx < 3; vx++) {
                float r0 = cs[1][vx] + cs[2][vx];
                float r1v = cs[0][vx] + cs[1][vx] + cs[2][vx];
                float r2 = cs[0][vx] + cs[1][vx];
                s[0*3+vx] = fmaf(bv, r0,  s[0*3+vx]);
                s[1*3+vx] = fmaf(bv, r1v, s[1*3+vx]);
                s[2*3+vx] = fmaf(bv, r2,  s[2*3+vx]);
            }
        }
        #pragma unroll
        for (int q = 0; q < 9; q++) contrib[((size_t)n*9 + q)*64 + co] = s[q];
    } else if (tid >= 64 && tid < 84) {
        int co = tid - 64;
        float q = 0.f;
        for (int ci = 0; ci < 16; ci++)
            q = fmaf(blur_s[ci], pw[co*48 + ci], q);
        pwblur[n*20 + co] = q;
    }
}

// ---------------- BN finalize from per-block partials -----------------------
template<int C>
__global__ void bn_fin2_k(const float* __restrict__ part, const float* __restrict__ g,
                          const float* __restrict__ be, float* __restrict__ scale,
                          float* __restrict__ shift)
{
    int c = blockIdx.x;
    __shared__ float rs[256], rs2[256];
    float s = 0.f, s2 = 0.f;
    for (int i = threadIdx.x; i < 2048; i += 256) {
        s  += part[(size_t)c*2048 + i];
        s2 += part[(size_t)C*2048 + (size_t)c*2048 + i];
    }
    rs[threadIdx.x] = s; rs2[threadIdx.x] = s2;
    __syncthreads();
    for (int o = 128; o > 0; o >>= 1) {
        if (threadIdx.x < o) {
            rs[threadIdx.x]  += rs[threadIdx.x + o];
            rs2[threadIdx.x] += rs2[threadIdx.x + o];
        }
        __syncthreads();
    }
    if (threadIdx.x == 0) {
        const float cnt = (float)NB * 4096.f;
        float mu  = rs[0] / cnt;
        float var = rs2[0] / cnt - mu*mu;
        float sc  = g[c] * rsqrtf(var + 1e-5f);
        scale[c] = sc;
        shift[c] = be[c] - mu*sc;
    }
}

// ---------------- bn2 apply + pointwise(ds) + pwblur residual --------------
__global__ __launch_bounds__(128) void bn2pw_k(
    float* __restrict__ r2, const float* __restrict__ pwblur,
    const float* __restrict__ ds, const float* __restrict__ pw,
    const float* __restrict__ pb, const float* __restrict__ scale,
    const float* __restrict__ shift)
{
    __shared__ float sw[32*20];
    __shared__ float sb[20], ssc[20], ssh[20];
    for (int i = threadIdx.x; i < 32*20; i += blockDim.x) {
        int co = i % 20, ci = i / 20;
        sw[i] = pw[co*48 + 16 + ci];
    }
    if (threadIdx.x < 20) {
        sb[threadIdx.x]  = pb[threadIdx.x];
        ssc[threadIdx.x] = scale[threadIdx.x];
        ssh[threadIdx.x] = shift[threadIdx.x];
    }
    __syncthreads();

    int idx = blockIdx.x*blockDim.x + threadIdx.x;
    if (idx >= NB*4096) return;
    int p = idx & 4095; int n = idx >> 12;

    u64 acc[10];
    const float* pbl = &pwblur[n*20];
    #pragma unroll
    for (int j = 0; j < 10; j++)
        acc[j] = pack2(sb[2*j] + pbl[2*j], sb[2*j+1] + pbl[2*j+1]);

    const float* dsp = ds + (size_t)n*32*4096 + p;
    #pragma unroll 1
    for (int ci = 0; ci < 32; ci++) {
        u64 v = bcast2(__ldg(&dsp[(size_t)ci*4096]));
        const float* wpp = &sw[ci*20];
        #pragma unroll
        for (int j = 0; j < 10; j += 2) {
            ulonglong2 wq = *reinterpret_cast<const ulonglong2*>(wpp + 2*j);
            fma2(acc[j],   v, wq.x);
            fma2(acc[j+1], v, wq.y);
        }
    }
    float* rp = r2 + (size_t)n*20*4096 + p;
    #pragma unroll
    for (int j = 0; j < 10; j++) {
        float2 a = unpack2(acc[j]);
        int c = 2*j;
        rp[(size_t)c    *4096] = fmaf(rp[(size_t)c    *4096], ssc[c],   ssh[c])   + a.x;
        rp[(size_t)(c+1)*4096] = fmaf(rp[(size_t)(c+1)*4096], ssc[c+1], ssh[c+1]) + a.y;
    }
}

// ---------------- final: u2 1x1 + relu + pixel_shuffle(4) + sigmoid --------
__global__ __launch_bounds__(128) void final_k(
    const float* __restrict__ u1, const float* __restrict__ w,
    const float* __restrict__ b, float* __restrict__ out)
{
    __shared__ float sw[30*16];
    __shared__ float sb[16];
    for (int i = threadIdx.x; i < 30*16; i += blockDim.x) {
        int co = i % 16, ci = i / 16;
        sw[i] = w[co*30 + ci];
    }
    if (threadIdx.x < 16) sb[threadIdx.x] = b[threadIdx.x];
    __syncthreads();

    int idx = blockIdx.x*blockDim.x + threadIdx.x;
    if (idx >= NB*4096) return;
    int wq = idx & 63; int h = (idx >> 6) & 63; int n = idx >> 12;

    u64 acc[8];
    #pragma unroll
    for (int j = 0; j < 8; j++) acc[j] = pack2(sb[2*j], sb[2*j+1]);

    const float* up = u1 + (size_t)n*30*4096 + h*64 + wq;
    #pragma unroll 1
    for (int ci = 0; ci < 30; ci++) {
        u64 v = bcast2(__ldg(&up[(size_t)ci*4096]));
        const float* wpp = &sw[ci*16];
        #pragma unroll
        for (int j = 0; j < 8; j += 2) {
            ulonglong2 wqv = *reinterpret_cast<const ulonglong2*>(wpp + 2*j);
            fma2(acc[j],   v, wqv.x);
            fma2(acc[j+1], v, wqv.y);
        }
    }
    float* op = out + (size_t)n*65536;
    #pragma unroll
    for (int j = 0; j < 8; j++) {
        float2 a = unpack2(acc[j]);
        #pragma unroll
        for (int h2 = 0; h2 < 2; h2++) {
            int c = 2*j + h2;
            float v = fmaxf(h2 ? a.y : a.x, 0.f);
            v = 1.f / (1.f + expf(-v));
            op[(h*4 + (c >> 2))*256 + wq*4 + (c & 3)] = v;
        }
    }
}

// ---------------------------------------------------------------------------
extern "C" void kernel_launch(void* const* d_in, const int* in_sizes, int n_in,
                              void* d_out, int out_size)
{
    const float* x1  = (const float*)d_in[0];
    const float* c1w = (const float*)d_in[1];  const float* c1b = (const float*)d_in[2];
    const float* c2w = (const float*)d_in[3];  const float* c2b = (const float*)d_in[4];
    const float* c3w = (const float*)d_in[5];  const float* c3b = (const float*)d_in[6];
    const float* c4w = (const float*)d_in[7];  const float* c4b = (const float*)d_in[8];
    const float* c5w = (const float*)d_in[9];  const float* c5b = (const float*)d_in[10];
    const float* c6w = (const float*)d_in[11]; const float* c6b = (const float*)d_in[12];
    const float* c7w = (const float*)d_in[13]; const float* c7b = (const float*)d_in[14];
    const float* r1w = (const float*)d_in[15]; const float* r1b = (const float*)d_in[16];
    const float* g1  = (const float*)d_in[17]; const float* be1 = (const float*)d_in[18];
    const float* r2w = (const float*)d_in[19]; const float* r2b = (const float*)d_in[20];
    const float* g2  = (const float*)d_in[21]; const float* be2 = (const float*)d_in[22];
    const float* pw  = (const float*)d_in[23]; const float* pb  = (const float*)d_in[24];
    const float* u1w = (const float*)d_in[25]; const float* u1b = (const float*)d_in[26];
    const float* u2w = (const float*)d_in[27]; const float* u2b = (const float*)d_in[28];

    float *t1,*ds,*t3,*r1,*r2,*u1,*part,*scale,*shift,*contrib,*pwblur;
    cudaGetSymbolAddress((void**)&t1,     g_t1);
    cudaGetSymbolAddress((void**)&ds,     g_ds);
    cudaGetSymbolAddress((void**)&t3,     g_t3);
    cudaGetSymbolAddress((void**)&r1,     g_r1);
    cudaGetSymbolAddress((void**)&r2,     g_r2);
    cudaGetSymbolAddress((void**)&u1,     g_u1);
    cudaGetSymbolAddress((void**)&part,   g_part);
    cudaGetSymbolAddress((void**)&scale,  g_scale);
    cudaGetSymbolAddress((void**)&shift,  g_shift);
    cudaGetSymbolAddress((void**)&contrib,g_contrib);
    cudaGetSymbolAddress((void**)&pwblur, g_pwblur);

    u64 *wp_r1, *wp_r2, *wp_u1, *wp_c2, *wp_c1;
    cudaGetSymbolAddress((void**)&wp_r1, g_wp_r1);
    cudaGetSymbolAddress((void**)&wp_r2, g_wp_r2);
    cudaGetSymbolAddress((void**)&wp_u1, g_wp_u1);
    cudaGetSymbolAddress((void**)&wp_c2, g_wp_c2);
    cudaGetSymbolAddress((void**)&wp_c1, g_wp_c1);

    auto smemL = [](int cin, int coutp, int k) { return (size_t)(cin*k*k*coutp + coutp)*4; };
    auto smemTC = [](int cinc, int coutp, int kp, int kcp) {
        size_t in_s = (size_t)((cinc*6*68 + 3) & ~3);
        return in_s*4 + (size_t)coutp*pad64(kp/2)*8
             + (size_t)(kcp/8)*4*8 + (size_t)16*coutp*2*4;
    };
    size_t sm_r1 = smemTC(16, 64, 2*ceil8i(16*9), ceil8i(16*9));
    size_t sm_r2 = smemTC(16, 24, 4*ceil8i(16*9), ceil8i(16*9));
    size_t sm_u1 = smemTC(20, 32, 1*ceil8i(20*9), ceil8i(20*9));
    size_t sm_c2 = (size_t)(8*11*132)*4 + (size_t)32*100*8 + 100*8;
    size_t sm_c1 = (size_t)1292*4 + (size_t)8*20*8 + 8*8;
    size_t sm_tail = (size_t)30240*4;   // ~121 KB

    cudaFuncSetAttribute((const void*)tc_conv3_k<32,16,48,16,64,64,false,false,true,true>,
                         cudaFuncAttributeMaxDynamicSharedMemorySize, (int)sm_r1);
    cudaFuncSetAttribute((const void*)tc_conv3_k<64,16,64,0,20,24,false,true,false,true>,
                         cudaFuncAttributeMaxDynamicSharedMemorySize, (int)sm_r2);
    cudaFuncSetAttribute((const void*)tc_conv3_k<20,20,20,0,30,32,true,false,false,false>,
                         cudaFuncAttributeMaxDynamicSharedMemorySize, (int)sm_u1);
    cudaFuncSetAttribute((const void*)tc_conv2_k,
                         cudaFuncAttributeMaxDynamicSharedMemorySize, (int)sm_c2);
    cudaFuncSetAttribute((const void*)tail_k,
                         cudaFuncAttributeMaxDynamicSharedMemorySize, (int)sm_tail);

    // ---------------- weight pre-pack -------------
    pack3_k<32,16,48,16,64,64><<<(64*148+127)/128,128>>>(r1w, wp_r1);
    pack3_k<64,16,64,0,20,24><<<(24*292+127)/128,128>>>(r2w, wp_r2);
    pack3_k<20,20,20,0,30,32><<<(32*100+127)/128,128>>>(u1w, wp_u1);
    pack2p_k<<<(32*100+127)/128,128>>>(c2w, wp_c2);
    pack3_k<1,1,1,0,8,8><<<2,128>>>(c1w, wp_c1);

    // ---------------- encoder ----------------
    tc_conv1_k<<<dim3(64,NB),512, sm_c1>>>(x1, wp_c1, c1b, t1);
    tc_conv2_k<<<dim3(16,NB),512, sm_c2>>>(t1, wp_c2, c2b, ds);
    conv_k<32,4,3,2,1,64,64,false><<<(NB*32*32+127)/128,128, smemL(32,4,3)>>>(ds, c3w, c3b, t3);
    tail_k<<<NB,256, sm_tail>>>(t3, c4w, c4b, c5w, c5b, c6w, c6b, c7w, c7b,
                                r1w, pw, contrib, pwblur);

    // ---------------- residual block with training-mode BN ----------------
    tc_conv3_k<32,16,48,16,64,64,false,false,true,true>
        <<<dim3(16,NB),512, sm_r1>>>(ds, wp_r1, r1b, nullptr, nullptr, contrib, r1, part);
    bn_fin2_k<64><<<64,256>>>(part, g1, be1, scale, shift);

    tc_conv3_k<64,16,64,0,20,24,false,true,false,true>
        <<<dim3(16,NB),512, sm_r2>>>(r1, wp_r2, r2b, scale, shift, nullptr, r2, part);
    bn_fin2_k<20><<<20,256>>>(part, g2, be2, scale, shift);
    bn2pw_k<<<(NB*4096+127)/128,128>>>(r2, pwblur, ds, pw, pb, scale, shift);

    // ---------------- upsample head ----------------
    tc_conv3_k<20,20,20,0,30,32,true,false,false,false>
        <<<dim3(16,NB),512, sm_u1>>>(r2, wp_u1, u1b, nullptr, nullptr, nullptr, u1, nullptr);
    final_k<<<(NB*4096+127)/128,128>>>(u1, u2w, u2b, (float*)d_out);
}